// round 1
// baseline (speedup 1.0000x reference)
#include <cuda_runtime.h>
#include <cuda_bf16.h>

#define B_SZ   8
#define T_SEQ  1023
#define C_DIM  1024
#define H_NUM  16
#define DK     64
#define R_ROWS (B_SZ * T_SEQ)   // 8184

// Scratch (allocation-free contract: __device__ globals)
__device__ float g_relu[(size_t)R_ROWS * C_DIM];
__device__ float g_val [(size_t)R_ROWS * C_DIM];
__device__ float g_y   [(size_t)R_ROWS * C_DIM];

// ---------------------------------------------------------------------------
// GEMM: O[r][c] = act( sum_k X[r][k] * W[c][k] + bias[c] )
// X: [R x 1024] row-major, W: [1024 x 1024] row-major (dot of rows = X @ W^T)
// Tile 128x128x16, 256 threads, 8x8 per-thread microtile.
// ---------------------------------------------------------------------------
template<bool RELU>
__global__ __launch_bounds__(256, 2)
void gemm_nt_bias(const float* __restrict__ X, const float* __restrict__ W,
                  const float* __restrict__ bias, float* __restrict__ O, int R)
{
    __shared__ float Xs[16][132];   // [k][m], stride 132 keeps float4 reads aligned
    __shared__ float Ws[16][132];   // [k][n]

    const int m0  = blockIdx.y * 128;
    const int n0  = blockIdx.x * 128;
    const int tid = threadIdx.x;
    const int tx  = tid & 15;   // col group
    const int ty  = tid >> 4;   // row group

    float acc[8][8];
    #pragma unroll
    for (int i = 0; i < 8; i++)
        #pragma unroll
        for (int j = 0; j < 8; j++) acc[i][j] = 0.f;

    for (int k0 = 0; k0 < C_DIM; k0 += 16) {
        // Cooperative load: 128 rows x 16 k each for X and W (float4, transpose on store)
        #pragma unroll
        for (int p = 0; p < 2; p++) {
            int f   = tid + p * 256;
            int row = f >> 2;
            int kc  = (f & 3) << 2;
            int gr  = m0 + row;
            float4 xv = make_float4(0.f, 0.f, 0.f, 0.f);
            if (gr < R) xv = *(const float4*)&X[(size_t)gr * C_DIM + k0 + kc];
            Xs[kc+0][row] = xv.x; Xs[kc+1][row] = xv.y;
            Xs[kc+2][row] = xv.z; Xs[kc+3][row] = xv.w;

            int gc = n0 + row;   // N = 1024 exact, no guard
            float4 wv = *(const float4*)&W[(size_t)gc * C_DIM + k0 + kc];
            Ws[kc+0][row] = wv.x; Ws[kc+1][row] = wv.y;
            Ws[kc+2][row] = wv.z; Ws[kc+3][row] = wv.w;
        }
        __syncthreads();

        #pragma unroll
        for (int k = 0; k < 16; k++) {
            float a[8], b[8];
            *(float4*)&a[0] = *(const float4*)&Xs[k][ty * 8];
            *(float4*)&a[4] = *(const float4*)&Xs[k][ty * 8 + 4];
            *(float4*)&b[0] = *(const float4*)&Ws[k][tx * 8];
            *(float4*)&b[4] = *(const float4*)&Ws[k][tx * 8 + 4];
            #pragma unroll
            for (int i = 0; i < 8; i++)
                #pragma unroll
                for (int j = 0; j < 8; j++)
                    acc[i][j] += a[i] * b[j];
        }
        __syncthreads();
    }

    #pragma unroll
    for (int i = 0; i < 8; i++) {
        int gr = m0 + ty * 8 + i;
        if (gr < R) {
            #pragma unroll
            for (int j = 0; j < 8; j++) {
                int gc = n0 + tx * 8 + j;
                float v = acc[i][j] + bias[gc];
                if (RELU) v = fmaxf(v, 0.f);
                O[(size_t)gr * C_DIM + gc] = v;
            }
        }
    }
}

// ---------------------------------------------------------------------------
// Fused synthesizer attention (flash-style, K = w2 constant weight):
//   scores[t][s] = q[t] . w2[:, s] + b2[s]   (causal s <= t)
//   y[t] = softmax(scores) @ V
// One block per (b, h, 64-query tile). 64 threads, thread == query row.
// Causal tile skipping: block bx only visits KV tiles 0..bx.
// ---------------------------------------------------------------------------
__global__ __launch_bounds__(64)
void attn_kernel(const float* __restrict__ A, const float* __restrict__ V,
                 const float* __restrict__ w2, const float* __restrict__ b2,
                 float* __restrict__ Y)
{
    __shared__ float ks[DK][64];   // ks[d][n]  (compute reads are broadcast)
    __shared__ float vs[64][DK];   // vs[n][d]  (compute reads are broadcast)
    __shared__ float ps[64][64];   // ps[n][m]  (per-thread column: conflict-free)

    const int b   = blockIdx.z;
    const int h   = blockIdx.y;
    const int m0  = blockIdx.x * 64;
    const int tid = threadIdx.x;
    const int t   = m0 + tid;
    const bool valid = (t < T_SEQ);
    const int trow   = valid ? t : (T_SEQ - 1);   // safe row for loads

    // q into registers
    float q[DK];
    {
        const float* qp = &A[((size_t)b * T_SEQ + trow) * C_DIM + h * DK];
        #pragma unroll
        for (int c = 0; c < DK / 4; c++) {
            float4 v4 = *(const float4*)&qp[c * 4];
            q[c*4+0] = v4.x; q[c*4+1] = v4.y; q[c*4+2] = v4.z; q[c*4+3] = v4.w;
        }
    }

    float o[DK];
    #pragma unroll
    for (int d = 0; d < DK; d++) o[d] = 0.f;
    float mrun = -1e30f, lrun = 0.f;

    const int ntiles = blockIdx.x + 1;  // causal: only tiles with n0 <= t
    for (int nt = 0; nt < ntiles; nt++) {
        const int n0 = nt * 64;

        // load K tile (w2 slice): ks[d][tid]
        {
            const int n = n0 + tid;
            const bool nv = (n < T_SEQ);
            #pragma unroll 8
            for (int d = 0; d < DK; d++)
                ks[d][tid] = nv ? w2[d * T_SEQ + n] : 0.f;
        }
        // load V tile: vs[n][tid]   (tid = d, coalesced)
        #pragma unroll 8
        for (int n = 0; n < 64; n++) {
            int s = n0 + n;
            vs[n][tid] = (s < T_SEQ)
                ? V[((size_t)b * T_SEQ + s) * C_DIM + h * DK + tid] : 0.f;
        }
        __syncthreads();

        // scores for this thread's row, 8 columns at a time
        float tmax = -1e30f;
        for (int nc = 0; nc < 64; nc += 8) {
            float s[8];
            #pragma unroll
            for (int j = 0; j < 8; j++) s[j] = 0.f;
            #pragma unroll
            for (int d = 0; d < DK; d++) {
                float4 k0v = *(const float4*)&ks[d][nc];
                float4 k1v = *(const float4*)&ks[d][nc + 4];
                float qa = q[d];
                s[0] += qa * k0v.x; s[1] += qa * k0v.y;
                s[2] += qa * k0v.z; s[3] += qa * k0v.w;
                s[4] += qa * k1v.x; s[5] += qa * k1v.y;
                s[6] += qa * k1v.z; s[7] += qa * k1v.w;
            }
            #pragma unroll
            for (int j = 0; j < 8; j++) {
                int n = n0 + nc + j;
                float sc = s[j] + ((n < T_SEQ) ? b2[n] : 0.f);
                if (n > t) sc = -1e10f;      // causal mask (matches reference fill)
                ps[nc + j][tid] = sc;        // own column only; no sync needed
                tmax = fmaxf(tmax, sc);
            }
        }

        // online softmax merge
        float mnew = fmaxf(mrun, tmax);
        float corr = __expf(mrun - mnew);
        lrun *= corr;
        #pragma unroll
        for (int d = 0; d < DK; d++) o[d] *= corr;
        mrun = mnew;

        // PV accumulate
        for (int n = 0; n < 64; n++) {
            float p = __expf(ps[n][tid] - mnew);
            lrun += p;
            #pragma unroll
            for (int dc = 0; dc < DK; dc += 4) {
                float4 vv = *(const float4*)&vs[n][dc];
                o[dc+0] += p * vv.x; o[dc+1] += p * vv.y;
                o[dc+2] += p * vv.z; o[dc+3] += p * vv.w;
            }
        }
        __syncthreads();   // protect ks/vs for next tile
    }

    if (valid) {
        float inv = 1.f / lrun;
        float* yp = &Y[((size_t)b * T_SEQ + t) * C_DIM + h * DK];
        #pragma unroll
        for (int c = 0; c < DK / 4; c++) {
            float4 v4 = make_float4(o[c*4+0] * inv, o[c*4+1] * inv,
                                    o[c*4+2] * inv, o[c*4+3] * inv);
            *(float4*)&yp[c * 4] = v4;
        }
    }
}

// ---------------------------------------------------------------------------
extern "C" void kernel_launch(void* const* d_in, const int* in_sizes, int n_in,
                              void* d_out, int out_size)
{
    const float* x       = (const float*)d_in[0];
    const float* w1_w    = (const float*)d_in[1];
    const float* w1_b    = (const float*)d_in[2];
    const float* w2      = (const float*)d_in[3];
    const float* b2      = (const float*)d_in[4];
    const float* value_w = (const float*)d_in[5];
    const float* value_b = (const float*)d_in[6];
    const float* proj_w  = (const float*)d_in[7];
    const float* proj_b  = (const float*)d_in[8];
    float* out = (float*)d_out;

    float *relu_p, *val_p, *y_p;
    cudaGetSymbolAddress((void**)&relu_p, g_relu);
    cudaGetSymbolAddress((void**)&val_p,  g_val);
    cudaGetSymbolAddress((void**)&y_p,    g_y);

    dim3 ggrid(C_DIM / 128, (R_ROWS + 127) / 128);   // (8, 64)

    gemm_nt_bias<true ><<<ggrid, 256>>>(x, w1_w, w1_b, relu_p, R_ROWS);
    gemm_nt_bias<false><<<ggrid, 256>>>(x, value_w, value_b, val_p, R_ROWS);

    attn_kernel<<<dim3((T_SEQ + 63) / 64, H_NUM, B_SZ), 64>>>(relu_p, val_p, w2, b2, y_p);

    gemm_nt_bias<false><<<ggrid, 256>>>(y_p, proj_w, proj_b, out, R_ROWS);
}

// round 2
// speedup vs baseline: 1.9472x; 1.9472x over previous
#include <cuda_runtime.h>
#include <cuda_bf16.h>

#define B_SZ   8
#define T_SEQ  1023
#define C_DIM  1024
#define H_NUM  16
#define DK     64
#define R_ROWS (B_SZ * T_SEQ)   // 8184

// Scratch (allocation-free contract: __device__ globals)
__device__ float g_relu[(size_t)R_ROWS * C_DIM];
__device__ float g_val [(size_t)R_ROWS * C_DIM];
__device__ float g_y   [(size_t)R_ROWS * C_DIM];

// ---------------------------------------------------------------------------
// GEMM: O[r][c] = act( sum_k X[r][k] * W[c][k] + bias[c] )   (unchanged R1)
// ---------------------------------------------------------------------------
template<bool RELU>
__global__ __launch_bounds__(256, 2)
void gemm_nt_bias(const float* __restrict__ X, const float* __restrict__ W,
                  const float* __restrict__ bias, float* __restrict__ O, int R)
{
    __shared__ float Xs[16][132];
    __shared__ float Ws[16][132];

    const int m0  = blockIdx.y * 128;
    const int n0  = blockIdx.x * 128;
    const int tid = threadIdx.x;
    const int tx  = tid & 15;
    const int ty  = tid >> 4;

    float acc[8][8];
    #pragma unroll
    for (int i = 0; i < 8; i++)
        #pragma unroll
        for (int j = 0; j < 8; j++) acc[i][j] = 0.f;

    for (int k0 = 0; k0 < C_DIM; k0 += 16) {
        #pragma unroll
        for (int p = 0; p < 2; p++) {
            int f   = tid + p * 256;
            int row = f >> 2;
            int kc  = (f & 3) << 2;
            int gr  = m0 + row;
            float4 xv = make_float4(0.f, 0.f, 0.f, 0.f);
            if (gr < R) xv = *(const float4*)&X[(size_t)gr * C_DIM + k0 + kc];
            Xs[kc+0][row] = xv.x; Xs[kc+1][row] = xv.y;
            Xs[kc+2][row] = xv.z; Xs[kc+3][row] = xv.w;

            int gc = n0 + row;
            float4 wv = *(const float4*)&W[(size_t)gc * C_DIM + k0 + kc];
            Ws[kc+0][row] = wv.x; Ws[kc+1][row] = wv.y;
            Ws[kc+2][row] = wv.z; Ws[kc+3][row] = wv.w;
        }
        __syncthreads();

        #pragma unroll
        for (int k = 0; k < 16; k++) {
            float a[8], b[8];
            *(float4*)&a[0] = *(const float4*)&Xs[k][ty * 8];
            *(float4*)&a[4] = *(const float4*)&Xs[k][ty * 8 + 4];
            *(float4*)&b[0] = *(const float4*)&Ws[k][tx * 8];
            *(float4*)&b[4] = *(const float4*)&Ws[k][tx * 8 + 4];
            #pragma unroll
            for (int i = 0; i < 8; i++)
                #pragma unroll
                for (int j = 0; j < 8; j++)
                    acc[i][j] += a[i] * b[j];
        }
        __syncthreads();
    }

    #pragma unroll
    for (int i = 0; i < 8; i++) {
        int gr = m0 + ty * 8 + i;
        if (gr < R) {
            #pragma unroll
            for (int j = 0; j < 8; j++) {
                int gc = n0 + tx * 8 + j;
                float v = acc[i][j] + bias[gc];
                if (RELU) v = fmaxf(v, 0.f);
                O[(size_t)gr * C_DIM + gc] = v;
            }
        }
    }
}

// ---------------------------------------------------------------------------
// Fused synthesizer attention v2.
//  * |scores| <= ~0.5 (|w2| <= 1e-3, d_k=64, bounded relu acts, small b2) so
//    softmax needs NO running max: p = expf(s), masked -> 0, normalize by sum.
//  * 256 threads = 4 column-groups x 64 queries; thread (g,q) owns query m0+q
//    and KV columns [g*16, g*16+16) of each 64-wide tile; groups merge (o,l)
//    once at the end via smem.
//  * Causal tile skipping + heavy-blocks-first (bx = gridDim.x-1 - blockIdx.x).
// ---------------------------------------------------------------------------
__global__ __launch_bounds__(256, 2)
void attn_kernel(const float* __restrict__ A, const float* __restrict__ V,
                 const float* __restrict__ w2, const float* __restrict__ b2,
                 float* __restrict__ Y)
{
    __shared__ float qs[DK][65];    // [d][q]  padded: conflict-free both ways
    __shared__ float ks[DK][64];    // [d][n]  broadcast reads
    __shared__ float vs[64][DK];    // [n][d]  broadcast reads
    __shared__ float b2s[64];
    __shared__ float lred[4][64];

    const int b   = blockIdx.z;
    const int h   = blockIdx.y;
    const int bx  = (int)(gridDim.x - 1) - (int)blockIdx.x;  // heavy first
    const int m0  = bx * 64;
    const int tid = threadIdx.x;
    const int q   = tid & 63;
    const int g   = tid >> 6;       // 0..3
    const int t   = m0 + q;

    // Load Q tile -> qs[d][q]
    for (int idx = tid; idx < 64 * DK; idx += 256) {
        int qq = idx >> 6;
        int d  = idx & 63;
        int tr = m0 + qq; if (tr >= T_SEQ) tr = T_SEQ - 1;
        qs[d][qq] = A[((size_t)b * T_SEQ + tr) * C_DIM + h * DK + d];
    }

    float o[DK];
    #pragma unroll
    for (int d = 0; d < DK; d++) o[d] = 0.f;
    float l = 0.f;

    const int c0 = g * 16;
    const int ntiles = bx + 1;

    for (int nt = 0; nt < ntiles; nt++) {
        const int n0 = nt * 64;
        __syncthreads();            // protect tiles from previous iteration

        for (int idx = tid; idx < DK * 64; idx += 256) {
            int d = idx >> 6, n = idx & 63;
            int s = n0 + n;
            ks[d][n] = (s < T_SEQ) ? w2[d * T_SEQ + s] : 0.f;
        }
        for (int idx = tid; idx < 64 * DK; idx += 256) {
            int n = idx >> 6, d = idx & 63;
            int s = n0 + n;
            vs[n][d] = (s < T_SEQ)
                ? V[((size_t)b * T_SEQ + s) * C_DIM + h * DK + d] : 0.f;
        }
        if (tid < 64) {
            int s = n0 + tid;
            b2s[tid] = (s < T_SEQ) ? b2[s] : 0.f;
        }
        __syncthreads();

        // Scores for this thread's 16 columns
        float sc[16];
        #pragma unroll
        for (int j = 0; j < 16; j++) sc[j] = b2s[c0 + j];

        #pragma unroll 8
        for (int d = 0; d < DK; d++) {
            float qv = qs[d][q];
            float4 k0 = *(const float4*)&ks[d][c0 + 0];
            float4 k1 = *(const float4*)&ks[d][c0 + 4];
            float4 k2 = *(const float4*)&ks[d][c0 + 8];
            float4 k3 = *(const float4*)&ks[d][c0 + 12];
            sc[0]  += qv * k0.x; sc[1]  += qv * k0.y; sc[2]  += qv * k0.z; sc[3]  += qv * k0.w;
            sc[4]  += qv * k1.x; sc[5]  += qv * k1.y; sc[6]  += qv * k1.z; sc[7]  += qv * k1.w;
            sc[8]  += qv * k2.x; sc[9]  += qv * k2.y; sc[10] += qv * k2.z; sc[11] += qv * k2.w;
            sc[12] += qv * k3.x; sc[13] += qv * k3.y; sc[14] += qv * k3.z; sc[15] += qv * k3.w;
        }

        // exp + causal/valid mask (no max subtraction needed; |sc| tiny)
        float p[16];
        #pragma unroll
        for (int j = 0; j < 16; j++) {
            int n = n0 + c0 + j;
            bool ok = (n <= t) && (n < T_SEQ);
            p[j] = ok ? __expf(sc[j]) : 0.f;
            l += p[j];
        }

        // PV accumulate (vs reads broadcast within each warp)
        #pragma unroll
        for (int j = 0; j < 16; j++) {
            float pj = p[j];
            const float* vrow = &vs[c0 + j][0];
            #pragma unroll
            for (int dc = 0; dc < DK; dc += 4) {
                float4 vv = *(const float4*)&vrow[dc];
                o[dc+0] += pj * vv.x; o[dc+1] += pj * vv.y;
                o[dc+2] += pj * vv.z; o[dc+3] += pj * vv.w;
            }
        }
    }

    // Merge 4 column-groups through smem (reuse tiles; they're dead now).
    __syncthreads();
    lred[g][q] = l;
    if (g == 1) {
        #pragma unroll
        for (int d = 0; d < DK; d++) ks[d][q] = o[d];
    } else if (g == 2) {
        #pragma unroll
        for (int d = 0; d < DK; d++) vs[d][q] = o[d];
    } else if (g == 3) {
        #pragma unroll
        for (int d = 0; d < DK; d++) qs[d][q] = o[d];
    }
    __syncthreads();

    if (g == 0 && t < T_SEQ) {
        float lt  = l + lred[1][q] + lred[2][q] + lred[3][q];
        float inv = 1.f / lt;
        float* yp = &Y[((size_t)b * T_SEQ + t) * C_DIM + h * DK];
        #pragma unroll
        for (int d = 0; d < DK; d += 4) {
            float4 r;
            r.x = (o[d+0] + ks[d+0][q] + vs[d+0][q] + qs[d+0][q]) * inv;
            r.y = (o[d+1] + ks[d+1][q] + vs[d+1][q] + qs[d+1][q]) * inv;
            r.z = (o[d+2] + ks[d+2][q] + vs[d+2][q] + qs[d+2][q]) * inv;
            r.w = (o[d+3] + ks[d+3][q] + vs[d+3][q] + qs[d+3][q]) * inv;
            *(float4*)&yp[d] = r;
        }
    }
}

// ---------------------------------------------------------------------------
extern "C" void kernel_launch(void* const* d_in, const int* in_sizes, int n_in,
                              void* d_out, int out_size)
{
    const float* x       = (const float*)d_in[0];
    const float* w1_w    = (const float*)d_in[1];
    const float* w1_b    = (const float*)d_in[2];
    const float* w2      = (const float*)d_in[3];
    const float* b2      = (const float*)d_in[4];
    const float* value_w = (const float*)d_in[5];
    const float* value_b = (const float*)d_in[6];
    const float* proj_w  = (const float*)d_in[7];
    const float* proj_b  = (const float*)d_in[8];
    float* out = (float*)d_out;

    float *relu_p, *val_p, *y_p;
    cudaGetSymbolAddress((void**)&relu_p, g_relu);
    cudaGetSymbolAddress((void**)&val_p,  g_val);
    cudaGetSymbolAddress((void**)&y_p,    g_y);

    dim3 ggrid(C_DIM / 128, (R_ROWS + 127) / 128);   // (8, 64)

    gemm_nt_bias<true ><<<ggrid, 256>>>(x, w1_w, w1_b, relu_p, R_ROWS);
    gemm_nt_bias<false><<<ggrid, 256>>>(x, value_w, value_b, val_p, R_ROWS);

    attn_kernel<<<dim3((T_SEQ + 63) / 64, H_NUM, B_SZ), 256>>>(relu_p, val_p, w2, b2, y_p);

    gemm_nt_bias<false><<<ggrid, 256>>>(y_p, proj_w, proj_b, out, R_ROWS);
}

// round 5
// speedup vs baseline: 3.2167x; 1.6519x over previous
#include <cuda_runtime.h>
#include <cuda_bf16.h>
#include <cstdint>

#define B_SZ   8
#define T_SEQ  1023
#define C_DIM  1024
#define H_NUM  16
#define DK     64
#define R_ROWS (B_SZ * T_SEQ)   // 8184

// ---------------- scratch (__device__ globals: allocation-free contract) ----
__device__ float g_relu[(size_t)R_ROWS * C_DIM];
__device__ float g_val [(size_t)R_ROWS * C_DIM];
__device__ __nv_bfloat16 g_xh[(size_t)R_ROWS * C_DIM];
__device__ __nv_bfloat16 g_xl[(size_t)R_ROWS * C_DIM];
__device__ __nv_bfloat16 g_yh[(size_t)R_ROWS * C_DIM];
__device__ __nv_bfloat16 g_yl[(size_t)R_ROWS * C_DIM];
__device__ __nv_bfloat16 g_w1h[(size_t)C_DIM * C_DIM];
__device__ __nv_bfloat16 g_w1l[(size_t)C_DIM * C_DIM];
__device__ __nv_bfloat16 g_vwh[(size_t)C_DIM * C_DIM];
__device__ __nv_bfloat16 g_vwl[(size_t)C_DIM * C_DIM];
__device__ __nv_bfloat16 g_pwh[(size_t)C_DIM * C_DIM];
__device__ __nv_bfloat16 g_pwl[(size_t)C_DIM * C_DIM];

// ---------------- base-target tensor-core helpers (sm_80+ class) -----------
__device__ __forceinline__ uint32_t smem_to_u32(const void* p) {
    uint32_t a;
    asm("{ .reg .u64 t; cvta.to.shared.u64 t, %1; cvt.u32.u64 %0, t; }"
        : "=r"(a) : "l"(p));
    return a;
}
__device__ __forceinline__ void ldsm_x4(uint32_t& r0, uint32_t& r1,
                                        uint32_t& r2, uint32_t& r3, uint32_t addr) {
    asm volatile("ldmatrix.sync.aligned.m8n8.x4.shared.b16 {%0,%1,%2,%3}, [%4];"
                 : "=r"(r0), "=r"(r1), "=r"(r2), "=r"(r3) : "r"(addr));
}
__device__ __forceinline__ void mma_bf16(float* c, const uint32_t* a, const uint32_t* b) {
    asm volatile(
        "mma.sync.aligned.m16n8k16.row.col.f32.bf16.bf16.f32 "
        "{%0,%1,%2,%3}, {%4,%5,%6,%7}, {%8,%9}, {%0,%1,%2,%3};"
        : "+f"(c[0]), "+f"(c[1]), "+f"(c[2]), "+f"(c[3])
        : "r"(a[0]), "r"(a[1]), "r"(a[2]), "r"(a[3]), "r"(b[0]), "r"(b[1]));
}

// ---------------------------------------------------------------------------
// hi/lo bf16 split conversion:  v = hi + lo  (lo = bf16(v - hi))
// ---------------------------------------------------------------------------
__global__ void cvt_hilo(const float* __restrict__ in, __nv_bfloat16* __restrict__ hi,
                         __nv_bfloat16* __restrict__ lo, int n)
{
    int i = (blockIdx.x * blockDim.x + threadIdx.x) * 4;
    if (i < n) {
        float4 v = *(const float4*)(in + i);
        __nv_bfloat16 h0 = __float2bfloat16_rn(v.x);
        __nv_bfloat16 h1 = __float2bfloat16_rn(v.y);
        __nv_bfloat16 h2 = __float2bfloat16_rn(v.z);
        __nv_bfloat16 h3 = __float2bfloat16_rn(v.w);
        __nv_bfloat162 ha, hb;
        ha.x = h0; ha.y = h1; hb.x = h2; hb.y = h3;
        *(__nv_bfloat162*)(hi + i)     = ha;
        *(__nv_bfloat162*)(hi + i + 2) = hb;
        __nv_bfloat162 la, lb;
        la.x = __float2bfloat16_rn(v.x - __bfloat162float(h0));
        la.y = __float2bfloat16_rn(v.y - __bfloat162float(h1));
        lb.x = __float2bfloat16_rn(v.z - __bfloat162float(h2));
        lb.y = __float2bfloat16_rn(v.w - __bfloat162float(h3));
        *(__nv_bfloat162*)(lo + i)     = la;
        *(__nv_bfloat162*)(lo + i + 2) = lb;
    }
}

// ---------------------------------------------------------------------------
// HMMA GEMM: O[r][c] = act( sum_k A[r][k]*W[c][k] + bias[c] )
// A = Ah+Al, W = Bh+Bl (bf16 hi/lo);  D = Ah*Bh + Ah*Bl + Al*Bh  (fp32 acc)
// CTA 128x128, 8 warps as 2(m) x 4(n); warp tile 64x32 (4x4 m16n8k16 frags).
// K-chunk 64. smem padded to LDS=72 bf16/row -> conflict-free ldmatrix.
// ---------------------------------------------------------------------------
#define BM  128
#define BN  128
#define BK  64
#define LDS 72
#define TILE_ELEMS (BM * LDS)                 // per smem tile
#define GSMEM (4 * TILE_ELEMS * 2)            // 73728 bytes

__global__ __launch_bounds__(256, 2)
void gemm_mma(const __nv_bfloat16* __restrict__ Ah, const __nv_bfloat16* __restrict__ Al,
              const __nv_bfloat16* __restrict__ Bh, const __nv_bfloat16* __restrict__ Bl,
              const float* __restrict__ bias, float* __restrict__ O,
              int R, int relu)
{
    extern __shared__ __nv_bfloat16 sm[];
    __nv_bfloat16* sAh = sm;
    __nv_bfloat16* sAl = sm + TILE_ELEMS;
    __nv_bfloat16* sBh = sm + 2 * TILE_ELEMS;
    __nv_bfloat16* sBl = sm + 3 * TILE_ELEMS;

    const int tid  = threadIdx.x;
    const int wid  = tid >> 5;
    const int lane = tid & 31;
    const int wm   = wid >> 2;      // 0..1
    const int wn   = wid & 3;       // 0..3
    const int m0   = blockIdx.y * BM;
    const int n0   = blockIdx.x * BN;

    const uint32_t sb   = smem_to_u32(sm);
    const uint32_t sbAh = sb;
    const uint32_t sbAl = sb + TILE_ELEMS * 2;
    const uint32_t sbBh = sb + 2 * TILE_ELEMS * 2;
    const uint32_t sbBl = sb + 3 * TILE_ELEMS * 2;

    float acc[4][4][4];
    #pragma unroll
    for (int f = 0; f < 4; f++)
        #pragma unroll
        for (int j = 0; j < 4; j++)
            #pragma unroll
            for (int e = 0; e < 4; e++) acc[f][j][e] = 0.f;

    // ldmatrix base offsets (elements) for this thread
    const int a_r = wm * 64 + (lane & 15);
    const int b_r = wn * 32 + (lane & 15);
    const int l_c = (lane >> 4) << 3;       // 0 or 8

    for (int k0 = 0; k0 < C_DIM; k0 += BK) {
        // ---- cooperative load: 4 tiles of 128x64 bf16 ----
        #pragma unroll
        for (int i = 0; i < 4; i++) {
            int g   = tid + i * 256;        // 0..1023
            int row = g >> 3;
            int c8  = (g & 7) * 8;
            size_t gA = (size_t)(m0 + row) * C_DIM + k0 + c8;
            size_t gB = (size_t)(n0 + row) * C_DIM + k0 + c8;
            int so = row * LDS + c8;
            uint4 z = make_uint4(0u, 0u, 0u, 0u);
            bool av = (m0 + row) < R;
            *(uint4*)(sAh + so) = av ? *(const uint4*)(Ah + gA) : z;
            *(uint4*)(sAl + so) = av ? *(const uint4*)(Al + gA) : z;
            *(uint4*)(sBh + so) = *(const uint4*)(Bh + gB);
            *(uint4*)(sBl + so) = *(const uint4*)(Bl + gB);
        }
        __syncthreads();

        #pragma unroll
        for (int kk = 0; kk < BK; kk += 16) {
            uint32_t af[4][4], bh[2][4], bl[2][4];
            // B fragments (hi & lo): 2 n16-pairs each
            #pragma unroll
            for (int p = 0; p < 2; p++) {
                uint32_t off = (uint32_t)((b_r + p * 16) * LDS + kk + l_c) * 2;
                ldsm_x4(bh[p][0], bh[p][1], bh[p][2], bh[p][3], sbBh + off);
                ldsm_x4(bl[p][0], bl[p][1], bl[p][2], bl[p][3], sbBl + off);
            }
            // A-hi fragments
            #pragma unroll
            for (int f = 0; f < 4; f++) {
                uint32_t off = (uint32_t)((a_r + f * 16) * LDS + kk + l_c) * 2;
                ldsm_x4(af[f][0], af[f][1], af[f][2], af[f][3], sbAh + off);
            }
            // acc += Ah*Bh + Ah*Bl
            #pragma unroll
            for (int f = 0; f < 4; f++)
                #pragma unroll
                for (int j = 0; j < 4; j++) {
                    int p = j >> 1, hhalf = j & 1;
                    uint32_t bfr[2] = { bh[p][hhalf], bh[p][2 + hhalf] };
                    uint32_t blr[2] = { bl[p][hhalf], bl[p][2 + hhalf] };
                    mma_bf16(acc[f][j], af[f], bfr);
                    mma_bf16(acc[f][j], af[f], blr);
                }
            // A-lo fragments (reuse regs)
            #pragma unroll
            for (int f = 0; f < 4; f++) {
                uint32_t off = (uint32_t)((a_r + f * 16) * LDS + kk + l_c) * 2;
                ldsm_x4(af[f][0], af[f][1], af[f][2], af[f][3], sbAl + off);
            }
            // acc += Al*Bh
            #pragma unroll
            for (int f = 0; f < 4; f++)
                #pragma unroll
                for (int j = 0; j < 4; j++) {
                    int p = j >> 1, hhalf = j & 1;
                    uint32_t bfr[2] = { bh[p][hhalf], bh[p][2 + hhalf] };
                    mma_bf16(acc[f][j], af[f], bfr);
                }
        }
        __syncthreads();
    }

    // ---- epilogue: bias + optional relu, f32 stores ----
    const int qr = lane >> 2;       // 0..7
    const int qc = (lane & 3) * 2;  // 0,2,4,6
    #pragma unroll
    for (int f = 0; f < 4; f++) {
        #pragma unroll
        for (int j = 0; j < 4; j++) {
            int col = n0 + wn * 32 + j * 8 + qc;
            float b0 = bias[col], b1 = bias[col + 1];
            #pragma unroll
            for (int half = 0; half < 2; half++) {
                int row = m0 + wm * 64 + f * 16 + qr + half * 8;
                if (row < R) {
                    float v0 = acc[f][j][half * 2 + 0] + b0;
                    float v1 = acc[f][j][half * 2 + 1] + b1;
                    if (relu) { v0 = fmaxf(v0, 0.f); v1 = fmaxf(v1, 0.f); }
                    float2 r = make_float2(v0, v1);
                    *(float2*)&O[(size_t)row * C_DIM + col] = r;
                }
            }
        }
    }
}

// ---------------------------------------------------------------------------
// Fused synthesizer attention (v2 math) — emits y as bf16 hi/lo for the
// tensor-core projection GEMM.
// ---------------------------------------------------------------------------
__global__ __launch_bounds__(256, 2)
void attn_kernel(const float* __restrict__ A, const float* __restrict__ V,
                 const float* __restrict__ w2, const float* __restrict__ b2,
                 __nv_bfloat16* __restrict__ Yh, __nv_bfloat16* __restrict__ Yl)
{
    __shared__ float qs[DK][65];
    __shared__ float ks[DK][64];
    __shared__ float vs[64][DK];
    __shared__ float b2s[64];
    __shared__ float lred[4][64];

    const int b   = blockIdx.z;
    const int h   = blockIdx.y;
    const int bx  = (int)(gridDim.x - 1) - (int)blockIdx.x;  // heavy first
    const int m0  = bx * 64;
    const int tid = threadIdx.x;
    const int q   = tid & 63;
    const int g   = tid >> 6;
    const int t   = m0 + q;

    for (int idx = tid; idx < 64 * DK; idx += 256) {
        int qq = idx >> 6;
        int d  = idx & 63;
        int tr = m0 + qq; if (tr >= T_SEQ) tr = T_SEQ - 1;
        qs[d][qq] = A[((size_t)b * T_SEQ + tr) * C_DIM + h * DK + d];
    }

    float o[DK];
    #pragma unroll
    for (int d = 0; d < DK; d++) o[d] = 0.f;
    float l = 0.f;

    const int c0 = g * 16;
    const int ntiles = bx + 1;

    for (int nt = 0; nt < ntiles; nt++) {
        const int n0 = nt * 64;
        __syncthreads();

        for (int idx = tid; idx < DK * 64; idx += 256) {
            int d = idx >> 6, n = idx & 63;
            int s = n0 + n;
            ks[d][n] = (s < T_SEQ) ? w2[d * T_SEQ + s] : 0.f;
        }
        for (int idx = tid; idx < 64 * DK; idx += 256) {
            int n = idx >> 6, d = idx & 63;
            int s = n0 + n;
            vs[n][d] = (s < T_SEQ)
                ? V[((size_t)b * T_SEQ + s) * C_DIM + h * DK + d] : 0.f;
        }
        if (tid < 64) {
            int s = n0 + tid;
            b2s[tid] = (s < T_SEQ) ? b2[s] : 0.f;
        }
        __syncthreads();

        float sc[16];
        #pragma unroll
        for (int j = 0; j < 16; j++) sc[j] = b2s[c0 + j];

        #pragma unroll 8
        for (int d = 0; d < DK; d++) {
            float qv = qs[d][q];
            float4 k0 = *(const float4*)&ks[d][c0 + 0];
            float4 k1 = *(const float4*)&ks[d][c0 + 4];
            float4 k2 = *(const float4*)&ks[d][c0 + 8];
            float4 k3 = *(const float4*)&ks[d][c0 + 12];
            sc[0]  += qv * k0.x; sc[1]  += qv * k0.y; sc[2]  += qv * k0.z; sc[3]  += qv * k0.w;
            sc[4]  += qv * k1.x; sc[5]  += qv * k1.y; sc[6]  += qv * k1.z; sc[7]  += qv * k1.w;
            sc[8]  += qv * k2.x; sc[9]  += qv * k2.y; sc[10] += qv * k2.z; sc[11] += qv * k2.w;
            sc[12] += qv * k3.x; sc[13] += qv * k3.y; sc[14] += qv * k3.z; sc[15] += qv * k3.w;
        }

        float p[16];
        #pragma unroll
        for (int j = 0; j < 16; j++) {
            int n = n0 + c0 + j;
            bool ok = (n <= t) && (n < T_SEQ);
            p[j] = ok ? __expf(sc[j]) : 0.f;
            l += p[j];
        }

        #pragma unroll
        for (int j = 0; j < 16; j++) {
            float pj = p[j];
            const float* vrow = &vs[c0 + j][0];
            #pragma unroll
            for (int dc = 0; dc < DK; dc += 4) {
                float4 vv = *(const float4*)&vrow[dc];
                o[dc+0] += pj * vv.x; o[dc+1] += pj * vv.y;
                o[dc+2] += pj * vv.z; o[dc+3] += pj * vv.w;
            }
        }
    }

    __syncthreads();
    lred[g][q] = l;
    if (g == 1) {
        #pragma unroll
        for (int d = 0; d < DK; d++) ks[d][q] = o[d];
    } else if (g == 2) {
        #pragma unroll
        for (int d = 0; d < DK; d++) vs[d][q] = o[d];
    } else if (g == 3) {
        #pragma unroll
        for (int d = 0; d < DK; d++) qs[d][q] = o[d];
    }
    __syncthreads();

    if (g == 0 && t < T_SEQ) {
        float lt  = l + lred[1][q] + lred[2][q] + lred[3][q];
        float inv = 1.f / lt;
        size_t base = ((size_t)b * T_SEQ + t) * C_DIM + h * DK;
        #pragma unroll
        for (int d = 0; d < DK; d += 2) {
            float r0 = (o[d+0] + ks[d+0][q] + vs[d+0][q] + qs[d+0][q]) * inv;
            float r1 = (o[d+1] + ks[d+1][q] + vs[d+1][q] + qs[d+1][q]) * inv;
            __nv_bfloat16 h0 = __float2bfloat16_rn(r0);
            __nv_bfloat16 h1 = __float2bfloat16_rn(r1);
            __nv_bfloat162 hp, lp;
            hp.x = h0; hp.y = h1;
            lp.x = __float2bfloat16_rn(r0 - __bfloat162float(h0));
            lp.y = __float2bfloat16_rn(r1 - __bfloat162float(h1));
            *(__nv_bfloat162*)(Yh + base + d) = hp;
            *(__nv_bfloat162*)(Yl + base + d) = lp;
        }
    }
}

// ---------------------------------------------------------------------------
extern "C" void kernel_launch(void* const* d_in, const int* in_sizes, int n_in,
                              void* d_out, int out_size)
{
    const float* x       = (const float*)d_in[0];
    const float* w1_w    = (const float*)d_in[1];
    const float* w1_b    = (const float*)d_in[2];
    const float* w2      = (const float*)d_in[3];
    const float* b2      = (const float*)d_in[4];
    const float* value_w = (const float*)d_in[5];
    const float* value_b = (const float*)d_in[6];
    const float* proj_w  = (const float*)d_in[7];
    const float* proj_b  = (const float*)d_in[8];
    float* out = (float*)d_out;

    float *relu_p, *val_p;
    __nv_bfloat16 *xh, *xl, *yh, *yl, *w1h, *w1l, *vwh, *vwl, *pwh, *pwl;
    cudaGetSymbolAddress((void**)&relu_p, g_relu);
    cudaGetSymbolAddress((void**)&val_p,  g_val);
    cudaGetSymbolAddress((void**)&xh,  g_xh);  cudaGetSymbolAddress((void**)&xl,  g_xl);
    cudaGetSymbolAddress((void**)&yh,  g_yh);  cudaGetSymbolAddress((void**)&yl,  g_yl);
    cudaGetSymbolAddress((void**)&w1h, g_w1h); cudaGetSymbolAddress((void**)&w1l, g_w1l);
    cudaGetSymbolAddress((void**)&vwh, g_vwh); cudaGetSymbolAddress((void**)&vwl, g_vwl);
    cudaGetSymbolAddress((void**)&pwh, g_pwh); cudaGetSymbolAddress((void**)&pwl, g_pwl);

    cudaFuncSetAttribute(gemm_mma, cudaFuncAttributeMaxDynamicSharedMemorySize, GSMEM);

    const int NX = R_ROWS * C_DIM;     // 8,380,416 (mult of 4)
    const int NW = C_DIM * C_DIM;      // 1,048,576
    cvt_hilo<<<NX / 4 / 256, 256>>>(x, xh, xl, NX);
    cvt_hilo<<<NW / 4 / 256, 256>>>(w1_w,    w1h, w1l, NW);
    cvt_hilo<<<NW / 4 / 256, 256>>>(value_w, vwh, vwl, NW);
    cvt_hilo<<<NW / 4 / 256, 256>>>(proj_w,  pwh, pwl, NW);

    dim3 ggrid(C_DIM / BN, (R_ROWS + BM - 1) / BM);   // (8, 64)
    gemm_mma<<<ggrid, 256, GSMEM>>>(xh, xl, w1h, w1l, w1_b, relu_p, R_ROWS, 1);
    gemm_mma<<<ggrid, 256, GSMEM>>>(xh, xl, vwh, vwl, value_b, val_p, R_ROWS, 0);

    attn_kernel<<<dim3((T_SEQ + 63) / 64, H_NUM, B_SZ), 256>>>(relu_p, val_p, w2, b2, yh, yl);

    gemm_mma<<<ggrid, 256, GSMEM>>>(yh, yl, pwh, pwl, proj_b, out, R_ROWS, 0);
}

// round 7
// speedup vs baseline: 5.5313x; 1.7196x over previous
#include <cuda_runtime.h>
#include <cuda_bf16.h>
#include <cstdint>

#define B_SZ   8
#define T_SEQ  1023
#define C_DIM  1024
#define H_NUM  16
#define DK     64
#define R_ROWS (B_SZ * T_SEQ)   // 8184

// ---------------- scratch (__device__ globals: allocation-free contract) ----
__device__ __nv_bfloat16 g_xh[(size_t)R_ROWS * C_DIM];
__device__ __nv_bfloat16 g_xl[(size_t)R_ROWS * C_DIM];
__device__ __nv_bfloat16 g_qb[(size_t)R_ROWS * C_DIM];   // relu_out bf16
__device__ __nv_bfloat16 g_vh[(size_t)R_ROWS * C_DIM];   // value hi
__device__ __nv_bfloat16 g_vl[(size_t)R_ROWS * C_DIM];   // value lo
__device__ __nv_bfloat16 g_yh[(size_t)R_ROWS * C_DIM];
__device__ __nv_bfloat16 g_yl[(size_t)R_ROWS * C_DIM];
__device__ __nv_bfloat16 g_w1h[(size_t)C_DIM * C_DIM];
__device__ __nv_bfloat16 g_w1l[(size_t)C_DIM * C_DIM];
__device__ __nv_bfloat16 g_vwh[(size_t)C_DIM * C_DIM];
__device__ __nv_bfloat16 g_vwl[(size_t)C_DIM * C_DIM];
__device__ __nv_bfloat16 g_pwh[(size_t)C_DIM * C_DIM];
__device__ __nv_bfloat16 g_pwl[(size_t)C_DIM * C_DIM];
__device__ __nv_bfloat16 g_w2t[(size_t)1024 * DK];       // w2 transposed, bf16, padded

// ---------------- tensor-core helpers (base-target sm_80+ class) -----------
__device__ __forceinline__ uint32_t smem_to_u32(const void* p) {
    uint32_t a;
    asm("{ .reg .u64 t; cvta.to.shared.u64 t, %1; cvt.u32.u64 %0, t; }"
        : "=r"(a) : "l"(p));
    return a;
}
__device__ __forceinline__ void ldsm_x4(uint32_t& r0, uint32_t& r1,
                                        uint32_t& r2, uint32_t& r3, uint32_t addr) {
    asm volatile("ldmatrix.sync.aligned.m8n8.x4.shared.b16 {%0,%1,%2,%3}, [%4];"
                 : "=r"(r0), "=r"(r1), "=r"(r2), "=r"(r3) : "r"(addr));
}
__device__ __forceinline__ void ldsm_x4_t(uint32_t& r0, uint32_t& r1,
                                          uint32_t& r2, uint32_t& r3, uint32_t addr) {
    asm volatile("ldmatrix.sync.aligned.m8n8.x4.trans.shared.b16 {%0,%1,%2,%3}, [%4];"
                 : "=r"(r0), "=r"(r1), "=r"(r2), "=r"(r3) : "r"(addr));
}
__device__ __forceinline__ void mma_bf16(float* c, const uint32_t* a, const uint32_t* b) {
    asm volatile(
        "mma.sync.aligned.m16n8k16.row.col.f32.bf16.bf16.f32 "
        "{%0,%1,%2,%3}, {%4,%5,%6,%7}, {%8,%9}, {%0,%1,%2,%3};"
        : "+f"(c[0]), "+f"(c[1]), "+f"(c[2]), "+f"(c[3])
        : "r"(a[0]), "r"(a[1]), "r"(a[2]), "r"(a[3]), "r"(b[0]), "r"(b[1]));
}
__device__ __forceinline__ uint32_t pack_bf16(float lo, float hi) {
    uint32_t r;
    asm("cvt.rn.bf16x2.f32 %0, %1, %2;" : "=r"(r) : "f"(hi), "f"(lo));
    return r;
}

// ---------------------------------------------------------------------------
// hi/lo bf16 split conversion:  v = hi + lo  (lo = bf16(v - hi))
// ---------------------------------------------------------------------------
__global__ void cvt_hilo(const float* __restrict__ in, __nv_bfloat16* __restrict__ hi,
                         __nv_bfloat16* __restrict__ lo, int n)
{
    int i = (blockIdx.x * blockDim.x + threadIdx.x) * 4;
    if (i < n) {
        float4 v = *(const float4*)(in + i);
        __nv_bfloat16 h0 = __float2bfloat16_rn(v.x);
        __nv_bfloat16 h1 = __float2bfloat16_rn(v.y);
        __nv_bfloat16 h2 = __float2bfloat16_rn(v.z);
        __nv_bfloat16 h3 = __float2bfloat16_rn(v.w);
        __nv_bfloat162 ha, hb;
        ha.x = h0; ha.y = h1; hb.x = h2; hb.y = h3;
        *(__nv_bfloat162*)(hi + i)     = ha;
        *(__nv_bfloat162*)(hi + i + 2) = hb;
        __nv_bfloat162 la, lb;
        la.x = __float2bfloat16_rn(v.x - __bfloat162float(h0));
        la.y = __float2bfloat16_rn(v.y - __bfloat162float(h1));
        lb.x = __float2bfloat16_rn(v.z - __bfloat162float(h2));
        lb.y = __float2bfloat16_rn(v.w - __bfloat162float(h3));
        *(__nv_bfloat162*)(lo + i)     = la;
        *(__nv_bfloat162*)(lo + i + 2) = lb;
    }
}

// w2 [DK][T_SEQ] f32  ->  w2t [1024][DK] bf16 (row 1023 zero-padded)
__global__ void prep_w2t(const float* __restrict__ w2, __nv_bfloat16* __restrict__ w2t)
{
    int idx = blockIdx.x * 256 + threadIdx.x;     // 1024*64
    int s = idx >> 6, d = idx & 63;
    float v = (s < T_SEQ) ? w2[d * T_SEQ + s] : 0.f;
    w2t[idx] = __float2bfloat16_rn(v);
}

// ---------------------------------------------------------------------------
// HMMA GEMM (hi/lo split). MODE 0: f32 out (+bias). MODE 1: relu -> bf16.
// MODE 2: bf16 hi/lo out.  CTA 128x128, 8 warps 2x4, warp 64x32.
// ---------------------------------------------------------------------------
#define BM  128
#define BN  128
#define BK  64
#define LDS 72
#define TILE_ELEMS (BM * LDS)
#define GSMEM (4 * TILE_ELEMS * 2)            // 73728 bytes

template<int MODE>
__global__ __launch_bounds__(256, 2)
void gemm_mma(const __nv_bfloat16* __restrict__ Ah, const __nv_bfloat16* __restrict__ Al,
              const __nv_bfloat16* __restrict__ Bh, const __nv_bfloat16* __restrict__ Bl,
              const float* __restrict__ bias, float* __restrict__ Of,
              __nv_bfloat16* __restrict__ Obh, __nv_bfloat16* __restrict__ Obl, int R)
{
    extern __shared__ __nv_bfloat16 sm[];
    __nv_bfloat16* sAh = sm;
    __nv_bfloat16* sAl = sm + TILE_ELEMS;
    __nv_bfloat16* sBh = sm + 2 * TILE_ELEMS;
    __nv_bfloat16* sBl = sm + 3 * TILE_ELEMS;

    const int tid  = threadIdx.x;
    const int wid  = tid >> 5;
    const int lane = tid & 31;
    const int wm   = wid >> 2;
    const int wn   = wid & 3;
    const int m0   = blockIdx.y * BM;
    const int n0   = blockIdx.x * BN;

    const uint32_t sb   = smem_to_u32(sm);
    const uint32_t sbAh = sb;
    const uint32_t sbAl = sb + TILE_ELEMS * 2;
    const uint32_t sbBh = sb + 2 * TILE_ELEMS * 2;
    const uint32_t sbBl = sb + 3 * TILE_ELEMS * 2;

    float acc[4][4][4];
    #pragma unroll
    for (int f = 0; f < 4; f++)
        #pragma unroll
        for (int j = 0; j < 4; j++)
            #pragma unroll
            for (int e = 0; e < 4; e++) acc[f][j][e] = 0.f;

    const int a_r = wm * 64 + (lane & 15);
    const int b_r = wn * 32 + (lane & 15);
    const int l_c = (lane >> 4) << 3;

    for (int k0 = 0; k0 < C_DIM; k0 += BK) {
        #pragma unroll
        for (int i = 0; i < 4; i++) {
            int g   = tid + i * 256;
            int row = g >> 3;
            int c8  = (g & 7) * 8;
            size_t gA = (size_t)(m0 + row) * C_DIM + k0 + c8;
            size_t gB = (size_t)(n0 + row) * C_DIM + k0 + c8;
            int so = row * LDS + c8;
            uint4 z = make_uint4(0u, 0u, 0u, 0u);
            bool av = (m0 + row) < R;
            *(uint4*)(sAh + so) = av ? *(const uint4*)(Ah + gA) : z;
            *(uint4*)(sAl + so) = av ? *(const uint4*)(Al + gA) : z;
            *(uint4*)(sBh + so) = *(const uint4*)(Bh + gB);
            *(uint4*)(sBl + so) = *(const uint4*)(Bl + gB);
        }
        __syncthreads();

        #pragma unroll
        for (int kk = 0; kk < BK; kk += 16) {
            uint32_t af[4][4], bh[2][4], bl[2][4];
            #pragma unroll
            for (int p = 0; p < 2; p++) {
                uint32_t off = (uint32_t)((b_r + p * 16) * LDS + kk + l_c) * 2;
                ldsm_x4(bh[p][0], bh[p][1], bh[p][2], bh[p][3], sbBh + off);
                ldsm_x4(bl[p][0], bl[p][1], bl[p][2], bl[p][3], sbBl + off);
            }
            #pragma unroll
            for (int f = 0; f < 4; f++) {
                uint32_t off = (uint32_t)((a_r + f * 16) * LDS + kk + l_c) * 2;
                ldsm_x4(af[f][0], af[f][1], af[f][2], af[f][3], sbAh + off);
            }
            #pragma unroll
            for (int f = 0; f < 4; f++)
                #pragma unroll
                for (int j = 0; j < 4; j++) {
                    int p = j >> 1, hh = j & 1;
                    uint32_t bfr[2] = { bh[p][hh], bh[p][2 + hh] };
                    uint32_t blr[2] = { bl[p][hh], bl[p][2 + hh] };
                    mma_bf16(acc[f][j], af[f], bfr);
                    mma_bf16(acc[f][j], af[f], blr);
                }
            #pragma unroll
            for (int f = 0; f < 4; f++) {
                uint32_t off = (uint32_t)((a_r + f * 16) * LDS + kk + l_c) * 2;
                ldsm_x4(af[f][0], af[f][1], af[f][2], af[f][3], sbAl + off);
            }
            #pragma unroll
            for (int f = 0; f < 4; f++)
                #pragma unroll
                for (int j = 0; j < 4; j++) {
                    int p = j >> 1, hh = j & 1;
                    uint32_t bfr[2] = { bh[p][hh], bh[p][2 + hh] };
                    mma_bf16(acc[f][j], af[f], bfr);
                }
        }
        __syncthreads();
    }

    const int qr = lane >> 2;
    const int qc = (lane & 3) * 2;
    #pragma unroll
    for (int f = 0; f < 4; f++) {
        #pragma unroll
        for (int j = 0; j < 4; j++) {
            int col = n0 + wn * 32 + j * 8 + qc;
            float b0 = bias[col], b1 = bias[col + 1];
            #pragma unroll
            for (int half = 0; half < 2; half++) {
                int row = m0 + wm * 64 + f * 16 + qr + half * 8;
                if (row < R) {
                    float v0 = acc[f][j][half * 2 + 0] + b0;
                    float v1 = acc[f][j][half * 2 + 1] + b1;
                    if (MODE == 0) {
                        *(float2*)&Of[(size_t)row * C_DIM + col] = make_float2(v0, v1);
                    } else if (MODE == 1) {
                        v0 = fmaxf(v0, 0.f); v1 = fmaxf(v1, 0.f);
                        __nv_bfloat162 hp;
                        hp.x = __float2bfloat16_rn(v0); hp.y = __float2bfloat16_rn(v1);
                        *(__nv_bfloat162*)&Obh[(size_t)row * C_DIM + col] = hp;
                    } else {
                        __nv_bfloat16 h0 = __float2bfloat16_rn(v0);
                        __nv_bfloat16 h1 = __float2bfloat16_rn(v1);
                        __nv_bfloat162 hp, lp;
                        hp.x = h0; hp.y = h1;
                        lp.x = __float2bfloat16_rn(v0 - __bfloat162float(h0));
                        lp.y = __float2bfloat16_rn(v1 - __bfloat162float(h1));
                        *(__nv_bfloat162*)&Obh[(size_t)row * C_DIM + col] = hp;
                        *(__nv_bfloat162*)&Obl[(size_t)row * C_DIM + col] = lp;
                    }
                }
            }
        }
    }
}

// ---------------------------------------------------------------------------
// HMMA flash attention. CTA = (b, h, 128-query tile); 8 warps x 16 rows.
// S = Q(bf16) @ w2t^T; p = exp(S + b2) with causal mask (no max pass: |S| tiny);
// Y += Ph@Vh + Ph@Vl + Pl@Vh  (P split hi/lo in registers, FA2 frag repack).
// FIX vs R6: K-fragment pairing for S-MMA is {mat0,mat2}/{mat1,mat3}.
// ---------------------------------------------------------------------------
#define ATE (128 * LDS)                  // elems per attn smem tile
#define ASMEM (4 * ATE * 2 + 512)        // 4 tiles + b2

__global__ __launch_bounds__(256, 1)
void attn_mma(const __nv_bfloat16* __restrict__ Q, const __nv_bfloat16* __restrict__ Vh,
              const __nv_bfloat16* __restrict__ Vl, const __nv_bfloat16* __restrict__ w2t,
              const float* __restrict__ b2,
              __nv_bfloat16* __restrict__ Yh, __nv_bfloat16* __restrict__ Yl)
{
    extern __shared__ __nv_bfloat16 asmem[];
    __nv_bfloat16* sQ  = asmem;
    __nv_bfloat16* sK  = asmem + ATE;
    __nv_bfloat16* sVh = asmem + 2 * ATE;
    __nv_bfloat16* sVl = asmem + 3 * ATE;
    float* sb2 = (float*)(asmem + 4 * ATE);

    const uint32_t sbQ  = smem_to_u32(sQ);
    const uint32_t sbK  = smem_to_u32(sK);
    const uint32_t sbVh = smem_to_u32(sVh);
    const uint32_t sbVl = smem_to_u32(sVl);

    const int b    = blockIdx.z;
    const int h    = blockIdx.y;
    const int qt   = (int)(gridDim.x - 1) - (int)blockIdx.x;   // heavy first
    const int m0   = qt * 128;
    const int tid  = threadIdx.x;
    const int wid  = tid >> 5;
    const int lane = tid & 31;
    const int mw   = wid * 16;               // warp's query-row offset in tile

    // load Q tile [128][64] bf16 (row-clamped)
    for (int idx = tid; idx < 1024; idx += 256) {
        int row = idx >> 3, c8 = (idx & 7) * 8;
        int t = m0 + row; if (t > T_SEQ - 1) t = T_SEQ - 1;
        *(uint4*)(sQ + row * LDS + c8) =
            *(const uint4*)(Q + ((size_t)b * T_SEQ + t) * C_DIM + h * DK + c8);
    }
    __syncthreads();

    // preload Q fragments (persist across all KV tiles)
    uint32_t qf[4][4];
    {
        int r  = mw + (lane & 15);
        int cg = (lane >> 4) << 3;
        #pragma unroll
        for (int k = 0; k < 4; k++)
            ldsm_x4(qf[k][0], qf[k][1], qf[k][2], qf[k][3],
                    sbQ + (uint32_t)(r * LDS + k * 16 + cg) * 2);
    }

    float yacc[8][4];
    #pragma unroll
    for (int j = 0; j < 8; j++)
        #pragma unroll
        for (int e = 0; e < 4; e++) yacc[j][e] = 0.f;
    float ls0 = 0.f, ls1 = 0.f;

    const int r0  = lane >> 2;        // 0..7
    const int c0l = (lane & 3) * 2;   // 0,2,4,6
    const int trow0 = m0 + mw + r0;   // global t of this lane's lower row

    for (int nt = 0; nt <= qt; nt++) {
        const int s0 = nt * 128;
        __syncthreads();
        // load K / Vh / Vl tiles [128][64]
        for (int idx = tid; idx < 1024; idx += 256) {
            int row = idx >> 3, c8 = (idx & 7) * 8;
            int so = row * LDS + c8;
            *(uint4*)(sK + so) = *(const uint4*)(w2t + (size_t)(s0 + row) * DK + c8);
            int s = s0 + row; if (s > T_SEQ - 1) s = T_SEQ - 1;
            size_t vb = ((size_t)b * T_SEQ + s) * C_DIM + h * DK + c8;
            *(uint4*)(sVh + so) = *(const uint4*)(Vh + vb);
            *(uint4*)(sVl + so) = *(const uint4*)(Vl + vb);
        }
        if (tid < 128) {
            int s = s0 + tid;
            sb2[tid] = (s < T_SEQ) ? b2[s] : 0.f;
        }
        __syncthreads();

        // ---- S = Q @ K^T : 16 n8 frags ----
        float S[16][4];
        #pragma unroll
        for (int f = 0; f < 16; f++)
            #pragma unroll
            for (int e = 0; e < 4; e++) S[f][e] = 0.f;

        #pragma unroll
        for (int k = 0; k < 4; k++) {
            #pragma unroll
            for (int ng = 0; ng < 8; ng++) {
                uint32_t bb[4];
                int nr = ng * 16 + (lane & 15);
                int cg = k * 16 + ((lane >> 4) << 3);
                ldsm_x4(bb[0], bb[1], bb[2], bb[3], sbK + (uint32_t)(nr * LDS + cg) * 2);
                // FIX: pair {mat0, mat2} (same s cols, d lo/hi halves) and {mat1, mat3}
                uint32_t blo[2] = { bb[0], bb[2] };
                uint32_t bhi[2] = { bb[1], bb[3] };
                mma_bf16(S[2 * ng],     qf[k], blo);
                mma_bf16(S[2 * ng + 1], qf[k], bhi);
            }
        }

        // ---- bias + mask + exp + split + PV, one k16 chunk at a time ----
        const bool diag = (nt == qt);
        #pragma unroll
        for (int j = 0; j < 8; j++) {
            float p[2][4];   // [frag 2j / 2j+1][e]
            #pragma unroll
            for (int fh = 0; fh < 2; fh++) {
                int f = 2 * j + fh;
                #pragma unroll
                for (int e = 0; e < 4; e++) {
                    int col = 8 * f + c0l + (e & 1);           // local col
                    int rr  = trow0 + ((e >> 1) << 3);         // global t
                    float sv = S[f][e] + sb2[col];
                    bool ok = !diag || (s0 + col <= rr);
                    float pv = ok ? __expf(sv) : 0.f;
                    p[fh][e] = pv;
                    if (e < 2) ls0 += pv; else ls1 += pv;
                }
            }
            // A-frags: hi and lo parts
            uint32_t pah[4], pal[4];
            #pragma unroll
            for (int fh = 0; fh < 2; fh++) {
                #pragma unroll
                for (int hh = 0; hh < 2; hh++) {
                    float v0 = p[fh][2 * hh], v1 = p[fh][2 * hh + 1];
                    uint32_t ph = pack_bf16(v0, v1);
                    pah[2 * fh + hh] = ph;
                    __nv_bfloat162 hb = *(__nv_bfloat162*)&ph;
                    pal[2 * fh + hh] = pack_bf16(v0 - __bfloat162float(hb.x),
                                                 v1 - __bfloat162float(hb.y));
                }
            }
            uint32_t Ah_[4] = { pah[0], pah[1], pah[2], pah[3] };
            uint32_t Al_[4] = { pal[0], pal[1], pal[2], pal[3] };

            // V fragments for this k16 chunk (s rows 16j..16j+15)
            int srow = 16 * j + (lane & 15);
            int dgof = (lane >> 4) << 3;
            #pragma unroll
            for (int dg = 0; dg < 4; dg++) {
                uint32_t vh4[4], vl4[4];
                uint32_t off = (uint32_t)(srow * LDS + dg * 16 + dgof) * 2;
                ldsm_x4_t(vh4[0], vh4[1], vh4[2], vh4[3], sbVh + off);
                ldsm_x4_t(vl4[0], vl4[1], vl4[2], vl4[3], sbVl + off);
                uint32_t bh0[2] = { vh4[0], vh4[1] };
                uint32_t bh1[2] = { vh4[2], vh4[3] };
                uint32_t bl0[2] = { vl4[0], vl4[1] };
                uint32_t bl1[2] = { vl4[2], vl4[3] };
                mma_bf16(yacc[2 * dg],     Ah_, bh0);
                mma_bf16(yacc[2 * dg + 1], Ah_, bh1);
                mma_bf16(yacc[2 * dg],     Ah_, bl0);
                mma_bf16(yacc[2 * dg + 1], Ah_, bl1);
                mma_bf16(yacc[2 * dg],     Al_, bh0);
                mma_bf16(yacc[2 * dg + 1], Al_, bh1);
            }
        }
    }

    // row-sum reduction across the 4 lanes sharing each row
    ls0 += __shfl_xor_sync(0xffffffffu, ls0, 1);
    ls0 += __shfl_xor_sync(0xffffffffu, ls0, 2);
    ls1 += __shfl_xor_sync(0xffffffffu, ls1, 1);
    ls1 += __shfl_xor_sync(0xffffffffu, ls1, 2);
    float inv0 = 1.f / ls0, inv1 = 1.f / ls1;

    #pragma unroll
    for (int half = 0; half < 2; half++) {
        int t = trow0 + half * 8;
        if (t < T_SEQ) {
            float inv = half ? inv1 : inv0;
            size_t base = ((size_t)b * T_SEQ + t) * C_DIM + h * DK;
            #pragma unroll
            for (int j = 0; j < 8; j++) {
                float v0 = yacc[j][2 * half + 0] * inv;
                float v1 = yacc[j][2 * half + 1] * inv;
                __nv_bfloat16 h0 = __float2bfloat16_rn(v0);
                __nv_bfloat16 h1 = __float2bfloat16_rn(v1);
                __nv_bfloat162 hp, lp;
                hp.x = h0; hp.y = h1;
                lp.x = __float2bfloat16_rn(v0 - __bfloat162float(h0));
                lp.y = __float2bfloat16_rn(v1 - __bfloat162float(h1));
                int col = j * 8 + c0l;
                *(__nv_bfloat162*)&Yh[base + col] = hp;
                *(__nv_bfloat162*)&Yl[base + col] = lp;
            }
        }
    }
}

// ---------------------------------------------------------------------------
extern "C" void kernel_launch(void* const* d_in, const int* in_sizes, int n_in,
                              void* d_out, int out_size)
{
    const float* x       = (const float*)d_in[0];
    const float* w1_w    = (const float*)d_in[1];
    const float* w1_b    = (const float*)d_in[2];
    const float* w2      = (const float*)d_in[3];
    const float* b2      = (const float*)d_in[4];
    const float* value_w = (const float*)d_in[5];
    const float* value_b = (const float*)d_in[6];
    const float* proj_w  = (const float*)d_in[7];
    const float* proj_b  = (const float*)d_in[8];
    float* out = (float*)d_out;

    __nv_bfloat16 *xh, *xl, *qb, *vh, *vl, *yh, *yl;
    __nv_bfloat16 *w1h, *w1l, *vwh, *vwl, *pwh, *pwl, *w2t;
    cudaGetSymbolAddress((void**)&xh,  g_xh);  cudaGetSymbolAddress((void**)&xl,  g_xl);
    cudaGetSymbolAddress((void**)&qb,  g_qb);
    cudaGetSymbolAddress((void**)&vh,  g_vh);  cudaGetSymbolAddress((void**)&vl,  g_vl);
    cudaGetSymbolAddress((void**)&yh,  g_yh);  cudaGetSymbolAddress((void**)&yl,  g_yl);
    cudaGetSymbolAddress((void**)&w1h, g_w1h); cudaGetSymbolAddress((void**)&w1l, g_w1l);
    cudaGetSymbolAddress((void**)&vwh, g_vwh); cudaGetSymbolAddress((void**)&vwl, g_vwl);
    cudaGetSymbolAddress((void**)&pwh, g_pwh); cudaGetSymbolAddress((void**)&pwl, g_pwl);
    cudaGetSymbolAddress((void**)&w2t, g_w2t);

    cudaFuncSetAttribute(gemm_mma<0>, cudaFuncAttributeMaxDynamicSharedMemorySize, GSMEM);
    cudaFuncSetAttribute(gemm_mma<1>, cudaFuncAttributeMaxDynamicSharedMemorySize, GSMEM);
    cudaFuncSetAttribute(gemm_mma<2>, cudaFuncAttributeMaxDynamicSharedMemorySize, GSMEM);
    cudaFuncSetAttribute(attn_mma,    cudaFuncAttributeMaxDynamicSharedMemorySize, ASMEM);

    const int NX = R_ROWS * C_DIM;
    const int NW = C_DIM * C_DIM;
    cvt_hilo<<<NX / 4 / 256, 256>>>(x, xh, xl, NX);
    cvt_hilo<<<NW / 4 / 256, 256>>>(w1_w,    w1h, w1l, NW);
    cvt_hilo<<<NW / 4 / 256, 256>>>(value_w, vwh, vwl, NW);
    cvt_hilo<<<NW / 4 / 256, 256>>>(proj_w,  pwh, pwl, NW);
    prep_w2t<<<(1024 * DK) / 256, 256>>>(w2, w2t);

    dim3 ggrid(C_DIM / BN, (R_ROWS + BM - 1) / BM);   // (8, 64)
    gemm_mma<1><<<ggrid, 256, GSMEM>>>(xh, xl, w1h, w1l, w1_b, nullptr, qb, nullptr, R_ROWS);
    gemm_mma<2><<<ggrid, 256, GSMEM>>>(xh, xl, vwh, vwl, value_b, nullptr, vh, vl, R_ROWS);

    attn_mma<<<dim3(8, H_NUM, B_SZ), 256, ASMEM>>>(qb, vh, vl, w2t, b2, yh, yl);

    gemm_mma<0><<<ggrid, 256, GSMEM>>>(yh, yl, pwh, pwl, proj_b, out, nullptr, nullptr, R_ROWS);
}

// round 8
// speedup vs baseline: 8.6252x; 1.5593x over previous
#include <cuda_runtime.h>
#include <cuda_fp16.h>
#include <cstdint>

#define B_SZ   8
#define T_SEQ  1023
#define C_DIM  1024
#define H_NUM  16
#define DK     64
#define R_ROWS (B_SZ * T_SEQ)   // 8184

// ---------------- scratch (__device__ globals: allocation-free contract) ----
__device__ __half g_xh [(size_t)R_ROWS * C_DIM];
__device__ __half g_xl [(size_t)R_ROWS * C_DIM];
__device__ __half g_qb [(size_t)R_ROWS * C_DIM];   // relu_out fp16 (Q)
__device__ __half g_vs [(size_t)R_ROWS * C_DIM];   // value fp16 single
__device__ __half g_yh [(size_t)R_ROWS * C_DIM];
__device__ __half g_yl [(size_t)R_ROWS * C_DIM];
__device__ __half g_w1s[(size_t)C_DIM * C_DIM];
__device__ __half g_vws[(size_t)C_DIM * C_DIM];
__device__ __half g_pws[(size_t)C_DIM * C_DIM];
__device__ __half g_w2t[(size_t)1024 * DK];        // w2 transposed fp16, padded

// ---------------- tensor-core helpers (base-target sm_80+ class) -----------
__device__ __forceinline__ uint32_t smem_to_u32(const void* p) {
    uint32_t a;
    asm("{ .reg .u64 t; cvta.to.shared.u64 t, %1; cvt.u32.u64 %0, t; }"
        : "=r"(a) : "l"(p));
    return a;
}
__device__ __forceinline__ void ldsm_x4(uint32_t& r0, uint32_t& r1,
                                        uint32_t& r2, uint32_t& r3, uint32_t addr) {
    asm volatile("ldmatrix.sync.aligned.m8n8.x4.shared.b16 {%0,%1,%2,%3}, [%4];"
                 : "=r"(r0), "=r"(r1), "=r"(r2), "=r"(r3) : "r"(addr));
}
__device__ __forceinline__ void ldsm_x4_t(uint32_t& r0, uint32_t& r1,
                                          uint32_t& r2, uint32_t& r3, uint32_t addr) {
    asm volatile("ldmatrix.sync.aligned.m8n8.x4.trans.shared.b16 {%0,%1,%2,%3}, [%4];"
                 : "=r"(r0), "=r"(r1), "=r"(r2), "=r"(r3) : "r"(addr));
}
__device__ __forceinline__ void mma_f16(float* c, const uint32_t* a, const uint32_t* b) {
    asm volatile(
        "mma.sync.aligned.m16n8k16.row.col.f32.f16.f16.f32 "
        "{%0,%1,%2,%3}, {%4,%5,%6,%7}, {%8,%9}, {%0,%1,%2,%3};"
        : "+f"(c[0]), "+f"(c[1]), "+f"(c[2]), "+f"(c[3])
        : "r"(a[0]), "r"(a[1]), "r"(a[2]), "r"(a[3]), "r"(b[0]), "r"(b[1]));
}
__device__ __forceinline__ uint32_t pack_f16(float lo, float hi) {
    uint32_t r;
    asm("cvt.rn.f16x2.f32 %0, %1, %2;" : "=r"(r) : "f"(hi), "f"(lo));
    return r;
}

// ---------------------------------------------------------------------------
// conversions
// ---------------------------------------------------------------------------
__global__ void cvt_hilo_h(const float* __restrict__ in, __half* __restrict__ hi,
                           __half* __restrict__ lo, int n)
{
    int i = (blockIdx.x * blockDim.x + threadIdx.x) * 4;
    if (i < n) {
        float4 v = *(const float4*)(in + i);
        __half h0 = __float2half_rn(v.x);
        __half h1 = __float2half_rn(v.y);
        __half h2 = __float2half_rn(v.z);
        __half h3 = __float2half_rn(v.w);
        __half2 ha, hb;
        ha.x = h0; ha.y = h1; hb.x = h2; hb.y = h3;
        *(__half2*)(hi + i)     = ha;
        *(__half2*)(hi + i + 2) = hb;
        __half2 la, lb;
        la.x = __float2half_rn(v.x - __half2float(h0));
        la.y = __float2half_rn(v.y - __half2float(h1));
        lb.x = __float2half_rn(v.z - __half2float(h2));
        lb.y = __float2half_rn(v.w - __half2float(h3));
        *(__half2*)(lo + i)     = la;
        *(__half2*)(lo + i + 2) = lb;
    }
}

__global__ void cvt_h(const float* __restrict__ in, __half* __restrict__ out, int n)
{
    int i = (blockIdx.x * blockDim.x + threadIdx.x) * 4;
    if (i < n) {
        float4 v = *(const float4*)(in + i);
        __half2 a, b;
        a.x = __float2half_rn(v.x); a.y = __float2half_rn(v.y);
        b.x = __float2half_rn(v.z); b.y = __float2half_rn(v.w);
        *(__half2*)(out + i)     = a;
        *(__half2*)(out + i + 2) = b;
    }
}

// w2 [DK][T_SEQ] f32  ->  w2t [1024][DK] fp16 (row 1023 zero-padded)
__global__ void prep_w2t(const float* __restrict__ w2, __half* __restrict__ w2t)
{
    int idx = blockIdx.x * 256 + threadIdx.x;     // 1024*64
    int s = idx >> 6, d = idx & 63;
    float v = (s < T_SEQ) ? w2[d * T_SEQ + s] : 0.f;
    w2t[idx] = __float2half_rn(v);
}

// ---------------------------------------------------------------------------
// HMMA fp16 GEMM.  TERMS=1: D = A0*B.  TERMS=2: D = (A0+A1)*B  (A hi/lo).
// MODE 0: f32 out (+bias). MODE 1: relu -> fp16. MODE 3: fp16 single.
// MODE 2: fp16 hi/lo out.  CTA 128x128, 8 warps 2x4, warp 64x32.
// ---------------------------------------------------------------------------
#define BM  128
#define BN  128
#define BK  64
#define LDS 72
#define TILE_ELEMS (BM * LDS)
#define GSMEM2 (2 * TILE_ELEMS * 2)           // TERMS=1: 36864
#define GSMEM3 (3 * TILE_ELEMS * 2)           // TERMS=2: 55296

template<int TERMS, int MODE>
__global__ __launch_bounds__(256, 2)
void gemm_mma(const __half* __restrict__ A0, const __half* __restrict__ A1,
              const __half* __restrict__ B,  const float* __restrict__ bias,
              float* __restrict__ Of, __half* __restrict__ Oh,
              __half* __restrict__ Ol, int R)
{
    extern __shared__ __half sm[];
    __half* sA0 = sm;
    __half* sA1 = sm + TILE_ELEMS;                       // valid iff TERMS==2
    __half* sB  = sm + TERMS * TILE_ELEMS;

    const int tid  = threadIdx.x;
    const int wid  = tid >> 5;
    const int lane = tid & 31;
    const int wm   = wid >> 2;
    const int wn   = wid & 3;
    const int m0   = blockIdx.y * BM;
    const int n0   = blockIdx.x * BN;

    const uint32_t sbA0 = smem_to_u32(sA0);
    const uint32_t sbA1 = smem_to_u32(sA1);
    const uint32_t sbB  = smem_to_u32(sB);

    float acc[4][4][4];
    #pragma unroll
    for (int f = 0; f < 4; f++)
        #pragma unroll
        for (int j = 0; j < 4; j++)
            #pragma unroll
            for (int e = 0; e < 4; e++) acc[f][j][e] = 0.f;

    const int a_r = wm * 64 + (lane & 15);
    const int b_r = wn * 32 + (lane & 15);
    const int l_c = (lane >> 4) << 3;

    for (int k0 = 0; k0 < C_DIM; k0 += BK) {
        #pragma unroll
        for (int i = 0; i < 4; i++) {
            int g   = tid + i * 256;
            int row = g >> 3;
            int c8  = (g & 7) * 8;
            size_t gA = (size_t)(m0 + row) * C_DIM + k0 + c8;
            int so = row * LDS + c8;
            uint4 z = make_uint4(0u, 0u, 0u, 0u);
            bool av = (m0 + row) < R;
            *(uint4*)(sA0 + so) = av ? *(const uint4*)(A0 + gA) : z;
            if (TERMS == 2)
                *(uint4*)(sA1 + so) = av ? *(const uint4*)(A1 + gA) : z;
            *(uint4*)(sB + so) = *(const uint4*)(B + (size_t)(n0 + row) * C_DIM + k0 + c8);
        }
        __syncthreads();

        #pragma unroll
        for (int kk = 0; kk < BK; kk += 16) {
            uint32_t af[4][4], bh[2][4];
            #pragma unroll
            for (int p = 0; p < 2; p++) {
                uint32_t off = (uint32_t)((b_r + p * 16) * LDS + kk + l_c) * 2;
                ldsm_x4(bh[p][0], bh[p][1], bh[p][2], bh[p][3], sbB + off);
            }
            #pragma unroll
            for (int f = 0; f < 4; f++) {
                uint32_t off = (uint32_t)((a_r + f * 16) * LDS + kk + l_c) * 2;
                ldsm_x4(af[f][0], af[f][1], af[f][2], af[f][3], sbA0 + off);
            }
            #pragma unroll
            for (int f = 0; f < 4; f++)
                #pragma unroll
                for (int j = 0; j < 4; j++) {
                    int p = j >> 1, hh = j & 1;
                    uint32_t bfr[2] = { bh[p][hh], bh[p][2 + hh] };
                    mma_f16(acc[f][j], af[f], bfr);
                }
            if (TERMS == 2) {
                #pragma unroll
                for (int f = 0; f < 4; f++) {
                    uint32_t off = (uint32_t)((a_r + f * 16) * LDS + kk + l_c) * 2;
                    ldsm_x4(af[f][0], af[f][1], af[f][2], af[f][3], sbA1 + off);
                }
                #pragma unroll
                for (int f = 0; f < 4; f++)
                    #pragma unroll
                    for (int j = 0; j < 4; j++) {
                        int p = j >> 1, hh = j & 1;
                        uint32_t bfr[2] = { bh[p][hh], bh[p][2 + hh] };
                        mma_f16(acc[f][j], af[f], bfr);
                    }
            }
        }
        __syncthreads();
    }

    const int qr = lane >> 2;
    const int qc = (lane & 3) * 2;
    #pragma unroll
    for (int f = 0; f < 4; f++) {
        #pragma unroll
        for (int j = 0; j < 4; j++) {
            int col = n0 + wn * 32 + j * 8 + qc;
            float b0 = bias[col], b1 = bias[col + 1];
            #pragma unroll
            for (int half = 0; half < 2; half++) {
                int row = m0 + wm * 64 + f * 16 + qr + half * 8;
                if (row < R) {
                    float v0 = acc[f][j][half * 2 + 0] + b0;
                    float v1 = acc[f][j][half * 2 + 1] + b1;
                    if (MODE == 0) {
                        *(float2*)&Of[(size_t)row * C_DIM + col] = make_float2(v0, v1);
                    } else if (MODE == 1) {
                        v0 = fmaxf(v0, 0.f); v1 = fmaxf(v1, 0.f);
                        __half2 hp;
                        hp.x = __float2half_rn(v0); hp.y = __float2half_rn(v1);
                        *(__half2*)&Oh[(size_t)row * C_DIM + col] = hp;
                    } else if (MODE == 3) {
                        __half2 hp;
                        hp.x = __float2half_rn(v0); hp.y = __float2half_rn(v1);
                        *(__half2*)&Oh[(size_t)row * C_DIM + col] = hp;
                    } else {
                        __half h0 = __float2half_rn(v0);
                        __half h1 = __float2half_rn(v1);
                        __half2 hp, lp;
                        hp.x = h0; hp.y = h1;
                        lp.x = __float2half_rn(v0 - __half2float(h0));
                        lp.y = __float2half_rn(v1 - __half2float(h1));
                        *(__half2*)&Oh[(size_t)row * C_DIM + col] = hp;
                        *(__half2*)&Ol[(size_t)row * C_DIM + col] = lp;
                    }
                }
            }
        }
    }
}

// ---------------------------------------------------------------------------
// HMMA fp16 flash attention. CTA = (b, h, 128-query tile); 8 warps x 16 rows.
// S = Q @ w2t^T; p = exp(S + b2) causal-masked (no max pass: |S| tiny).
// PV: P split hi/lo fp16 in registers (exact) x V single fp16 -> 2 MMA terms.
// S computation fused into the j-loop (no S[16] array) -> fits occupancy 2.
// ---------------------------------------------------------------------------
#define ATE (128 * LDS)
#define ASMEM (3 * ATE * 2 + 512)            // Q + K + V tiles + b2

__global__ __launch_bounds__(256, 2)
void attn_mma(const __half* __restrict__ Q, const __half* __restrict__ V,
              const __half* __restrict__ w2t, const float* __restrict__ b2,
              __half* __restrict__ Yh, __half* __restrict__ Yl)
{
    extern __shared__ __half asmem[];
    __half* sQ = asmem;
    __half* sK = asmem + ATE;
    __half* sV = asmem + 2 * ATE;
    float* sb2 = (float*)(asmem + 3 * ATE);

    const uint32_t sbQ = smem_to_u32(sQ);
    const uint32_t sbK = smem_to_u32(sK);
    const uint32_t sbV = smem_to_u32(sV);

    const int b    = blockIdx.z;
    const int h    = blockIdx.y;
    const int qt   = (int)(gridDim.x - 1) - (int)blockIdx.x;   // heavy first
    const int m0   = qt * 128;
    const int tid  = threadIdx.x;
    const int wid  = tid >> 5;
    const int lane = tid & 31;
    const int mw   = wid * 16;

    // load Q tile [128][64] (row-clamped)
    for (int idx = tid; idx < 1024; idx += 256) {
        int row = idx >> 3, c8 = (idx & 7) * 8;
        int t = m0 + row; if (t > T_SEQ - 1) t = T_SEQ - 1;
        *(uint4*)(sQ + row * LDS + c8) =
            *(const uint4*)(Q + ((size_t)b * T_SEQ + t) * C_DIM + h * DK + c8);
    }
    __syncthreads();

    // preload Q fragments (persist across KV tiles)
    uint32_t qf[4][4];
    {
        int r  = mw + (lane & 15);
        int cg = (lane >> 4) << 3;
        #pragma unroll
        for (int k = 0; k < 4; k++)
            ldsm_x4(qf[k][0], qf[k][1], qf[k][2], qf[k][3],
                    sbQ + (uint32_t)(r * LDS + k * 16 + cg) * 2);
    }

    float yacc[8][4];
    #pragma unroll
    for (int j = 0; j < 8; j++)
        #pragma unroll
        for (int e = 0; e < 4; e++) yacc[j][e] = 0.f;
    float ls0 = 0.f, ls1 = 0.f;

    const int r0    = lane >> 2;
    const int c0l   = (lane & 3) * 2;
    const int trow0 = m0 + mw + r0;
    const int lgo   = (lane >> 4) << 3;      // ldmatrix column-group offset
    const int lr16  = lane & 15;

    for (int nt = 0; nt <= qt; nt++) {
        const int s0 = nt * 128;
        __syncthreads();
        for (int idx = tid; idx < 1024; idx += 256) {
            int row = idx >> 3, c8 = (idx & 7) * 8;
            int so = row * LDS + c8;
            *(uint4*)(sK + so) = *(const uint4*)(w2t + (size_t)(s0 + row) * DK + c8);
            int s = s0 + row; if (s > T_SEQ - 1) s = T_SEQ - 1;
            *(uint4*)(sV + so) =
                *(const uint4*)(V + ((size_t)b * T_SEQ + s) * C_DIM + h * DK + c8);
        }
        if (tid < 128) {
            int s = s0 + tid;
            sb2[tid] = (s < T_SEQ) ? b2[s] : 0.f;
        }
        __syncthreads();

        const bool diag = (nt == qt);
        #pragma unroll
        for (int j = 0; j < 8; j++) {
            // ---- S pair for s-cols 16j..16j+15 ----
            float Sp[2][4];
            #pragma unroll
            for (int fh = 0; fh < 2; fh++)
                #pragma unroll
                for (int e = 0; e < 4; e++) Sp[fh][e] = 0.f;

            int nr = j * 16 + lr16;
            #pragma unroll
            for (int k = 0; k < 4; k++) {
                uint32_t bb[4];
                ldsm_x4(bb[0], bb[1], bb[2], bb[3],
                        sbK + (uint32_t)(nr * LDS + k * 16 + lgo) * 2);
                uint32_t blo[2] = { bb[0], bb[2] };
                uint32_t bhi[2] = { bb[1], bb[3] };
                mma_f16(Sp[0], qf[k], blo);
                mma_f16(Sp[1], qf[k], bhi);
            }

            // ---- bias + mask + exp ----
            float p[2][4];
            #pragma unroll
            for (int fh = 0; fh < 2; fh++) {
                int f = 2 * j + fh;
                #pragma unroll
                for (int e = 0; e < 4; e++) {
                    int col = 8 * f + c0l + (e & 1);
                    int rr  = trow0 + ((e >> 1) << 3);
                    float sv = Sp[fh][e] + sb2[col];
                    bool ok = !diag || (s0 + col <= rr);
                    float pv = ok ? __expf(sv) : 0.f;
                    p[fh][e] = pv;
                    if (e < 2) ls0 += pv; else ls1 += pv;
                }
            }

            // ---- split P hi/lo fp16 (exact pair) ----
            uint32_t Ah_[4], Al_[4];
            #pragma unroll
            for (int fh = 0; fh < 2; fh++) {
                #pragma unroll
                for (int hh = 0; hh < 2; hh++) {
                    float v0 = p[fh][2 * hh], v1 = p[fh][2 * hh + 1];
                    uint32_t ph = pack_f16(v0, v1);
                    Ah_[2 * fh + hh] = ph;
                    __half2 hb = *(__half2*)&ph;
                    Al_[2 * fh + hh] = pack_f16(v0 - __half2float(hb.x),
                                                v1 - __half2float(hb.y));
                }
            }

            // ---- PV: 2 terms ----
            int srow = j * 16 + lr16;
            #pragma unroll
            for (int dg = 0; dg < 4; dg++) {
                uint32_t v4[4];
                ldsm_x4_t(v4[0], v4[1], v4[2], v4[3],
                          sbV + (uint32_t)(srow * LDS + dg * 16 + lgo) * 2);
                uint32_t b0[2] = { v4[0], v4[1] };
                uint32_t b1[2] = { v4[2], v4[3] };
                mma_f16(yacc[2 * dg],     Ah_, b0);
                mma_f16(yacc[2 * dg + 1], Ah_, b1);
                mma_f16(yacc[2 * dg],     Al_, b0);
                mma_f16(yacc[2 * dg + 1], Al_, b1);
            }
        }
    }

    // row-sum across the 4 lanes sharing each row
    ls0 += __shfl_xor_sync(0xffffffffu, ls0, 1);
    ls0 += __shfl_xor_sync(0xffffffffu, ls0, 2);
    ls1 += __shfl_xor_sync(0xffffffffu, ls1, 1);
    ls1 += __shfl_xor_sync(0xffffffffu, ls1, 2);
    float inv0 = 1.f / ls0, inv1 = 1.f / ls1;

    #pragma unroll
    for (int half = 0; half < 2; half++) {
        int t = trow0 + half * 8;
        if (t < T_SEQ) {
            float inv = half ? inv1 : inv0;
            size_t base = ((size_t)b * T_SEQ + t) * C_DIM + h * DK;
            #pragma unroll
            for (int j = 0; j < 8; j++) {
                float v0 = yacc[j][2 * half + 0] * inv;
                float v1 = yacc[j][2 * half + 1] * inv;
                __half h0 = __float2half_rn(v0);
                __half h1 = __float2half_rn(v1);
                __half2 hp, lp;
                hp.x = h0; hp.y = h1;
                lp.x = __float2half_rn(v0 - __half2float(h0));
                lp.y = __float2half_rn(v1 - __half2float(h1));
                int col = j * 8 + c0l;
                *(__half2*)&Yh[base + col] = hp;
                *(__half2*)&Yl[base + col] = lp;
            }
        }
    }
}

// ---------------------------------------------------------------------------
extern "C" void kernel_launch(void* const* d_in, const int* in_sizes, int n_in,
                              void* d_out, int out_size)
{
    const float* x       = (const float*)d_in[0];
    const float* w1_w    = (const float*)d_in[1];
    const float* w1_b    = (const float*)d_in[2];
    const float* w2      = (const float*)d_in[3];
    const float* b2      = (const float*)d_in[4];
    const float* value_w = (const float*)d_in[5];
    const float* value_b = (const float*)d_in[6];
    const float* proj_w  = (const float*)d_in[7];
    const float* proj_b  = (const float*)d_in[8];
    float* out = (float*)d_out;

    __half *xh, *xl, *qb, *vs, *yh, *yl, *w1s, *vws, *pws, *w2t;
    cudaGetSymbolAddress((void**)&xh,  g_xh);  cudaGetSymbolAddress((void**)&xl,  g_xl);
    cudaGetSymbolAddress((void**)&qb,  g_qb);  cudaGetSymbolAddress((void**)&vs,  g_vs);
    cudaGetSymbolAddress((void**)&yh,  g_yh);  cudaGetSymbolAddress((void**)&yl,  g_yl);
    cudaGetSymbolAddress((void**)&w1s, g_w1s); cudaGetSymbolAddress((void**)&vws, g_vws);
    cudaGetSymbolAddress((void**)&pws, g_pws); cudaGetSymbolAddress((void**)&w2t, g_w2t);

    cudaFuncSetAttribute(gemm_mma<1,1>, cudaFuncAttributeMaxDynamicSharedMemorySize, GSMEM2);
    cudaFuncSetAttribute(gemm_mma<2,3>, cudaFuncAttributeMaxDynamicSharedMemorySize, GSMEM3);
    cudaFuncSetAttribute(gemm_mma<2,0>, cudaFuncAttributeMaxDynamicSharedMemorySize, GSMEM3);
    cudaFuncSetAttribute(attn_mma,      cudaFuncAttributeMaxDynamicSharedMemorySize, ASMEM);

    const int NX = R_ROWS * C_DIM;
    const int NW = C_DIM * C_DIM;
    cvt_hilo_h<<<NX / 4 / 256, 256>>>(x, xh, xl, NX);
    cvt_h<<<NW / 4 / 256, 256>>>(w1_w,    w1s, NW);
    cvt_h<<<NW / 4 / 256, 256>>>(value_w, vws, NW);
    cvt_h<<<NW / 4 / 256, 256>>>(proj_w,  pws, NW);
    prep_w2t<<<(1024 * DK) / 256, 256>>>(w2, w2t);

    dim3 ggrid(C_DIM / BN, (R_ROWS + BM - 1) / BM);   // (8, 64)
    // relu/Q path: single-fp16 both sides (error provably negligible via scores)
    gemm_mma<1,1><<<ggrid, 256, GSMEM2>>>(xh, nullptr, w1s, w1_b,
                                          nullptr, qb, nullptr, R_ROWS);
    // value path: A = x hi/lo (exact), B = vw fp16 -> V fp16 single out
    gemm_mma<2,3><<<ggrid, 256, GSMEM3>>>(xh, xl, vws, value_b,
                                          nullptr, vs, nullptr, R_ROWS);

    attn_mma<<<dim3(8, H_NUM, B_SZ), 256, ASMEM>>>(qb, vs, w2t, b2, yh, yl);

    // projection: A = y hi/lo (exact), B = pw fp16 -> f32 out
    gemm_mma<2,0><<<ggrid, 256, GSMEM3>>>(yh, yl, pws, proj_b,
                                          out, nullptr, nullptr, R_ROWS);
}

// round 9
// speedup vs baseline: 12.0395x; 1.3958x over previous
#include <cuda_runtime.h>
#include <cuda_fp16.h>
#include <cstdint>

#define B_SZ   8
#define T_SEQ  1023
#define C_DIM  1024
#define H_NUM  16
#define DK     64
#define R_ROWS (B_SZ * T_SEQ)   // 8184

// ---------------- scratch (__device__ globals: allocation-free contract) ----
__device__ __half g_xb [(size_t)R_ROWS * C_DIM];   // x fp16
__device__ __half g_qb [(size_t)R_ROWS * C_DIM];   // relu_out fp16 (Q)
__device__ __half g_vs [(size_t)R_ROWS * C_DIM];   // value fp16
__device__ __half g_yh [(size_t)R_ROWS * C_DIM];   // attn out fp16
__device__ __half g_w1s[(size_t)C_DIM * C_DIM];
__device__ __half g_vws[(size_t)C_DIM * C_DIM];
__device__ __half g_pws[(size_t)C_DIM * C_DIM];
__device__ __half g_w2t[(size_t)1024 * DK];        // w2 transposed fp16, padded

// ---------------- tensor-core helpers (base-target sm_80+ class) -----------
__device__ __forceinline__ uint32_t smem_to_u32(const void* p) {
    uint32_t a;
    asm("{ .reg .u64 t; cvta.to.shared.u64 t, %1; cvt.u32.u64 %0, t; }"
        : "=r"(a) : "l"(p));
    return a;
}
__device__ __forceinline__ void ldsm_x4(uint32_t& r0, uint32_t& r1,
                                        uint32_t& r2, uint32_t& r3, uint32_t addr) {
    asm volatile("ldmatrix.sync.aligned.m8n8.x4.shared.b16 {%0,%1,%2,%3}, [%4];"
                 : "=r"(r0), "=r"(r1), "=r"(r2), "=r"(r3) : "r"(addr));
}
__device__ __forceinline__ void ldsm_x4_t(uint32_t& r0, uint32_t& r1,
                                          uint32_t& r2, uint32_t& r3, uint32_t addr) {
    asm volatile("ldmatrix.sync.aligned.m8n8.x4.trans.shared.b16 {%0,%1,%2,%3}, [%4];"
                 : "=r"(r0), "=r"(r1), "=r"(r2), "=r"(r3) : "r"(addr));
}
__device__ __forceinline__ void mma_f16(float* c, const uint32_t* a, const uint32_t* b) {
    asm volatile(
        "mma.sync.aligned.m16n8k16.row.col.f32.f16.f16.f32 "
        "{%0,%1,%2,%3}, {%4,%5,%6,%7}, {%8,%9}, {%0,%1,%2,%3};"
        : "+f"(c[0]), "+f"(c[1]), "+f"(c[2]), "+f"(c[3])
        : "r"(a[0]), "r"(a[1]), "r"(a[2]), "r"(a[3]), "r"(b[0]), "r"(b[1]));
}
__device__ __forceinline__ uint32_t pack_f16(float lo, float hi) {
    uint32_t r;
    asm("cvt.rn.f16x2.f32 %0, %1, %2;" : "=r"(r) : "f"(hi), "f"(lo));
    return r;
}

// ---------------------------------------------------------------------------
// conversions
// ---------------------------------------------------------------------------
__global__ void cvt_h(const float* __restrict__ in, __half* __restrict__ out, int n)
{
    int i = (blockIdx.x * blockDim.x + threadIdx.x) * 4;
    if (i < n) {
        float4 v = *(const float4*)(in + i);
        __half2 a, b;
        a.x = __float2half_rn(v.x); a.y = __float2half_rn(v.y);
        b.x = __float2half_rn(v.z); b.y = __float2half_rn(v.w);
        *(__half2*)(out + i)     = a;
        *(__half2*)(out + i + 2) = b;
    }
}

// w2 [DK][T_SEQ] f32  ->  w2t [1024][DK] fp16 (row 1023 zero-padded)
__global__ void prep_w2t(const float* __restrict__ w2, __half* __restrict__ w2t)
{
    int idx = blockIdx.x * 256 + threadIdx.x;     // 1024*64
    int s = idx >> 6, d = idx & 63;
    float v = (s < T_SEQ) ? w2[d * T_SEQ + s] : 0.f;
    w2t[idx] = __float2half_rn(v);
}

// ---------------------------------------------------------------------------
// Single-term fp16 HMMA GEMM core (CTA 128x128, 8 warps 2x4, warp 64x32).
// ---------------------------------------------------------------------------
#define BM  128
#define BN  128
#define BK  64
#define LDS 72
#define TILE_ELEMS (BM * LDS)
#define GSMEM (2 * TILE_ELEMS * 2)            // A + B tiles: 36864 bytes

// Fused QV GEMM: blockIdx.x < 8 -> relu(x@w1^T + w1_b) -> qb
//                blockIdx.x >= 8 -> x@vw^T + value_b  -> vs
__global__ __launch_bounds__(256, 2)
void gemm_qv(const __half* __restrict__ A0,
             const __half* __restrict__ W1, const __half* __restrict__ VW,
             const float* __restrict__ b1, const float* __restrict__ bv,
             __half* __restrict__ Oq, __half* __restrict__ Ov, int R)
{
    extern __shared__ __half sm[];
    __half* sA = sm;
    __half* sB = sm + TILE_ELEMS;

    const int  tid  = threadIdx.x;
    const int  wid  = tid >> 5;
    const int  lane = tid & 31;
    const int  wm   = wid >> 2;
    const int  wn   = wid & 3;
    const int  m0   = blockIdx.y * BM;
    const bool isQ  = (blockIdx.x < 8);
    const int  n0   = (isQ ? blockIdx.x : blockIdx.x - 8) * BN;
    const __half* B   = isQ ? W1 : VW;
    const float*  bias = isQ ? b1 : bv;
    __half* O = isQ ? Oq : Ov;

    const uint32_t sbA = smem_to_u32(sA);
    const uint32_t sbB = smem_to_u32(sB);

    float acc[4][4][4];
    #pragma unroll
    for (int f = 0; f < 4; f++)
        #pragma unroll
        for (int j = 0; j < 4; j++)
            #pragma unroll
            for (int e = 0; e < 4; e++) acc[f][j][e] = 0.f;

    const int a_r = wm * 64 + (lane & 15);
    const int b_r = wn * 32 + (lane & 15);
    const int l_c = (lane >> 4) << 3;

    for (int k0 = 0; k0 < C_DIM; k0 += BK) {
        #pragma unroll
        for (int i = 0; i < 4; i++) {
            int g   = tid + i * 256;
            int row = g >> 3;
            int c8  = (g & 7) * 8;
            int so  = row * LDS + c8;
            uint4 z = make_uint4(0u, 0u, 0u, 0u);
            bool av = (m0 + row) < R;
            *(uint4*)(sA + so) = av
                ? *(const uint4*)(A0 + (size_t)(m0 + row) * C_DIM + k0 + c8) : z;
            *(uint4*)(sB + so) =
                *(const uint4*)(B + (size_t)(n0 + row) * C_DIM + k0 + c8);
        }
        __syncthreads();

        #pragma unroll
        for (int kk = 0; kk < BK; kk += 16) {
            uint32_t af[4][4], bh[2][4];
            #pragma unroll
            for (int p = 0; p < 2; p++) {
                uint32_t off = (uint32_t)((b_r + p * 16) * LDS + kk + l_c) * 2;
                ldsm_x4(bh[p][0], bh[p][1], bh[p][2], bh[p][3], sbB + off);
            }
            #pragma unroll
            for (int f = 0; f < 4; f++) {
                uint32_t off = (uint32_t)((a_r + f * 16) * LDS + kk + l_c) * 2;
                ldsm_x4(af[f][0], af[f][1], af[f][2], af[f][3], sbA + off);
            }
            #pragma unroll
            for (int f = 0; f < 4; f++)
                #pragma unroll
                for (int j = 0; j < 4; j++) {
                    int p = j >> 1, hh = j & 1;
                    uint32_t bfr[2] = { bh[p][hh], bh[p][2 + hh] };
                    mma_f16(acc[f][j], af[f], bfr);
                }
        }
        __syncthreads();
    }

    const int qr = lane >> 2;
    const int qc = (lane & 3) * 2;
    #pragma unroll
    for (int f = 0; f < 4; f++) {
        #pragma unroll
        for (int j = 0; j < 4; j++) {
            int col = n0 + wn * 32 + j * 8 + qc;
            float b0 = bias[col], b1v = bias[col + 1];
            #pragma unroll
            for (int half = 0; half < 2; half++) {
                int row = m0 + wm * 64 + f * 16 + qr + half * 8;
                if (row < R) {
                    float v0 = acc[f][j][half * 2 + 0] + b0;
                    float v1 = acc[f][j][half * 2 + 1] + b1v;
                    if (isQ) { v0 = fmaxf(v0, 0.f); v1 = fmaxf(v1, 0.f); }
                    __half2 hp;
                    hp.x = __float2half_rn(v0); hp.y = __float2half_rn(v1);
                    *(__half2*)&O[(size_t)row * C_DIM + col] = hp;
                }
            }
        }
    }
}

// Projection GEMM: out = y @ pw^T + proj_b (f32 out), single term.
__global__ __launch_bounds__(256, 2)
void gemm_proj(const __half* __restrict__ A0, const __half* __restrict__ B,
               const float* __restrict__ bias, float* __restrict__ O, int R)
{
    extern __shared__ __half sm[];
    __half* sA = sm;
    __half* sB = sm + TILE_ELEMS;

    const int tid  = threadIdx.x;
    const int wid  = tid >> 5;
    const int lane = tid & 31;
    const int wm   = wid >> 2;
    const int wn   = wid & 3;
    const int m0   = blockIdx.y * BM;
    const int n0   = blockIdx.x * BN;

    const uint32_t sbA = smem_to_u32(sA);
    const uint32_t sbB = smem_to_u32(sB);

    float acc[4][4][4];
    #pragma unroll
    for (int f = 0; f < 4; f++)
        #pragma unroll
        for (int j = 0; j < 4; j++)
            #pragma unroll
            for (int e = 0; e < 4; e++) acc[f][j][e] = 0.f;

    const int a_r = wm * 64 + (lane & 15);
    const int b_r = wn * 32 + (lane & 15);
    const int l_c = (lane >> 4) << 3;

    for (int k0 = 0; k0 < C_DIM; k0 += BK) {
        #pragma unroll
        for (int i = 0; i < 4; i++) {
            int g   = tid + i * 256;
            int row = g >> 3;
            int c8  = (g & 7) * 8;
            int so  = row * LDS + c8;
            uint4 z = make_uint4(0u, 0u, 0u, 0u);
            bool av = (m0 + row) < R;
            *(uint4*)(sA + so) = av
                ? *(const uint4*)(A0 + (size_t)(m0 + row) * C_DIM + k0 + c8) : z;
            *(uint4*)(sB + so) =
                *(const uint4*)(B + (size_t)(n0 + row) * C_DIM + k0 + c8);
        }
        __syncthreads();

        #pragma unroll
        for (int kk = 0; kk < BK; kk += 16) {
            uint32_t af[4][4], bh[2][4];
            #pragma unroll
            for (int p = 0; p < 2; p++) {
                uint32_t off = (uint32_t)((b_r + p * 16) * LDS + kk + l_c) * 2;
                ldsm_x4(bh[p][0], bh[p][1], bh[p][2], bh[p][3], sbB + off);
            }
            #pragma unroll
            for (int f = 0; f < 4; f++) {
                uint32_t off = (uint32_t)((a_r + f * 16) * LDS + kk + l_c) * 2;
                ldsm_x4(af[f][0], af[f][1], af[f][2], af[f][3], sbA + off);
            }
            #pragma unroll
            for (int f = 0; f < 4; f++)
                #pragma unroll
                for (int j = 0; j < 4; j++) {
                    int p = j >> 1, hh = j & 1;
                    uint32_t bfr[2] = { bh[p][hh], bh[p][2 + hh] };
                    mma_f16(acc[f][j], af[f], bfr);
                }
        }
        __syncthreads();
    }

    const int qr = lane >> 2;
    const int qc = (lane & 3) * 2;
    #pragma unroll
    for (int f = 0; f < 4; f++) {
        #pragma unroll
        for (int j = 0; j < 4; j++) {
            int col = n0 + wn * 32 + j * 8 + qc;
            float b0 = bias[col], b1 = bias[col + 1];
            #pragma unroll
            for (int half = 0; half < 2; half++) {
                int row = m0 + wm * 64 + f * 16 + qr + half * 8;
                if (row < R) {
                    float v0 = acc[f][j][half * 2 + 0] + b0;
                    float v1 = acc[f][j][half * 2 + 1] + b1;
                    *(float2*)&O[(size_t)row * C_DIM + col] = make_float2(v0, v1);
                }
            }
        }
    }
}

// ---------------------------------------------------------------------------
// HMMA fp16 flash attention (R8 structure; emits single-fp16 Y).
// ---------------------------------------------------------------------------
#define ATE (128 * LDS)
#define ASMEM (3 * ATE * 2 + 512)            // Q + K + V tiles + b2

__global__ __launch_bounds__(256, 2)
void attn_mma(const __half* __restrict__ Q, const __half* __restrict__ V,
              const __half* __restrict__ w2t, const float* __restrict__ b2,
              __half* __restrict__ Yh)
{
    extern __shared__ __half asmem[];
    __half* sQ = asmem;
    __half* sK = asmem + ATE;
    __half* sV = asmem + 2 * ATE;
    float* sb2 = (float*)(asmem + 3 * ATE);

    const uint32_t sbQ = smem_to_u32(sQ);
    const uint32_t sbK = smem_to_u32(sK);
    const uint32_t sbV = smem_to_u32(sV);

    const int b    = blockIdx.z;
    const int h    = blockIdx.y;
    const int qt   = (int)(gridDim.x - 1) - (int)blockIdx.x;   // heavy first
    const int m0   = qt * 128;
    const int tid  = threadIdx.x;
    const int wid  = tid >> 5;
    const int lane = tid & 31;
    const int mw   = wid * 16;

    for (int idx = tid; idx < 1024; idx += 256) {
        int row = idx >> 3, c8 = (idx & 7) * 8;
        int t = m0 + row; if (t > T_SEQ - 1) t = T_SEQ - 1;
        *(uint4*)(sQ + row * LDS + c8) =
            *(const uint4*)(Q + ((size_t)b * T_SEQ + t) * C_DIM + h * DK + c8);
    }
    __syncthreads();

    uint32_t qf[4][4];
    {
        int r  = mw + (lane & 15);
        int cg = (lane >> 4) << 3;
        #pragma unroll
        for (int k = 0; k < 4; k++)
            ldsm_x4(qf[k][0], qf[k][1], qf[k][2], qf[k][3],
                    sbQ + (uint32_t)(r * LDS + k * 16 + cg) * 2);
    }

    float yacc[8][4];
    #pragma unroll
    for (int j = 0; j < 8; j++)
        #pragma unroll
        for (int e = 0; e < 4; e++) yacc[j][e] = 0.f;
    float ls0 = 0.f, ls1 = 0.f;

    const int r0    = lane >> 2;
    const int c0l   = (lane & 3) * 2;
    const int trow0 = m0 + mw + r0;
    const int lgo   = (lane >> 4) << 3;
    const int lr16  = lane & 15;

    for (int nt = 0; nt <= qt; nt++) {
        const int s0 = nt * 128;
        __syncthreads();
        for (int idx = tid; idx < 1024; idx += 256) {
            int row = idx >> 3, c8 = (idx & 7) * 8;
            int so = row * LDS + c8;
            *(uint4*)(sK + so) = *(const uint4*)(w2t + (size_t)(s0 + row) * DK + c8);
            int s = s0 + row; if (s > T_SEQ - 1) s = T_SEQ - 1;
            *(uint4*)(sV + so) =
                *(const uint4*)(V + ((size_t)b * T_SEQ + s) * C_DIM + h * DK + c8);
        }
        if (tid < 128) {
            int s = s0 + tid;
            sb2[tid] = (s < T_SEQ) ? b2[s] : 0.f;
        }
        __syncthreads();

        const bool diag = (nt == qt);
        #pragma unroll
        for (int j = 0; j < 8; j++) {
            float Sp[2][4];
            #pragma unroll
            for (int fh = 0; fh < 2; fh++)
                #pragma unroll
                for (int e = 0; e < 4; e++) Sp[fh][e] = 0.f;

            int nr = j * 16 + lr16;
            #pragma unroll
            for (int k = 0; k < 4; k++) {
                uint32_t bb[4];
                ldsm_x4(bb[0], bb[1], bb[2], bb[3],
                        sbK + (uint32_t)(nr * LDS + k * 16 + lgo) * 2);
                uint32_t blo[2] = { bb[0], bb[2] };
                uint32_t bhi[2] = { bb[1], bb[3] };
                mma_f16(Sp[0], qf[k], blo);
                mma_f16(Sp[1], qf[k], bhi);
            }

            float p[2][4];
            #pragma unroll
            for (int fh = 0; fh < 2; fh++) {
                int f = 2 * j + fh;
                #pragma unroll
                for (int e = 0; e < 4; e++) {
                    int col = 8 * f + c0l + (e & 1);
                    int rr  = trow0 + ((e >> 1) << 3);
                    float sv = Sp[fh][e] + sb2[col];
                    bool ok = !diag || (s0 + col <= rr);
                    float pv = ok ? __expf(sv) : 0.f;
                    p[fh][e] = pv;
                    if (e < 2) ls0 += pv; else ls1 += pv;
                }
            }

            uint32_t Ah_[4], Al_[4];
            #pragma unroll
            for (int fh = 0; fh < 2; fh++) {
                #pragma unroll
                for (int hh = 0; hh < 2; hh++) {
                    float v0 = p[fh][2 * hh], v1 = p[fh][2 * hh + 1];
                    uint32_t ph = pack_f16(v0, v1);
                    Ah_[2 * fh + hh] = ph;
                    __half2 hb = *(__half2*)&ph;
                    Al_[2 * fh + hh] = pack_f16(v0 - __half2float(hb.x),
                                                v1 - __half2float(hb.y));
                }
            }

            int srow = j * 16 + lr16;
            #pragma unroll
            for (int dg = 0; dg < 4; dg++) {
                uint32_t v4[4];
                ldsm_x4_t(v4[0], v4[1], v4[2], v4[3],
                          sbV + (uint32_t)(srow * LDS + dg * 16 + lgo) * 2);
                uint32_t b0[2] = { v4[0], v4[1] };
                uint32_t b1[2] = { v4[2], v4[3] };
                mma_f16(yacc[2 * dg],     Ah_, b0);
                mma_f16(yacc[2 * dg + 1], Ah_, b1);
                mma_f16(yacc[2 * dg],     Al_, b0);
                mma_f16(yacc[2 * dg + 1], Al_, b1);
            }
        }
    }

    ls0 += __shfl_xor_sync(0xffffffffu, ls0, 1);
    ls0 += __shfl_xor_sync(0xffffffffu, ls0, 2);
    ls1 += __shfl_xor_sync(0xffffffffu, ls1, 1);
    ls1 += __shfl_xor_sync(0xffffffffu, ls1, 2);
    float inv0 = 1.f / ls0, inv1 = 1.f / ls1;

    #pragma unroll
    for (int half = 0; half < 2; half++) {
        int t = trow0 + half * 8;
        if (t < T_SEQ) {
            float inv = half ? inv1 : inv0;
            size_t base = ((size_t)b * T_SEQ + t) * C_DIM + h * DK;
            #pragma unroll
            for (int j = 0; j < 8; j++) {
                float v0 = yacc[j][2 * half + 0] * inv;
                float v1 = yacc[j][2 * half + 1] * inv;
                __half2 hp;
                hp.x = __float2half_rn(v0); hp.y = __float2half_rn(v1);
                *(__half2*)&Yh[base + j * 8 + c0l] = hp;
            }
        }
    }
}

// ---------------------------------------------------------------------------
extern "C" void kernel_launch(void* const* d_in, const int* in_sizes, int n_in,
                              void* d_out, int out_size)
{
    const float* x       = (const float*)d_in[0];
    const float* w1_w    = (const float*)d_in[1];
    const float* w1_b    = (const float*)d_in[2];
    const float* w2      = (const float*)d_in[3];
    const float* b2      = (const float*)d_in[4];
    const float* value_w = (const float*)d_in[5];
    const float* value_b = (const float*)d_in[6];
    const float* proj_w  = (const float*)d_in[7];
    const float* proj_b  = (const float*)d_in[8];
    float* out = (float*)d_out;

    __half *xb, *qb, *vs, *yh, *w1s, *vws, *pws, *w2t;
    cudaGetSymbolAddress((void**)&xb,  g_xb);
    cudaGetSymbolAddress((void**)&qb,  g_qb);  cudaGetSymbolAddress((void**)&vs,  g_vs);
    cudaGetSymbolAddress((void**)&yh,  g_yh);
    cudaGetSymbolAddress((void**)&w1s, g_w1s); cudaGetSymbolAddress((void**)&vws, g_vws);
    cudaGetSymbolAddress((void**)&pws, g_pws); cudaGetSymbolAddress((void**)&w2t, g_w2t);

    cudaFuncSetAttribute(gemm_qv,   cudaFuncAttributeMaxDynamicSharedMemorySize, GSMEM);
    cudaFuncSetAttribute(gemm_proj, cudaFuncAttributeMaxDynamicSharedMemorySize, GSMEM);
    cudaFuncSetAttribute(attn_mma,  cudaFuncAttributeMaxDynamicSharedMemorySize, ASMEM);

    const int NX = R_ROWS * C_DIM;
    const int NW = C_DIM * C_DIM;
    cvt_h<<<NX / 4 / 256, 256>>>(x, xb, NX);
    cvt_h<<<NW / 4 / 256, 256>>>(w1_w,    w1s, NW);
    cvt_h<<<NW / 4 / 256, 256>>>(value_w, vws, NW);
    cvt_h<<<NW / 4 / 256, 256>>>(proj_w,  pws, NW);
    prep_w2t<<<(1024 * DK) / 256, 256>>>(w2, w2t);

    // fused relu + value GEMMs (1024 CTAs, single wave-train)
    gemm_qv<<<dim3(16, 64), 256, GSMEM>>>(xb, w1s, vws, w1_b, value_b, qb, vs, R_ROWS);

    attn_mma<<<dim3(8, H_NUM, B_SZ), 256, ASMEM>>>(qb, vs, w2t, b2, yh);

    gemm_proj<<<dim3(8, 64), 256, GSMEM>>>(yh, pws, proj_b, out, R_ROWS);
}

// round 10
// speedup vs baseline: 12.4561x; 1.0346x over previous
#include <cuda_runtime.h>
#include <cuda_fp16.h>
#include <cstdint>

#define B_SZ   8
#define T_SEQ  1023
#define C_DIM  1024
#define H_NUM  16
#define DK     64
#define R_ROWS (B_SZ * T_SEQ)   // 8184

// ---------------- scratch (__device__ globals: allocation-free contract) ----
__device__ __half g_xb [(size_t)R_ROWS * C_DIM];   // x fp16
__device__ __half g_qb [(size_t)R_ROWS * C_DIM];   // relu_out fp16 (Q)
__device__ __half g_vs [(size_t)R_ROWS * C_DIM];   // value fp16
__device__ __half g_yh [(size_t)R_ROWS * C_DIM];   // attn out fp16
__device__ __half g_w1s[(size_t)C_DIM * C_DIM];
__device__ __half g_vws[(size_t)C_DIM * C_DIM];
__device__ __half g_pws[(size_t)C_DIM * C_DIM];
__device__ __half g_w2t[(size_t)1024 * DK];        // w2 transposed fp16, padded

// ---------------- tensor-core helpers (base-target sm_80+ class) -----------
__device__ __forceinline__ uint32_t smem_to_u32(const void* p) {
    uint32_t a;
    asm("{ .reg .u64 t; cvta.to.shared.u64 t, %1; cvt.u32.u64 %0, t; }"
        : "=r"(a) : "l"(p));
    return a;
}
__device__ __forceinline__ void ldsm_x4(uint32_t& r0, uint32_t& r1,
                                        uint32_t& r2, uint32_t& r3, uint32_t addr) {
    asm volatile("ldmatrix.sync.aligned.m8n8.x4.shared.b16 {%0,%1,%2,%3}, [%4];"
                 : "=r"(r0), "=r"(r1), "=r"(r2), "=r"(r3) : "r"(addr));
}
__device__ __forceinline__ void ldsm_x4_t(uint32_t& r0, uint32_t& r1,
                                          uint32_t& r2, uint32_t& r3, uint32_t addr) {
    asm volatile("ldmatrix.sync.aligned.m8n8.x4.trans.shared.b16 {%0,%1,%2,%3}, [%4];"
                 : "=r"(r0), "=r"(r1), "=r"(r2), "=r"(r3) : "r"(addr));
}
__device__ __forceinline__ void mma_f16(float* c, const uint32_t* a, const uint32_t* b) {
    asm volatile(
        "mma.sync.aligned.m16n8k16.row.col.f32.f16.f16.f32 "
        "{%0,%1,%2,%3}, {%4,%5,%6,%7}, {%8,%9}, {%0,%1,%2,%3};"
        : "+f"(c[0]), "+f"(c[1]), "+f"(c[2]), "+f"(c[3])
        : "r"(a[0]), "r"(a[1]), "r"(a[2]), "r"(a[3]), "r"(b[0]), "r"(b[1]));
}
__device__ __forceinline__ uint32_t pack_f16(float lo, float hi) {
    uint32_t r;
    asm("cvt.rn.f16x2.f32 %0, %1, %2;" : "=r"(r) : "f"(hi), "f"(lo));
    return r;
}

// ---------------------------------------------------------------------------
// conversions
// ---------------------------------------------------------------------------
__global__ void cvt_h(const float* __restrict__ in, __half* __restrict__ out, int n)
{
    int i = (blockIdx.x * blockDim.x + threadIdx.x) * 4;
    if (i < n) {
        float4 v = *(const float4*)(in + i);
        __half2 a, b;
        a.x = __float2half_rn(v.x); a.y = __float2half_rn(v.y);
        b.x = __float2half_rn(v.z); b.y = __float2half_rn(v.w);
        *(__half2*)(out + i)     = a;
        *(__half2*)(out + i + 2) = b;
    }
}

// w2 [DK][T_SEQ] f32  ->  w2t [1024][DK] fp16 (row 1023 zero-padded)
__global__ void prep_w2t(const float* __restrict__ w2, __half* __restrict__ w2t)
{
    int idx = blockIdx.x * 256 + threadIdx.x;     // 1024*64
    int s = idx >> 6, d = idx & 63;
    float v = (s < T_SEQ) ? w2[d * T_SEQ + s] : 0.f;
    w2t[idx] = __float2half_rn(v);
}

// ---------------------------------------------------------------------------
// Single-term fp16 HMMA GEMM core (CTA 128x128, 8 warps 2x4, warp 64x32).
// ---------------------------------------------------------------------------
#define BM  128
#define BN  128
#define BK  64
#define LDS 72
#define TILE_ELEMS (BM * LDS)
#define GSMEM (2 * TILE_ELEMS * 2)            // A + B tiles: 36864 bytes

// Fused QV GEMM: blockIdx.x < 8 -> relu(x@w1^T + w1_b) -> qb
//                blockIdx.x >= 8 -> x@vw^T + value_b  -> vs
__global__ __launch_bounds__(256, 2)
void gemm_qv(const __half* __restrict__ A0,
             const __half* __restrict__ W1, const __half* __restrict__ VW,
             const float* __restrict__ b1, const float* __restrict__ bv,
             __half* __restrict__ Oq, __half* __restrict__ Ov, int R)
{
    extern __shared__ __half sm[];
    __half* sA = sm;
    __half* sB = sm + TILE_ELEMS;

    const int  tid  = threadIdx.x;
    const int  wid  = tid >> 5;
    const int  lane = tid & 31;
    const int  wm   = wid >> 2;
    const int  wn   = wid & 3;
    const int  m0   = blockIdx.y * BM;
    const bool isQ  = (blockIdx.x < 8);
    const int  n0   = (isQ ? blockIdx.x : blockIdx.x - 8) * BN;
    const __half* B    = isQ ? W1 : VW;
    const float*  bias = isQ ? b1 : bv;
    __half* O = isQ ? Oq : Ov;

    const uint32_t sbA = smem_to_u32(sA);
    const uint32_t sbB = smem_to_u32(sB);

    float acc[4][4][4];
    #pragma unroll
    for (int f = 0; f < 4; f++)
        #pragma unroll
        for (int j = 0; j < 4; j++)
            #pragma unroll
            for (int e = 0; e < 4; e++) acc[f][j][e] = 0.f;

    const int a_r = wm * 64 + (lane & 15);
    const int b_r = wn * 32 + (lane & 15);
    const int l_c = (lane >> 4) << 3;

    for (int k0 = 0; k0 < C_DIM; k0 += BK) {
        #pragma unroll
        for (int i = 0; i < 4; i++) {
            int g   = tid + i * 256;
            int row = g >> 3;
            int c8  = (g & 7) * 8;
            int so  = row * LDS + c8;
            uint4 z = make_uint4(0u, 0u, 0u, 0u);
            bool av = (m0 + row) < R;
            *(uint4*)(sA + so) = av
                ? *(const uint4*)(A0 + (size_t)(m0 + row) * C_DIM + k0 + c8) : z;
            *(uint4*)(sB + so) =
                *(const uint4*)(B + (size_t)(n0 + row) * C_DIM + k0 + c8);
        }
        __syncthreads();

        #pragma unroll
        for (int kk = 0; kk < BK; kk += 16) {
            uint32_t af[4][4], bh[2][4];
            #pragma unroll
            for (int p = 0; p < 2; p++) {
                uint32_t off = (uint32_t)((b_r + p * 16) * LDS + kk + l_c) * 2;
                ldsm_x4(bh[p][0], bh[p][1], bh[p][2], bh[p][3], sbB + off);
            }
            #pragma unroll
            for (int f = 0; f < 4; f++) {
                uint32_t off = (uint32_t)((a_r + f * 16) * LDS + kk + l_c) * 2;
                ldsm_x4(af[f][0], af[f][1], af[f][2], af[f][3], sbA + off);
            }
            #pragma unroll
            for (int f = 0; f < 4; f++)
                #pragma unroll
                for (int j = 0; j < 4; j++) {
                    int p = j >> 1, hh = j & 1;
                    uint32_t bfr[2] = { bh[p][hh], bh[p][2 + hh] };
                    mma_f16(acc[f][j], af[f], bfr);
                }
        }
        __syncthreads();
    }

    const int qr = lane >> 2;
    const int qc = (lane & 3) * 2;
    #pragma unroll
    for (int f = 0; f < 4; f++) {
        #pragma unroll
        for (int j = 0; j < 4; j++) {
            int col = n0 + wn * 32 + j * 8 + qc;
            float b0 = bias[col], b1v = bias[col + 1];
            #pragma unroll
            for (int half = 0; half < 2; half++) {
                int row = m0 + wm * 64 + f * 16 + qr + half * 8;
                if (row < R) {
                    float v0 = acc[f][j][half * 2 + 0] + b0;
                    float v1 = acc[f][j][half * 2 + 1] + b1v;
                    if (isQ) { v0 = fmaxf(v0, 0.f); v1 = fmaxf(v1, 0.f); }
                    __half2 hp;
                    hp.x = __float2half_rn(v0); hp.y = __float2half_rn(v1);
                    *(__half2*)&O[(size_t)row * C_DIM + col] = hp;
                }
            }
        }
    }
}

// Projection GEMM: out = y @ pw^T + proj_b (f32 out), single term.
__global__ __launch_bounds__(256, 2)
void gemm_proj(const __half* __restrict__ A0, const __half* __restrict__ B,
               const float* __restrict__ bias, float* __restrict__ O, int R)
{
    extern __shared__ __half sm[];
    __half* sA = sm;
    __half* sB = sm + TILE_ELEMS;

    const int tid  = threadIdx.x;
    const int wid  = tid >> 5;
    const int lane = tid & 31;
    const int wm   = wid >> 2;
    const int wn   = wid & 3;
    const int m0   = blockIdx.y * BM;
    const int n0   = blockIdx.x * BN;

    const uint32_t sbA = smem_to_u32(sA);
    const uint32_t sbB = smem_to_u32(sB);

    float acc[4][4][4];
    #pragma unroll
    for (int f = 0; f < 4; f++)
        #pragma unroll
        for (int j = 0; j < 4; j++)
            #pragma unroll
            for (int e = 0; e < 4; e++) acc[f][j][e] = 0.f;

    const int a_r = wm * 64 + (lane & 15);
    const int b_r = wn * 32 + (lane & 15);
    const int l_c = (lane >> 4) << 3;

    for (int k0 = 0; k0 < C_DIM; k0 += BK) {
        #pragma unroll
        for (int i = 0; i < 4; i++) {
            int g   = tid + i * 256;
            int row = g >> 3;
            int c8  = (g & 7) * 8;
            int so  = row * LDS + c8;
            uint4 z = make_uint4(0u, 0u, 0u, 0u);
            bool av = (m0 + row) < R;
            *(uint4*)(sA + so) = av
                ? *(const uint4*)(A0 + (size_t)(m0 + row) * C_DIM + k0 + c8) : z;
            *(uint4*)(sB + so) =
                *(const uint4*)(B + (size_t)(n0 + row) * C_DIM + k0 + c8);
        }
        __syncthreads();

        #pragma unroll
        for (int kk = 0; kk < BK; kk += 16) {
            uint32_t af[4][4], bh[2][4];
            #pragma unroll
            for (int p = 0; p < 2; p++) {
                uint32_t off = (uint32_t)((b_r + p * 16) * LDS + kk + l_c) * 2;
                ldsm_x4(bh[p][0], bh[p][1], bh[p][2], bh[p][3], sbB + off);
            }
            #pragma unroll
            for (int f = 0; f < 4; f++) {
                uint32_t off = (uint32_t)((a_r + f * 16) * LDS + kk + l_c) * 2;
                ldsm_x4(af[f][0], af[f][1], af[f][2], af[f][3], sbA + off);
            }
            #pragma unroll
            for (int f = 0; f < 4; f++)
                #pragma unroll
                for (int j = 0; j < 4; j++) {
                    int p = j >> 1, hh = j & 1;
                    uint32_t bfr[2] = { bh[p][hh], bh[p][2 + hh] };
                    mma_f16(acc[f][j], af[f], bfr);
                }
        }
        __syncthreads();
    }

    const int qr = lane >> 2;
    const int qc = (lane & 3) * 2;
    #pragma unroll
    for (int f = 0; f < 4; f++) {
        #pragma unroll
        for (int j = 0; j < 4; j++) {
            int col = n0 + wn * 32 + j * 8 + qc;
            float b0 = bias[col], b1 = bias[col + 1];
            #pragma unroll
            for (int half = 0; half < 2; half++) {
                int row = m0 + wm * 64 + f * 16 + qr + half * 8;
                if (row < R) {
                    float v0 = acc[f][j][half * 2 + 0] + b0;
                    float v1 = acc[f][j][half * 2 + 1] + b1;
                    *(float2*)&O[(size_t)row * C_DIM + col] = make_float2(v0, v1);
                }
            }
        }
    }
}

// ---------------------------------------------------------------------------
// HMMA fp16 flash attention, centered-P:
//   P = 1 + P'  (P' = exp(s+b2)-1 unmasked, exactly -1 masked/out-of-range)
//   y = colacc(V) + P' @ V          (single PV MMA term)
//   l = 128*(qt+1) + sum(P')
// Masked/clamped rows cancel exactly: +v (colsum) + (-1)*v (MMA) = 0.
// ---------------------------------------------------------------------------
#define ATE (128 * LDS)
#define ASMEM (3 * ATE * 2 + 512 + 4 * 64 * 4 + 64 * 4)

__global__ __launch_bounds__(256, 2)
void attn_mma(const __half* __restrict__ Q, const __half* __restrict__ V,
              const __half* __restrict__ w2t, const float* __restrict__ b2,
              __half* __restrict__ Yh)
{
    extern __shared__ __half asmem[];
    __half* sQ = asmem;
    __half* sK = asmem + ATE;
    __half* sV = asmem + 2 * ATE;
    float* sb2    = (float*)(asmem + 3 * ATE);           // 128 f32
    float* cpart  = sb2 + 128;                           // [4][64]
    float* colacc = cpart + 4 * 64;                      // [64]

    const uint32_t sbQ = smem_to_u32(sQ);
    const uint32_t sbK = smem_to_u32(sK);
    const uint32_t sbV = smem_to_u32(sV);

    const int b    = blockIdx.z;
    const int h    = blockIdx.y;
    const int qt   = (int)(gridDim.x - 1) - (int)blockIdx.x;   // heavy first
    const int m0   = qt * 128;
    const int tid  = threadIdx.x;
    const int wid  = tid >> 5;
    const int lane = tid & 31;
    const int mw   = wid * 16;

    if (tid < 64) colacc[tid] = 0.f;

    for (int idx = tid; idx < 1024; idx += 256) {
        int row = idx >> 3, c8 = (idx & 7) * 8;
        int t = m0 + row; if (t > T_SEQ - 1) t = T_SEQ - 1;
        *(uint4*)(sQ + row * LDS + c8) =
            *(const uint4*)(Q + ((size_t)b * T_SEQ + t) * C_DIM + h * DK + c8);
    }
    __syncthreads();

    uint32_t qf[4][4];
    {
        int r  = mw + (lane & 15);
        int cg = (lane >> 4) << 3;
        #pragma unroll
        for (int k = 0; k < 4; k++)
            ldsm_x4(qf[k][0], qf[k][1], qf[k][2], qf[k][3],
                    sbQ + (uint32_t)(r * LDS + k * 16 + cg) * 2);
    }

    float yacc[8][4];
    #pragma unroll
    for (int j = 0; j < 8; j++)
        #pragma unroll
        for (int e = 0; e < 4; e++) yacc[j][e] = 0.f;
    float ls0 = 0.f, ls1 = 0.f;

    const int r0    = lane >> 2;
    const int c0l   = (lane & 3) * 2;
    const int trow0 = m0 + mw + r0;
    const int lgo   = (lane >> 4) << 3;
    const int lr16  = lane & 15;

    for (int nt = 0; nt <= qt; nt++) {
        const int s0 = nt * 128;
        __syncthreads();
        for (int idx = tid; idx < 1024; idx += 256) {
            int row = idx >> 3, c8 = (idx & 7) * 8;
            int so = row * LDS + c8;
            *(uint4*)(sK + so) = *(const uint4*)(w2t + (size_t)(s0 + row) * DK + c8);
            int s = s0 + row; if (s > T_SEQ - 1) s = T_SEQ - 1;
            *(uint4*)(sV + so) =
                *(const uint4*)(V + ((size_t)b * T_SEQ + s) * C_DIM + h * DK + c8);
        }
        if (tid < 128) {
            int s = s0 + tid;
            sb2[tid] = (s < T_SEQ) ? b2[s] : 0.f;
        }
        __syncthreads();

        // ---- tile colsum of V -> colacc (f32, cooperative) ----
        {
            int d = tid & 63, g = tid >> 6;
            const __half* base = sV + (g * 32) * LDS + d;
            float cs = 0.f;
            #pragma unroll 8
            for (int i = 0; i < 32; i++)
                cs += __half2float(base[i * LDS]);
            cpart[g * 64 + d] = cs;
        }
        __syncthreads();
        if (tid < 64)
            colacc[tid] += cpart[tid] + cpart[64 + tid] + cpart[128 + tid] + cpart[192 + tid];

        const bool diag = (nt == qt);
        #pragma unroll
        for (int j = 0; j < 8; j++) {
            float Sp[2][4];
            #pragma unroll
            for (int fh = 0; fh < 2; fh++)
                #pragma unroll
                for (int e = 0; e < 4; e++) Sp[fh][e] = 0.f;

            int nr = j * 16 + lr16;
            #pragma unroll
            for (int k = 0; k < 4; k++) {
                uint32_t bb[4];
                ldsm_x4(bb[0], bb[1], bb[2], bb[3],
                        sbK + (uint32_t)(nr * LDS + k * 16 + lgo) * 2);
                uint32_t blo[2] = { bb[0], bb[2] };
                uint32_t bhi[2] = { bb[1], bb[3] };
                mma_f16(Sp[0], qf[k], blo);
                mma_f16(Sp[1], qf[k], bhi);
            }

            // centered p' = exp(s)-1 (unmasked) / exactly -1 (masked)
            float p[2][4];
            #pragma unroll
            for (int fh = 0; fh < 2; fh++) {
                int f = 2 * j + fh;
                #pragma unroll
                for (int e = 0; e < 4; e++) {
                    int col = 8 * f + c0l + (e & 1);
                    int rr  = trow0 + ((e >> 1) << 3);
                    float sv = Sp[fh][e] + sb2[col];
                    bool ok = !diag || (s0 + col <= rr);
                    float pv = ok ? (__expf(sv) - 1.0f) : -1.0f;
                    p[fh][e] = pv;
                    if (e < 2) ls0 += pv; else ls1 += pv;
                }
            }

            uint32_t Ah_[4];
            #pragma unroll
            for (int fh = 0; fh < 2; fh++) {
                Ah_[2 * fh + 0] = pack_f16(p[fh][0], p[fh][1]);
                Ah_[2 * fh + 1] = pack_f16(p[fh][2], p[fh][3]);
            }

            int srow = j * 16 + lr16;
            #pragma unroll
            for (int dg = 0; dg < 4; dg++) {
                uint32_t v4[4];
                ldsm_x4_t(v4[0], v4[1], v4[2], v4[3],
                          sbV + (uint32_t)(srow * LDS + dg * 16 + lgo) * 2);
                uint32_t b0[2] = { v4[0], v4[1] };
                uint32_t b1[2] = { v4[2], v4[3] };
                mma_f16(yacc[2 * dg],     Ah_, b0);
                mma_f16(yacc[2 * dg + 1], Ah_, b1);
            }
        }
    }
    __syncthreads();   // colacc final before epilogue reads

    ls0 += __shfl_xor_sync(0xffffffffu, ls0, 1);
    ls0 += __shfl_xor_sync(0xffffffffu, ls0, 2);
    ls1 += __shfl_xor_sync(0xffffffffu, ls1, 1);
    ls1 += __shfl_xor_sync(0xffffffffu, ls1, 2);
    const float lbase = 128.f * (float)(qt + 1);
    float inv0 = 1.f / (lbase + ls0);
    float inv1 = 1.f / (lbase + ls1);

    #pragma unroll
    for (int half = 0; half < 2; half++) {
        int t = trow0 + half * 8;
        if (t < T_SEQ) {
            float inv = half ? inv1 : inv0;
            size_t base = ((size_t)b * T_SEQ + t) * C_DIM + h * DK;
            #pragma unroll
            for (int j = 0; j < 8; j++) {
                int col = j * 8 + c0l;
                float v0 = (yacc[j][2 * half + 0] + colacc[col])     * inv;
                float v1 = (yacc[j][2 * half + 1] + colacc[col + 1]) * inv;
                __half2 hp;
                hp.x = __float2half_rn(v0); hp.y = __float2half_rn(v1);
                *(__half2*)&Yh[base + col] = hp;
            }
        }
    }
}

// ---------------------------------------------------------------------------
extern "C" void kernel_launch(void* const* d_in, const int* in_sizes, int n_in,
                              void* d_out, int out_size)
{
    const float* x       = (const float*)d_in[0];
    const float* w1_w    = (const float*)d_in[1];
    const float* w1_b    = (const float*)d_in[2];
    const float* w2      = (const float*)d_in[3];
    const float* b2      = (const float*)d_in[4];
    const float* value_w = (const float*)d_in[5];
    const float* value_b = (const float*)d_in[6];
    const float* proj_w  = (const float*)d_in[7];
    const float* proj_b  = (const float*)d_in[8];
    float* out = (float*)d_out;

    __half *xb, *qb, *vs, *yh, *w1s, *vws, *pws, *w2t;
    cudaGetSymbolAddress((void**)&xb,  g_xb);
    cudaGetSymbolAddress((void**)&qb,  g_qb);  cudaGetSymbolAddress((void**)&vs,  g_vs);
    cudaGetSymbolAddress((void**)&yh,  g_yh);
    cudaGetSymbolAddress((void**)&w1s, g_w1s); cudaGetSymbolAddress((void**)&vws, g_vws);
    cudaGetSymbolAddress((void**)&pws, g_pws); cudaGetSymbolAddress((void**)&w2t, g_w2t);

    cudaFuncSetAttribute(gemm_qv,   cudaFuncAttributeMaxDynamicSharedMemorySize, GSMEM);
    cudaFuncSetAttribute(gemm_proj, cudaFuncAttributeMaxDynamicSharedMemorySize, GSMEM);
    cudaFuncSetAttribute(attn_mma,  cudaFuncAttributeMaxDynamicSharedMemorySize, ASMEM);

    const int NX = R_ROWS * C_DIM;
    const int NW = C_DIM * C_DIM;
    cvt_h<<<NX / 4 / 256, 256>>>(x, xb, NX);
    cvt_h<<<NW / 4 / 256, 256>>>(w1_w,    w1s, NW);
    cvt_h<<<NW / 4 / 256, 256>>>(value_w, vws, NW);
    cvt_h<<<NW / 4 / 256, 256>>>(proj_w,  pws, NW);
    prep_w2t<<<(1024 * DK) / 256, 256>>>(w2, w2t);

    gemm_qv<<<dim3(16, 64), 256, GSMEM>>>(xb, w1s, vws, w1_b, value_b, qb, vs, R_ROWS);

    attn_mma<<<dim3(8, H_NUM, B_SZ), 256, ASMEM>>>(qb, vs, w2t, b2, yh);

    gemm_proj<<<dim3(8, 64), 256, GSMEM>>>(yh, pws, proj_b, out, R_ROWS);
}

// round 11
// speedup vs baseline: 12.6302x; 1.0140x over previous
#include <cuda_runtime.h>
#include <cuda_fp16.h>
#include <cstdint>

#define B_SZ   8
#define T_SEQ  1023
#define C_DIM  1024
#define H_NUM  16
#define DK     64
#define R_ROWS (B_SZ * T_SEQ)   // 8184

// ---------------- scratch (__device__ globals: allocation-free contract) ----
__device__ __half g_xb [(size_t)R_ROWS * C_DIM];   // x fp16
__device__ __half g_qb [(size_t)R_ROWS * C_DIM];   // relu_out fp16 (Q)
__device__ __half g_vs [(size_t)R_ROWS * C_DIM];   // value fp16
__device__ __half g_yh [(size_t)R_ROWS * C_DIM];   // attn out fp16
__device__ __half g_w1s[(size_t)C_DIM * C_DIM];
__device__ __half g_vws[(size_t)C_DIM * C_DIM];
__device__ __half g_pws[(size_t)C_DIM * C_DIM];
__device__ __half g_w2t[(size_t)1024 * DK];        // w2 transposed fp16, padded
__device__ float  g_scs[(size_t)B_SZ * H_NUM * 8 * DK];  // per-(b,h,tile) V colsums

// ---------------- tensor-core helpers (base-target sm_80+ class) -----------
__device__ __forceinline__ uint32_t smem_to_u32(const void* p) {
    uint32_t a;
    asm("{ .reg .u64 t; cvta.to.shared.u64 t, %1; cvt.u32.u64 %0, t; }"
        : "=r"(a) : "l"(p));
    return a;
}
__device__ __forceinline__ void ldsm_x4(uint32_t& r0, uint32_t& r1,
                                        uint32_t& r2, uint32_t& r3, uint32_t addr) {
    asm volatile("ldmatrix.sync.aligned.m8n8.x4.shared.b16 {%0,%1,%2,%3}, [%4];"
                 : "=r"(r0), "=r"(r1), "=r"(r2), "=r"(r3) : "r"(addr));
}
__device__ __forceinline__ void ldsm_x4_t(uint32_t& r0, uint32_t& r1,
                                          uint32_t& r2, uint32_t& r3, uint32_t addr) {
    asm volatile("ldmatrix.sync.aligned.m8n8.x4.trans.shared.b16 {%0,%1,%2,%3}, [%4];"
                 : "=r"(r0), "=r"(r1), "=r"(r2), "=r"(r3) : "r"(addr));
}
__device__ __forceinline__ void mma_f16(float* c, const uint32_t* a, const uint32_t* b) {
    asm volatile(
        "mma.sync.aligned.m16n8k16.row.col.f32.f16.f16.f32 "
        "{%0,%1,%2,%3}, {%4,%5,%6,%7}, {%8,%9}, {%0,%1,%2,%3};"
        : "+f"(c[0]), "+f"(c[1]), "+f"(c[2]), "+f"(c[3])
        : "r"(a[0]), "r"(a[1]), "r"(a[2]), "r"(a[3]), "r"(b[0]), "r"(b[1]));
}
__device__ __forceinline__ uint32_t pack_f16(float lo, float hi) {
    uint32_t r;
    asm("cvt.rn.f16x2.f32 %0, %1, %2;" : "=r"(r) : "f"(hi), "f"(lo));
    return r;
}
__device__ __forceinline__ void cp16(uint32_t saddr, const void* gaddr) {
    asm volatile("cp.async.cg.shared.global [%0], [%1], 16;"
                 :: "r"(saddr), "l"(gaddr));
}
#define CP_COMMIT() asm volatile("cp.async.commit_group;")
template<int N>
__device__ __forceinline__ void cp_wait() {
    asm volatile("cp.async.wait_group %0;" :: "n"(N));
}

// ---------------------------------------------------------------------------
// conversions / prep
// ---------------------------------------------------------------------------
__global__ void cvt_h(const float* __restrict__ in, __half* __restrict__ out, int n)
{
    int i = (blockIdx.x * blockDim.x + threadIdx.x) * 4;
    if (i < n) {
        float4 v = *(const float4*)(in + i);
        __half2 a, b;
        a.x = __float2half_rn(v.x); a.y = __float2half_rn(v.y);
        b.x = __float2half_rn(v.z); b.y = __float2half_rn(v.w);
        *(__half2*)(out + i)     = a;
        *(__half2*)(out + i + 2) = b;
    }
}

// w2 [DK][T_SEQ] f32  ->  w2t [1024][DK] fp16 (row 1023 zero-padded)
__global__ void prep_w2t(const float* __restrict__ w2, __half* __restrict__ w2t)
{
    int idx = blockIdx.x * 256 + threadIdx.x;     // 1024*64
    int s = idx >> 6, d = idx & 63;
    float v = (s < T_SEQ) ? w2[d * T_SEQ + s] : 0.f;
    w2t[idx] = __float2half_rn(v);
}

// per-(b,h,tile) V column sums (with the SAME row clamping as attn's sV loads,
// so masked-column cancellation in centered-P stays exact).
__global__ void v_colsum(const __half* __restrict__ V, float* __restrict__ Scs)
{
    int t = blockIdx.x, h = blockIdx.y, b = blockIdx.z, d = threadIdx.x;
    float s = 0.f;
    #pragma unroll 8
    for (int i = 0; i < 128; i++) {
        int sidx = t * 128 + i; if (sidx > T_SEQ - 1) sidx = T_SEQ - 1;
        s += __half2float(V[((size_t)b * T_SEQ + sidx) * C_DIM + h * DK + d]);
    }
    Scs[(((size_t)b * H_NUM + h) * 8 + t) * DK + d] = s;
}

// ---------------------------------------------------------------------------
// Single-term fp16 HMMA GEMM core (CTA 128x128, 8 warps 2x4, warp 64x32).
// ---------------------------------------------------------------------------
#define BM  128
#define BN  128
#define BK  64
#define LDS 72
#define TILE_ELEMS (BM * LDS)
#define GSMEM (2 * TILE_ELEMS * 2)            // A + B tiles: 36864 bytes

__global__ __launch_bounds__(256, 2)
void gemm_qv(const __half* __restrict__ A0,
             const __half* __restrict__ W1, const __half* __restrict__ VW,
             const float* __restrict__ b1, const float* __restrict__ bv,
             __half* __restrict__ Oq, __half* __restrict__ Ov, int R)
{
    extern __shared__ __half sm[];
    __half* sA = sm;
    __half* sB = sm + TILE_ELEMS;

    const int  tid  = threadIdx.x;
    const int  wid  = tid >> 5;
    const int  lane = tid & 31;
    const int  wm   = wid >> 2;
    const int  wn   = wid & 3;
    const int  m0   = blockIdx.y * BM;
    const bool isQ  = (blockIdx.x < 8);
    const int  n0   = (isQ ? blockIdx.x : blockIdx.x - 8) * BN;
    const __half* B    = isQ ? W1 : VW;
    const float*  bias = isQ ? b1 : bv;
    __half* O = isQ ? Oq : Ov;

    const uint32_t sbA = smem_to_u32(sA);
    const uint32_t sbB = smem_to_u32(sB);

    float acc[4][4][4];
    #pragma unroll
    for (int f = 0; f < 4; f++)
        #pragma unroll
        for (int j = 0; j < 4; j++)
            #pragma unroll
            for (int e = 0; e < 4; e++) acc[f][j][e] = 0.f;

    const int a_r = wm * 64 + (lane & 15);
    const int b_r = wn * 32 + (lane & 15);
    const int l_c = (lane >> 4) << 3;

    for (int k0 = 0; k0 < C_DIM; k0 += BK) {
        #pragma unroll
        for (int i = 0; i < 4; i++) {
            int g   = tid + i * 256;
            int row = g >> 3;
            int c8  = (g & 7) * 8;
            int so  = row * LDS + c8;
            uint4 z = make_uint4(0u, 0u, 0u, 0u);
            bool av = (m0 + row) < R;
            *(uint4*)(sA + so) = av
                ? *(const uint4*)(A0 + (size_t)(m0 + row) * C_DIM + k0 + c8) : z;
            *(uint4*)(sB + so) =
                *(const uint4*)(B + (size_t)(n0 + row) * C_DIM + k0 + c8);
        }
        __syncthreads();

        #pragma unroll
        for (int kk = 0; kk < BK; kk += 16) {
            uint32_t af[4][4], bh[2][4];
            #pragma unroll
            for (int p = 0; p < 2; p++) {
                uint32_t off = (uint32_t)((b_r + p * 16) * LDS + kk + l_c) * 2;
                ldsm_x4(bh[p][0], bh[p][1], bh[p][2], bh[p][3], sbB + off);
            }
            #pragma unroll
            for (int f = 0; f < 4; f++) {
                uint32_t off = (uint32_t)((a_r + f * 16) * LDS + kk + l_c) * 2;
                ldsm_x4(af[f][0], af[f][1], af[f][2], af[f][3], sbA + off);
            }
            #pragma unroll
            for (int f = 0; f < 4; f++)
                #pragma unroll
                for (int j = 0; j < 4; j++) {
                    int p = j >> 1, hh = j & 1;
                    uint32_t bfr[2] = { bh[p][hh], bh[p][2 + hh] };
                    mma_f16(acc[f][j], af[f], bfr);
                }
        }
        __syncthreads();
    }

    const int qr = lane >> 2;
    const int qc = (lane & 3) * 2;
    #pragma unroll
    for (int f = 0; f < 4; f++) {
        #pragma unroll
        for (int j = 0; j < 4; j++) {
            int col = n0 + wn * 32 + j * 8 + qc;
            float b0 = bias[col], b1v = bias[col + 1];
            #pragma unroll
            for (int half = 0; half < 2; half++) {
                int row = m0 + wm * 64 + f * 16 + qr + half * 8;
                if (row < R) {
                    float v0 = acc[f][j][half * 2 + 0] + b0;
                    float v1 = acc[f][j][half * 2 + 1] + b1v;
                    if (isQ) { v0 = fmaxf(v0, 0.f); v1 = fmaxf(v1, 0.f); }
                    __half2 hp;
                    hp.x = __float2half_rn(v0); hp.y = __float2half_rn(v1);
                    *(__half2*)&O[(size_t)row * C_DIM + col] = hp;
                }
            }
        }
    }
}

__global__ __launch_bounds__(256, 2)
void gemm_proj(const __half* __restrict__ A0, const __half* __restrict__ B,
               const float* __restrict__ bias, float* __restrict__ O, int R)
{
    extern __shared__ __half sm[];
    __half* sA = sm;
    __half* sB = sm + TILE_ELEMS;

    const int tid  = threadIdx.x;
    const int wid  = tid >> 5;
    const int lane = tid & 31;
    const int wm   = wid >> 2;
    const int wn   = wid & 3;
    const int m0   = blockIdx.y * BM;
    const int n0   = blockIdx.x * BN;

    const uint32_t sbA = smem_to_u32(sA);
    const uint32_t sbB = smem_to_u32(sB);

    float acc[4][4][4];
    #pragma unroll
    for (int f = 0; f < 4; f++)
        #pragma unroll
        for (int j = 0; j < 4; j++)
            #pragma unroll
            for (int e = 0; e < 4; e++) acc[f][j][e] = 0.f;

    const int a_r = wm * 64 + (lane & 15);
    const int b_r = wn * 32 + (lane & 15);
    const int l_c = (lane >> 4) << 3;

    for (int k0 = 0; k0 < C_DIM; k0 += BK) {
        #pragma unroll
        for (int i = 0; i < 4; i++) {
            int g   = tid + i * 256;
            int row = g >> 3;
            int c8  = (g & 7) * 8;
            int so  = row * LDS + c8;
            uint4 z = make_uint4(0u, 0u, 0u, 0u);
            bool av = (m0 + row) < R;
            *(uint4*)(sA + so) = av
                ? *(const uint4*)(A0 + (size_t)(m0 + row) * C_DIM + k0 + c8) : z;
            *(uint4*)(sB + so) =
                *(const uint4*)(B + (size_t)(n0 + row) * C_DIM + k0 + c8);
        }
        __syncthreads();

        #pragma unroll
        for (int kk = 0; kk < BK; kk += 16) {
            uint32_t af[4][4], bh[2][4];
            #pragma unroll
            for (int p = 0; p < 2; p++) {
                uint32_t off = (uint32_t)((b_r + p * 16) * LDS + kk + l_c) * 2;
                ldsm_x4(bh[p][0], bh[p][1], bh[p][2], bh[p][3], sbB + off);
            }
            #pragma unroll
            for (int f = 0; f < 4; f++) {
                uint32_t off = (uint32_t)((a_r + f * 16) * LDS + kk + l_c) * 2;
                ldsm_x4(af[f][0], af[f][1], af[f][2], af[f][3], sbA + off);
            }
            #pragma unroll
            for (int f = 0; f < 4; f++)
                #pragma unroll
                for (int j = 0; j < 4; j++) {
                    int p = j >> 1, hh = j & 1;
                    uint32_t bfr[2] = { bh[p][hh], bh[p][2 + hh] };
                    mma_f16(acc[f][j], af[f], bfr);
                }
        }
        __syncthreads();
    }

    const int qr = lane >> 2;
    const int qc = (lane & 3) * 2;
    #pragma unroll
    for (int f = 0; f < 4; f++) {
        #pragma unroll
        for (int j = 0; j < 4; j++) {
            int col = n0 + wn * 32 + j * 8 + qc;
            float b0 = bias[col], b1 = bias[col + 1];
            #pragma unroll
            for (int half = 0; half < 2; half++) {
                int row = m0 + wm * 64 + f * 16 + qr + half * 8;
                if (row < R) {
                    float v0 = acc[f][j][half * 2 + 0] + b0;
                    float v1 = acc[f][j][half * 2 + 1] + b1;
                    *(float2*)&O[(size_t)row * C_DIM + col] = make_float2(v0, v1);
                }
            }
        }
    }
}

// ---------------------------------------------------------------------------
// HMMA fp16 flash attention, centered-P + cp.async double-buffered K/V.
//   P = 1 + P'; y = colacc(V) + P' @ V; l = 128*(qt+1) + sum(P')
//   colacc preloaded from g_scs; b2 preloaded whole; tile loads pipelined.
// smem: Q + 2x(K,V) + b2all + colacc = 96.5 KB, occupancy 2.
// ---------------------------------------------------------------------------
#define ATE   (128 * LDS)
#define ASMEM (5 * ATE * 2 + 1024 * 4 + 64 * 4)

__global__ __launch_bounds__(256, 2)
void attn_mma(const __half* __restrict__ Q, const __half* __restrict__ V,
              const __half* __restrict__ w2t, const float* __restrict__ b2,
              const float* __restrict__ Scs, __half* __restrict__ Yh)
{
    extern __shared__ __half asmem[];
    __half* sQ  = asmem;                       // ATE
    __half* sKV = asmem + ATE;                 // 2 bufs x (K tile, V tile)
    float* sb2a   = (float*)(asmem + 5 * ATE); // 1024 f32
    float* colacc = sb2a + 1024;               // 64 f32

    const uint32_t sbQ  = smem_to_u32(sQ);
    const uint32_t sbKV = smem_to_u32(sKV);

    const int b    = blockIdx.z;
    const int h    = blockIdx.y;
    const int qt   = (int)(gridDim.x - 1) - (int)blockIdx.x;   // heavy first
    const int m0   = qt * 128;
    const int tid  = threadIdx.x;
    const int wid  = tid >> 5;
    const int lane = tid & 31;
    const int mw   = wid * 16;

    const int lrow = tid >> 3;              // 0..31 (row group for loads)
    const int lc8  = (tid & 7) * 8;         // 16B column within row

    // issue one tile's K+V loads via cp.async (4 rows-strides x (K,V))
    auto issue_tile = [&](int nt, int buf) {
        const int s0 = nt * 128;
        const uint32_t dK = sbKV + (uint32_t)(buf * 2 * ATE) * 2;
        const uint32_t dV = dK + (uint32_t)ATE * 2;
        #pragma unroll
        for (int i = 0; i < 4; i++) {
            int row = lrow + i * 32;
            uint32_t so = (uint32_t)(row * LDS + lc8) * 2;
            cp16(dK + so, w2t + (size_t)(s0 + row) * DK + lc8);
            int s = s0 + row; if (s > T_SEQ - 1) s = T_SEQ - 1;
            cp16(dV + so, V + ((size_t)b * T_SEQ + s) * C_DIM + h * DK + lc8);
        }
    };

    // ---- prologue: tile 0 in flight; Q, b2, colacc loads ----
    issue_tile(0, 0);
    CP_COMMIT();

    for (int idx = tid; idx < 1024; idx += 256) {
        int row = idx >> 3, c8 = (idx & 7) * 8;
        int t = m0 + row; if (t > T_SEQ - 1) t = T_SEQ - 1;
        *(uint4*)(sQ + row * LDS + c8) =
            *(const uint4*)(Q + ((size_t)b * T_SEQ + t) * C_DIM + h * DK + c8);
    }
    for (int idx = tid; idx < 1024; idx += 256)
        sb2a[idx] = (idx < T_SEQ) ? b2[idx] : 0.f;
    if (tid < 64) {
        const float* sp = Scs + (((size_t)b * H_NUM + h) * 8) * DK + tid;
        float c = 0.f;
        for (int t = 0; t <= qt; t++) c += sp[t * DK];
        colacc[tid] = c;
    }
    __syncthreads();

    // Q fragments (persist across KV tiles)
    uint32_t qf[4][4];
    {
        int r  = mw + (lane & 15);
        int cg = (lane >> 4) << 3;
        #pragma unroll
        for (int k = 0; k < 4; k++)
            ldsm_x4(qf[k][0], qf[k][1], qf[k][2], qf[k][3],
                    sbQ + (uint32_t)(r * LDS + k * 16 + cg) * 2);
    }

    float yacc[8][4];
    #pragma unroll
    for (int j = 0; j < 8; j++)
        #pragma unroll
        for (int e = 0; e < 4; e++) yacc[j][e] = 0.f;
    float ls0 = 0.f, ls1 = 0.f;

    const int r0    = lane >> 2;
    const int c0l   = (lane & 3) * 2;
    const int trow0 = m0 + mw + r0;
    const int lgo   = (lane >> 4) << 3;
    const int lr16  = lane & 15;

    for (int nt = 0; nt <= qt; nt++) {
        const int p  = nt & 1;
        const int s0 = nt * 128;
        if (nt < qt) {
            issue_tile(nt + 1, 1 - p);
            CP_COMMIT();
            cp_wait<1>();          // tile nt complete; tile nt+1 in flight
        } else {
            cp_wait<0>();
        }
        __syncthreads();

        const uint32_t sbK = sbKV + (uint32_t)(p * 2 * ATE) * 2;
        const uint32_t sbV = sbK + (uint32_t)ATE * 2;
        const bool diag = (nt == qt);

        #pragma unroll
        for (int j = 0; j < 8; j++) {
            float Sp[2][4];
            #pragma unroll
            for (int fh = 0; fh < 2; fh++)
                #pragma unroll
                for (int e = 0; e < 4; e++) Sp[fh][e] = 0.f;

            int nr = j * 16 + lr16;
            #pragma unroll
            for (int k = 0; k < 4; k++) {
                uint32_t bb[4];
                ldsm_x4(bb[0], bb[1], bb[2], bb[3],
                        sbK + (uint32_t)(nr * LDS + k * 16 + lgo) * 2);
                uint32_t blo[2] = { bb[0], bb[2] };
                uint32_t bhi[2] = { bb[1], bb[3] };
                mma_f16(Sp[0], qf[k], blo);
                mma_f16(Sp[1], qf[k], bhi);
            }

            // centered p' = exp(s)-1 (unmasked) / exactly -1 (masked)
            float pv_[2][4];
            #pragma unroll
            for (int fh = 0; fh < 2; fh++) {
                int f = 2 * j + fh;
                #pragma unroll
                for (int e = 0; e < 4; e++) {
                    int col = 8 * f + c0l + (e & 1);
                    int rr  = trow0 + ((e >> 1) << 3);
                    float sv = Sp[fh][e] + sb2a[s0 + col];
                    bool ok = !diag || (s0 + col <= rr);
                    float pv = ok ? (__expf(sv) - 1.0f) : -1.0f;
                    pv_[fh][e] = pv;
                    if (e < 2) ls0 += pv; else ls1 += pv;
                }
            }

            uint32_t Ah_[4];
            #pragma unroll
            for (int fh = 0; fh < 2; fh++) {
                Ah_[2 * fh + 0] = pack_f16(pv_[fh][0], pv_[fh][1]);
                Ah_[2 * fh + 1] = pack_f16(pv_[fh][2], pv_[fh][3]);
            }

            int srow = j * 16 + lr16;
            #pragma unroll
            for (int dg = 0; dg < 4; dg++) {
                uint32_t v4[4];
                ldsm_x4_t(v4[0], v4[1], v4[2], v4[3],
                          sbV + (uint32_t)(srow * LDS + dg * 16 + lgo) * 2);
                uint32_t b0[2] = { v4[0], v4[1] };
                uint32_t b1[2] = { v4[2], v4[3] };
                mma_f16(yacc[2 * dg],     Ah_, b0);
                mma_f16(yacc[2 * dg + 1], Ah_, b1);
            }
        }
        __syncthreads();   // all warps done with buf p before it is overwritten
    }

    ls0 += __shfl_xor_sync(0xffffffffu, ls0, 1);
    ls0 += __shfl_xor_sync(0xffffffffu, ls0, 2);
    ls1 += __shfl_xor_sync(0xffffffffu, ls1, 1);
    ls1 += __shfl_xor_sync(0xffffffffu, ls1, 2);
    const float lbase = 128.f * (float)(qt + 1);
    float inv0 = 1.f / (lbase + ls0);
    float inv1 = 1.f / (lbase + ls1);

    #pragma unroll
    for (int half = 0; half < 2; half++) {
        int t = trow0 + half * 8;
        if (t < T_SEQ) {
            float inv = half ? inv1 : inv0;
            size_t base = ((size_t)b * T_SEQ + t) * C_DIM + h * DK;
            #pragma unroll
            for (int j = 0; j < 8; j++) {
                int col = j * 8 + c0l;
                float v0 = (yacc[j][2 * half + 0] + colacc[col])     * inv;
                float v1 = (yacc[j][2 * half + 1] + colacc[col + 1]) * inv;
                __half2 hp;
                hp.x = __float2half_rn(v0); hp.y = __float2half_rn(v1);
                *(__half2*)&Yh[base + col] = hp;
            }
        }
    }
}

// ---------------------------------------------------------------------------
extern "C" void kernel_launch(void* const* d_in, const int* in_sizes, int n_in,
                              void* d_out, int out_size)
{
    const float* x       = (const float*)d_in[0];
    const float* w1_w    = (const float*)d_in[1];
    const float* w1_b    = (const float*)d_in[2];
    const float* w2      = (const float*)d_in[3];
    const float* b2      = (const float*)d_in[4];
    const float* value_w = (const float*)d_in[5];
    const float* value_b = (const float*)d_in[6];
    const float* proj_w  = (const float*)d_in[7];
    const float* proj_b  = (const float*)d_in[8];
    float* out = (float*)d_out;

    __half *xb, *qb, *vs, *yh, *w1s, *vws, *pws, *w2t;
    float* scs;
    cudaGetSymbolAddress((void**)&xb,  g_xb);
    cudaGetSymbolAddress((void**)&qb,  g_qb);  cudaGetSymbolAddress((void**)&vs,  g_vs);
    cudaGetSymbolAddress((void**)&yh,  g_yh);
    cudaGetSymbolAddress((void**)&w1s, g_w1s); cudaGetSymbolAddress((void**)&vws, g_vws);
    cudaGetSymbolAddress((void**)&pws, g_pws); cudaGetSymbolAddress((void**)&w2t, g_w2t);
    cudaGetSymbolAddress((void**)&scs, g_scs);

    cudaFuncSetAttribute(gemm_qv,   cudaFuncAttributeMaxDynamicSharedMemorySize, GSMEM);
    cudaFuncSetAttribute(gemm_proj, cudaFuncAttributeMaxDynamicSharedMemorySize, GSMEM);
    cudaFuncSetAttribute(attn_mma,  cudaFuncAttributeMaxDynamicSharedMemorySize, ASMEM);

    const int NX = R_ROWS * C_DIM;
    const int NW = C_DIM * C_DIM;
    cvt_h<<<NX / 4 / 256, 256>>>(x, xb, NX);
    cvt_h<<<NW / 4 / 256, 256>>>(w1_w,    w1s, NW);
    cvt_h<<<NW / 4 / 256, 256>>>(value_w, vws, NW);
    cvt_h<<<NW / 4 / 256, 256>>>(proj_w,  pws, NW);
    prep_w2t<<<(1024 * DK) / 256, 256>>>(w2, w2t);

    gemm_qv<<<dim3(16, 64), 256, GSMEM>>>(xb, w1s, vws, w1_b, value_b, qb, vs, R_ROWS);

    v_colsum<<<dim3(8, H_NUM, B_SZ), 64>>>(vs, scs);

    attn_mma<<<dim3(8, H_NUM, B_SZ), 256, ASMEM>>>(qb, vs, w2t, b2, scs, yh);

    gemm_proj<<<dim3(8, 64), 256, GSMEM>>>(yh, pws, proj_b, out, R_ROWS);
}

// round 12
// speedup vs baseline: 13.2792x; 1.0514x over previous
#include <cuda_runtime.h>
#include <cuda_fp16.h>
#include <cstdint>

#define B_SZ   8
#define T_SEQ  1023
#define C_DIM  1024
#define H_NUM  16
#define DK     64
#define R_ROWS (B_SZ * T_SEQ)   // 8184
#define LOG2E  1.4426950408889634f

// ---------------- scratch (__device__ globals: allocation-free contract) ----
__device__ __half g_xb [(size_t)R_ROWS * C_DIM];   // x fp16
__device__ __half g_qb [(size_t)R_ROWS * C_DIM];   // relu_out fp16 (Q)
__device__ __half g_vs [(size_t)R_ROWS * C_DIM];   // value fp16
__device__ __half g_yh [(size_t)R_ROWS * C_DIM];   // attn out fp16
__device__ __half g_w1s[(size_t)C_DIM * C_DIM];
__device__ __half g_vws[(size_t)C_DIM * C_DIM];
__device__ __half g_pws[(size_t)C_DIM * C_DIM];
__device__ __half g_w2t[(size_t)1024 * DK];        // w2^T * log2e, fp16, padded
__device__ float  g_scs[(size_t)B_SZ * H_NUM * 8 * DK];  // per-(b,h,tile) V colsums

// ---------------- tensor-core helpers (base-target sm_80+ class) -----------
__device__ __forceinline__ uint32_t smem_to_u32(const void* p) {
    uint32_t a;
    asm("{ .reg .u64 t; cvta.to.shared.u64 t, %1; cvt.u32.u64 %0, t; }"
        : "=r"(a) : "l"(p));
    return a;
}
__device__ __forceinline__ void ldsm_x4(uint32_t& r0, uint32_t& r1,
                                        uint32_t& r2, uint32_t& r3, uint32_t addr) {
    asm volatile("ldmatrix.sync.aligned.m8n8.x4.shared.b16 {%0,%1,%2,%3}, [%4];"
                 : "=r"(r0), "=r"(r1), "=r"(r2), "=r"(r3) : "r"(addr));
}
__device__ __forceinline__ void ldsm_x4_t(uint32_t& r0, uint32_t& r1,
                                          uint32_t& r2, uint32_t& r3, uint32_t addr) {
    asm volatile("ldmatrix.sync.aligned.m8n8.x4.trans.shared.b16 {%0,%1,%2,%3}, [%4];"
                 : "=r"(r0), "=r"(r1), "=r"(r2), "=r"(r3) : "r"(addr));
}
__device__ __forceinline__ void mma_f16(float* c, const uint32_t* a, const uint32_t* b) {
    asm volatile(
        "mma.sync.aligned.m16n8k16.row.col.f32.f16.f16.f32 "
        "{%0,%1,%2,%3}, {%4,%5,%6,%7}, {%8,%9}, {%0,%1,%2,%3};"
        : "+f"(c[0]), "+f"(c[1]), "+f"(c[2]), "+f"(c[3])
        : "r"(a[0]), "r"(a[1]), "r"(a[2]), "r"(a[3]), "r"(b[0]), "r"(b[1]));
}
__device__ __forceinline__ uint32_t pack_f16(float lo, float hi) {
    uint32_t r;
    asm("cvt.rn.f16x2.f32 %0, %1, %2;" : "=r"(r) : "f"(hi), "f"(lo));
    return r;
}
__device__ __forceinline__ float ex2f(float x) {
    float r;
    asm("ex2.approx.f32 %0, %1;" : "=f"(r) : "f"(x));
    return r;
}
__device__ __forceinline__ void cp16(uint32_t saddr, const void* gaddr) {
    asm volatile("cp.async.cg.shared.global [%0], [%1], 16;"
                 :: "r"(saddr), "l"(gaddr));
}
#define CP_COMMIT() asm volatile("cp.async.commit_group;")
template<int N>
__device__ __forceinline__ void cp_wait() {
    asm volatile("cp.async.wait_group %0;" :: "n"(N));
}

// ---------------------------------------------------------------------------
// conversions / prep
// ---------------------------------------------------------------------------
__global__ void cvt_h(const float* __restrict__ in, __half* __restrict__ out, int n)
{
    int i = (blockIdx.x * blockDim.x + threadIdx.x) * 4;
    if (i < n) {
        float4 v = *(const float4*)(in + i);
        __half2 a, b;
        a.x = __float2half_rn(v.x); a.y = __float2half_rn(v.y);
        b.x = __float2half_rn(v.z); b.y = __float2half_rn(v.w);
        *(__half2*)(out + i)     = a;
        *(__half2*)(out + i + 2) = b;
    }
}

// w2 [DK][T_SEQ] f32 -> w2t [1024][DK] fp16, PRESCALED by log2e.
__global__ void prep_w2t(const float* __restrict__ w2, __half* __restrict__ w2t)
{
    int idx = blockIdx.x * 256 + threadIdx.x;     // 1024*64
    int s = idx >> 6, d = idx & 63;
    float v = (s < T_SEQ) ? w2[d * T_SEQ + s] * LOG2E : 0.f;
    w2t[idx] = __float2half_rn(v);
}

// per-(b,h,tile) V column sums (same row clamping as attn's sV loads).
__global__ void v_colsum(const __half* __restrict__ V, float* __restrict__ Scs)
{
    int t = blockIdx.x, h = blockIdx.y, b = blockIdx.z, d = threadIdx.x;
    float s = 0.f;
    #pragma unroll 8
    for (int i = 0; i < 128; i++) {
        int sidx = t * 128 + i; if (sidx > T_SEQ - 1) sidx = T_SEQ - 1;
        s += __half2float(V[((size_t)b * T_SEQ + sidx) * C_DIM + h * DK + d]);
    }
    Scs[(((size_t)b * H_NUM + h) * 8 + t) * DK + d] = s;
}

// ---------------------------------------------------------------------------
// Single-term fp16 HMMA GEMM core (CTA 128x128, 8 warps 2x4, warp 64x32).
// ---------------------------------------------------------------------------
#define BM  128
#define BN  128
#define BK  64
#define LDS 72
#define TILE_ELEMS (BM * LDS)
#define GSMEM (2 * TILE_ELEMS * 2)            // A + B tiles: 36864 bytes

__global__ __launch_bounds__(256, 2)
void gemm_qv(const __half* __restrict__ A0,
             const __half* __restrict__ W1, const __half* __restrict__ VW,
             const float* __restrict__ b1, const float* __restrict__ bv,
             __half* __restrict__ Oq, __half* __restrict__ Ov, int R)
{
    extern __shared__ __half sm[];
    __half* sA = sm;
    __half* sB = sm + TILE_ELEMS;

    const int  tid  = threadIdx.x;
    const int  wid  = tid >> 5;
    const int  lane = tid & 31;
    const int  wm   = wid >> 2;
    const int  wn   = wid & 3;
    const int  m0   = blockIdx.y * BM;
    const bool isQ  = (blockIdx.x < 8);
    const int  n0   = (isQ ? blockIdx.x : blockIdx.x - 8) * BN;
    const __half* B    = isQ ? W1 : VW;
    const float*  bias = isQ ? b1 : bv;
    __half* O = isQ ? Oq : Ov;

    const uint32_t sbA = smem_to_u32(sA);
    const uint32_t sbB = smem_to_u32(sB);

    float acc[4][4][4];
    #pragma unroll
    for (int f = 0; f < 4; f++)
        #pragma unroll
        for (int j = 0; j < 4; j++)
            #pragma unroll
            for (int e = 0; e < 4; e++) acc[f][j][e] = 0.f;

    const int a_r = wm * 64 + (lane & 15);
    const int b_r = wn * 32 + (lane & 15);
    const int l_c = (lane >> 4) << 3;

    for (int k0 = 0; k0 < C_DIM; k0 += BK) {
        #pragma unroll
        for (int i = 0; i < 4; i++) {
            int g   = tid + i * 256;
            int row = g >> 3;
            int c8  = (g & 7) * 8;
            int so  = row * LDS + c8;
            uint4 z = make_uint4(0u, 0u, 0u, 0u);
            bool av = (m0 + row) < R;
            *(uint4*)(sA + so) = av
                ? *(const uint4*)(A0 + (size_t)(m0 + row) * C_DIM + k0 + c8) : z;
            *(uint4*)(sB + so) =
                *(const uint4*)(B + (size_t)(n0 + row) * C_DIM + k0 + c8);
        }
        __syncthreads();

        #pragma unroll
        for (int kk = 0; kk < BK; kk += 16) {
            uint32_t af[4][4], bh[2][4];
            #pragma unroll
            for (int p = 0; p < 2; p++) {
                uint32_t off = (uint32_t)((b_r + p * 16) * LDS + kk + l_c) * 2;
                ldsm_x4(bh[p][0], bh[p][1], bh[p][2], bh[p][3], sbB + off);
            }
            #pragma unroll
            for (int f = 0; f < 4; f++) {
                uint32_t off = (uint32_t)((a_r + f * 16) * LDS + kk + l_c) * 2;
                ldsm_x4(af[f][0], af[f][1], af[f][2], af[f][3], sbA + off);
            }
            #pragma unroll
            for (int f = 0; f < 4; f++)
                #pragma unroll
                for (int j = 0; j < 4; j++) {
                    int p = j >> 1, hh = j & 1;
                    uint32_t bfr[2] = { bh[p][hh], bh[p][2 + hh] };
                    mma_f16(acc[f][j], af[f], bfr);
                }
        }
        __syncthreads();
    }

    const int qr = lane >> 2;
    const int qc = (lane & 3) * 2;
    #pragma unroll
    for (int f = 0; f < 4; f++) {
        #pragma unroll
        for (int j = 0; j < 4; j++) {
            int col = n0 + wn * 32 + j * 8 + qc;
            float b0 = bias[col], b1v = bias[col + 1];
            #pragma unroll
            for (int half = 0; half < 2; half++) {
                int row = m0 + wm * 64 + f * 16 + qr + half * 8;
                if (row < R) {
                    float v0 = acc[f][j][half * 2 + 0] + b0;
                    float v1 = acc[f][j][half * 2 + 1] + b1v;
                    if (isQ) { v0 = fmaxf(v0, 0.f); v1 = fmaxf(v1, 0.f); }
                    __half2 hp;
                    hp.x = __float2half_rn(v0); hp.y = __float2half_rn(v1);
                    *(__half2*)&O[(size_t)row * C_DIM + col] = hp;
                }
            }
        }
    }
}

__global__ __launch_bounds__(256, 2)
void gemm_proj(const __half* __restrict__ A0, const __half* __restrict__ B,
               const float* __restrict__ bias, float* __restrict__ O, int R)
{
    extern __shared__ __half sm[];
    __half* sA = sm;
    __half* sB = sm + TILE_ELEMS;

    const int tid  = threadIdx.x;
    const int wid  = tid >> 5;
    const int lane = tid & 31;
    const int wm   = wid >> 2;
    const int wn   = wid & 3;
    const int m0   = blockIdx.y * BM;
    const int n0   = blockIdx.x * BN;

    const uint32_t sbA = smem_to_u32(sA);
    const uint32_t sbB = smem_to_u32(sB);

    float acc[4][4][4];
    #pragma unroll
    for (int f = 0; f < 4; f++)
        #pragma unroll
        for (int j = 0; j < 4; j++)
            #pragma unroll
            for (int e = 0; e < 4; e++) acc[f][j][e] = 0.f;

    const int a_r = wm * 64 + (lane & 15);
    const int b_r = wn * 32 + (lane & 15);
    const int l_c = (lane >> 4) << 3;

    for (int k0 = 0; k0 < C_DIM; k0 += BK) {
        #pragma unroll
        for (int i = 0; i < 4; i++) {
            int g   = tid + i * 256;
            int row = g >> 3;
            int c8  = (g & 7) * 8;
            int so  = row * LDS + c8;
            uint4 z = make_uint4(0u, 0u, 0u, 0u);
            bool av = (m0 + row) < R;
            *(uint4*)(sA + so) = av
                ? *(const uint4*)(A0 + (size_t)(m0 + row) * C_DIM + k0 + c8) : z;
            *(uint4*)(sB + so) =
                *(const uint4*)(B + (size_t)(n0 + row) * C_DIM + k0 + c8);
        }
        __syncthreads();

        #pragma unroll
        for (int kk = 0; kk < BK; kk += 16) {
            uint32_t af[4][4], bh[2][4];
            #pragma unroll
            for (int p = 0; p < 2; p++) {
                uint32_t off = (uint32_t)((b_r + p * 16) * LDS + kk + l_c) * 2;
                ldsm_x4(bh[p][0], bh[p][1], bh[p][2], bh[p][3], sbB + off);
            }
            #pragma unroll
            for (int f = 0; f < 4; f++) {
                uint32_t off = (uint32_t)((a_r + f * 16) * LDS + kk + l_c) * 2;
                ldsm_x4(af[f][0], af[f][1], af[f][2], af[f][3], sbA + off);
            }
            #pragma unroll
            for (int f = 0; f < 4; f++)
                #pragma unroll
                for (int j = 0; j < 4; j++) {
                    int p = j >> 1, hh = j & 1;
                    uint32_t bfr[2] = { bh[p][hh], bh[p][2 + hh] };
                    mma_f16(acc[f][j], af[f], bfr);
                }
        }
        __syncthreads();
    }

    const int qr = lane >> 2;
    const int qc = (lane & 3) * 2;
    #pragma unroll
    for (int f = 0; f < 4; f++) {
        #pragma unroll
        for (int j = 0; j < 4; j++) {
            int col = n0 + wn * 32 + j * 8 + qc;
            float b0 = bias[col], b1 = bias[col + 1];
            #pragma unroll
            for (int half = 0; half < 2; half++) {
                int row = m0 + wm * 64 + f * 16 + qr + half * 8;
                if (row < R) {
                    float v0 = acc[f][j][half * 2 + 0] + b0;
                    float v1 = acc[f][j][half * 2 + 1] + b1;
                    *(float2*)&O[(size_t)row * C_DIM + col] = make_float2(v0, v1);
                }
            }
        }
    }
}

// ---------------------------------------------------------------------------
// HMMA fp16 flash attention, centered-P, prescaled-log2e scores,
// diag/non-diag split tile bodies, cp.async double-buffered K/V.
// ---------------------------------------------------------------------------
#define ATE   (128 * LDS)
#define ASMEM (5 * ATE * 2 + 1024 * 4 + 64 * 4)

template<bool DIAG>
__device__ __forceinline__ void attn_tile(
    uint32_t sbK, uint32_t sbV, int s0, const float* __restrict__ sb2a,
    const uint32_t (&qf)[4][4], float (&yacc)[8][4], float& ls0, float& ls1,
    int trow0, int c0l, int lgo, int lr16)
{
    #pragma unroll
    for (int j = 0; j < 8; j++) {
        // ---- S for s-cols 16j..16j+15 (already scaled by log2e) ----
        float Sp[2][4];
        #pragma unroll
        for (int fh = 0; fh < 2; fh++)
            #pragma unroll
            for (int e = 0; e < 4; e++) Sp[fh][e] = 0.f;

        int nr = j * 16 + lr16;
        #pragma unroll
        for (int k = 0; k < 4; k++) {
            uint32_t bb[4];
            ldsm_x4(bb[0], bb[1], bb[2], bb[3],
                    sbK + (uint32_t)(nr * LDS + k * 16 + lgo) * 2);
            uint32_t blo[2] = { bb[0], bb[2] };
            uint32_t bhi[2] = { bb[1], bb[3] };
            mma_f16(Sp[0], qf[k], blo);
            mma_f16(Sp[1], qf[k], bhi);
        }

        // ---- centered p' = ex2(S + b2s) - 1 ----
        float pv_[2][4];
        #pragma unroll
        for (int fh = 0; fh < 2; fh++) {
            int f = 2 * j + fh;
            float2 bb2 = *(const float2*)&sb2a[s0 + 8 * f + c0l];
            if (!DIAG) {
                pv_[fh][0] = ex2f(Sp[fh][0] + bb2.x) - 1.f;
                pv_[fh][1] = ex2f(Sp[fh][1] + bb2.y) - 1.f;
                pv_[fh][2] = ex2f(Sp[fh][2] + bb2.x) - 1.f;
                pv_[fh][3] = ex2f(Sp[fh][3] + bb2.y) - 1.f;
            } else {
                #pragma unroll
                for (int e = 0; e < 4; e++) {
                    int col = 8 * f + c0l + (e & 1);
                    int rr  = trow0 + ((e >> 1) << 3);
                    float sv = Sp[fh][e] + ((e & 1) ? bb2.y : bb2.x);
                    bool ok  = (s0 + col <= rr);
                    pv_[fh][e] = ok ? (ex2f(sv) - 1.f) : -1.f;
                }
            }
            ls0 += pv_[fh][0] + pv_[fh][1];
            ls1 += pv_[fh][2] + pv_[fh][3];
        }

        uint32_t Ah_[4];
        #pragma unroll
        for (int fh = 0; fh < 2; fh++) {
            Ah_[2 * fh + 0] = pack_f16(pv_[fh][0], pv_[fh][1]);
            Ah_[2 * fh + 1] = pack_f16(pv_[fh][2], pv_[fh][3]);
        }

        int srow = j * 16 + lr16;
        #pragma unroll
        for (int dg = 0; dg < 4; dg++) {
            uint32_t v4[4];
            ldsm_x4_t(v4[0], v4[1], v4[2], v4[3],
                      sbV + (uint32_t)(srow * LDS + dg * 16 + lgo) * 2);
            uint32_t b0[2] = { v4[0], v4[1] };
            uint32_t b1[2] = { v4[2], v4[3] };
            mma_f16(yacc[2 * dg],     Ah_, b0);
            mma_f16(yacc[2 * dg + 1], Ah_, b1);
        }
    }
}

__global__ __launch_bounds__(256, 2)
void attn_mma(const __half* __restrict__ Q, const __half* __restrict__ V,
              const __half* __restrict__ w2t, const float* __restrict__ b2,
              const float* __restrict__ Scs, __half* __restrict__ Yh)
{
    extern __shared__ __half asmem[];
    __half* sQ  = asmem;                       // ATE
    __half* sKV = asmem + ATE;                 // 2 bufs x (K tile, V tile)
    float* sb2a   = (float*)(asmem + 5 * ATE); // 1024 f32 (prescaled by log2e)
    float* colacc = sb2a + 1024;               // 64 f32

    const uint32_t sbQ  = smem_to_u32(sQ);
    const uint32_t sbKV = smem_to_u32(sKV);

    const int b    = blockIdx.z;
    const int h    = blockIdx.y;
    const int qt   = (int)(gridDim.x - 1) - (int)blockIdx.x;   // heavy first
    const int m0   = qt * 128;
    const int tid  = threadIdx.x;
    const int wid  = tid >> 5;
    const int lane = tid & 31;
    const int mw   = wid * 16;

    const int lrow = tid >> 3;
    const int lc8  = (tid & 7) * 8;

    auto issue_tile = [&](int nt, int buf) {
        const int s0 = nt * 128;
        const uint32_t dK = sbKV + (uint32_t)(buf * 2 * ATE) * 2;
        const uint32_t dV = dK + (uint32_t)ATE * 2;
        #pragma unroll
        for (int i = 0; i < 4; i++) {
            int row = lrow + i * 32;
            uint32_t so = (uint32_t)(row * LDS + lc8) * 2;
            cp16(dK + so, w2t + (size_t)(s0 + row) * DK + lc8);
            int s = s0 + row; if (s > T_SEQ - 1) s = T_SEQ - 1;
            cp16(dV + so, V + ((size_t)b * T_SEQ + s) * C_DIM + h * DK + lc8);
        }
    };

    // ---- prologue ----
    issue_tile(0, 0);
    CP_COMMIT();

    for (int idx = tid; idx < 1024; idx += 256) {
        int row = idx >> 3, c8 = (idx & 7) * 8;
        int t = m0 + row; if (t > T_SEQ - 1) t = T_SEQ - 1;
        *(uint4*)(sQ + row * LDS + c8) =
            *(const uint4*)(Q + ((size_t)b * T_SEQ + t) * C_DIM + h * DK + c8);
    }
    for (int idx = tid; idx < 1024; idx += 256)
        sb2a[idx] = (idx < T_SEQ) ? b2[idx] * LOG2E : 0.f;
    if (tid < 64) {
        const float* sp = Scs + (((size_t)b * H_NUM + h) * 8) * DK + tid;
        float c = 0.f;
        for (int t = 0; t <= qt; t++) c += sp[t * DK];
        colacc[tid] = c;
    }
    __syncthreads();

    uint32_t qf[4][4];
    {
        int r  = mw + (lane & 15);
        int cg = (lane >> 4) << 3;
        #pragma unroll
        for (int k = 0; k < 4; k++)
            ldsm_x4(qf[k][0], qf[k][1], qf[k][2], qf[k][3],
                    sbQ + (uint32_t)(r * LDS + k * 16 + cg) * 2);
    }

    float yacc[8][4];
    #pragma unroll
    for (int j = 0; j < 8; j++)
        #pragma unroll
        for (int e = 0; e < 4; e++) yacc[j][e] = 0.f;
    float ls0 = 0.f, ls1 = 0.f;

    const int r0    = lane >> 2;
    const int c0l   = (lane & 3) * 2;
    const int trow0 = m0 + mw + r0;
    const int lgo   = (lane >> 4) << 3;
    const int lr16  = lane & 15;

    // ---- non-diagonal tiles (no mask) ----
    for (int nt = 0; nt < qt; nt++) {
        const int p = nt & 1;
        issue_tile(nt + 1, 1 - p);
        CP_COMMIT();
        cp_wait<1>();
        __syncthreads();
        const uint32_t sbK = sbKV + (uint32_t)(p * 2 * ATE) * 2;
        const uint32_t sbV = sbK + (uint32_t)ATE * 2;
        attn_tile<false>(sbK, sbV, nt * 128, sb2a, qf, yacc, ls0, ls1,
                         trow0, c0l, lgo, lr16);
        __syncthreads();
    }
    // ---- diagonal tile (causal mask) ----
    {
        const int p = qt & 1;
        cp_wait<0>();
        __syncthreads();
        const uint32_t sbK = sbKV + (uint32_t)(p * 2 * ATE) * 2;
        const uint32_t sbV = sbK + (uint32_t)ATE * 2;
        attn_tile<true>(sbK, sbV, qt * 128, sb2a, qf, yacc, ls0, ls1,
                        trow0, c0l, lgo, lr16);
    }

    ls0 += __shfl_xor_sync(0xffffffffu, ls0, 1);
    ls0 += __shfl_xor_sync(0xffffffffu, ls0, 2);
    ls1 += __shfl_xor_sync(0xffffffffu, ls1, 1);
    ls1 += __shfl_xor_sync(0xffffffffu, ls1, 2);
    const float lbase = 128.f * (float)(qt + 1);
    float inv0 = 1.f / (lbase + ls0);
    float inv1 = 1.f / (lbase + ls1);

    #pragma unroll
    for (int half = 0; half < 2; half++) {
        int t = trow0 + half * 8;
        if (t < T_SEQ) {
            float inv = half ? inv1 : inv0;
            size_t base = ((size_t)b * T_SEQ + t) * C_DIM + h * DK;
            #pragma unroll
            for (int j = 0; j < 8; j++) {
                int col = j * 8 + c0l;
                float v0 = (yacc[j][2 * half + 0] + colacc[col])     * inv;
                float v1 = (yacc[j][2 * half + 1] + colacc[col + 1]) * inv;
                __half2 hp;
                hp.x = __float2half_rn(v0); hp.y = __float2half_rn(v1);
                *(__half2*)&Yh[base + col] = hp;
            }
        }
    }
}

// ---------------------------------------------------------------------------
extern "C" void kernel_launch(void* const* d_in, const int* in_sizes, int n_in,
                              void* d_out, int out_size)
{
    const float* x       = (const float*)d_in[0];
    const float* w1_w    = (const float*)d_in[1];
    const float* w1_b    = (const float*)d_in[2];
    const float* w2      = (const float*)d_in[3];
    const float* b2      = (const float*)d_in[4];
    const float* value_w = (const float*)d_in[5];
    const float* value_b = (const float*)d_in[6];
    const float* proj_w  = (const float*)d_in[7];
    const float* proj_b  = (const float*)d_in[8];
    float* out = (float*)d_out;

    __half *xb, *qb, *vs, *yh, *w1s, *vws, *pws, *w2t;
    float* scs;
    cudaGetSymbolAddress((void**)&xb,  g_xb);
    cudaGetSymbolAddress((void**)&qb,  g_qb);  cudaGetSymbolAddress((void**)&vs,  g_vs);
    cudaGetSymbolAddress((void**)&yh,  g_yh);
    cudaGetSymbolAddress((void**)&w1s, g_w1s); cudaGetSymbolAddress((void**)&vws, g_vws);
    cudaGetSymbolAddress((void**)&pws, g_pws); cudaGetSymbolAddress((void**)&w2t, g_w2t);
    cudaGetSymbolAddress((void**)&scs, g_scs);

    cudaFuncSetAttribute(gemm_qv,   cudaFuncAttributeMaxDynamicSharedMemorySize, GSMEM);
    cudaFuncSetAttribute(gemm_proj, cudaFuncAttributeMaxDynamicSharedMemorySize, GSMEM);
    cudaFuncSetAttribute(attn_mma,  cudaFuncAttributeMaxDynamicSharedMemorySize, ASMEM);

    const int NX = R_ROWS * C_DIM;
    const int NW = C_DIM * C_DIM;
    cvt_h<<<NX / 4 / 256, 256>>>(x, xb, NX);
    cvt_h<<<NW / 4 / 256, 256>>>(w1_w,    w1s, NW);
    cvt_h<<<NW / 4 / 256, 256>>>(value_w, vws, NW);
    cvt_h<<<NW / 4 / 256, 256>>>(proj_w,  pws, NW);
    prep_w2t<<<(1024 * DK) / 256, 256>>>(w2, w2t);

    gemm_qv<<<dim3(16, 64), 256, GSMEM>>>(xb, w1s, vws, w1_b, value_b, qb, vs, R_ROWS);

    v_colsum<<<dim3(8, H_NUM, B_SZ), 64>>>(vs, scs);

    attn_mma<<<dim3(8, H_NUM, B_SZ), 256, ASMEM>>>(qb, vs, w2t, b2, scs, yh);

    gemm_proj<<<dim3(8, 64), 256, GSMEM>>>(yh, pws, proj_b, out, R_ROWS);
}

// round 13
// speedup vs baseline: 14.2126x; 1.0703x over previous
#include <cuda_runtime.h>
#include <cuda_fp16.h>
#include <cstdint>

#define B_SZ   8
#define T_SEQ  1023
#define C_DIM  1024
#define H_NUM  16
#define DK     64
#define R_ROWS (B_SZ * T_SEQ)   // 8184
#define LOG2E  1.4426950408889634f

// ---------------- scratch (__device__ globals: allocation-free contract) ----
__device__ __half g_xb [(size_t)R_ROWS * C_DIM];   // x fp16
__device__ __half g_qb [(size_t)R_ROWS * C_DIM];   // relu_out fp16 (Q)
__device__ __half g_vs [(size_t)R_ROWS * C_DIM];   // value fp16
__device__ __half g_yh [(size_t)R_ROWS * C_DIM];   // attn out fp16
__device__ __half g_w1s[(size_t)C_DIM * C_DIM];
__device__ __half g_vws[(size_t)C_DIM * C_DIM];
__device__ __half g_pws[(size_t)C_DIM * C_DIM];
__device__ __half g_w2t[(size_t)1024 * DK];        // w2^T * log2e, fp16, padded
__device__ float  g_scs[(size_t)B_SZ * H_NUM * 8 * DK];  // per-(b,h,tile) V colsums

// ---------------- tensor-core helpers (base-target sm_80+ class) -----------
__device__ __forceinline__ uint32_t smem_to_u32(const void* p) {
    uint32_t a;
    asm("{ .reg .u64 t; cvta.to.shared.u64 t, %1; cvt.u32.u64 %0, t; }"
        : "=r"(a) : "l"(p));
    return a;
}
__device__ __forceinline__ void ldsm_x4(uint32_t& r0, uint32_t& r1,
                                        uint32_t& r2, uint32_t& r3, uint32_t addr) {
    asm volatile("ldmatrix.sync.aligned.m8n8.x4.shared.b16 {%0,%1,%2,%3}, [%4];"
                 : "=r"(r0), "=r"(r1), "=r"(r2), "=r"(r3) : "r"(addr));
}
__device__ __forceinline__ void ldsm_x4_t(uint32_t& r0, uint32_t& r1,
                                          uint32_t& r2, uint32_t& r3, uint32_t addr) {
    asm volatile("ldmatrix.sync.aligned.m8n8.x4.trans.shared.b16 {%0,%1,%2,%3}, [%4];"
                 : "=r"(r0), "=r"(r1), "=r"(r2), "=r"(r3) : "r"(addr));
}
__device__ __forceinline__ void mma_f16(float* c, const uint32_t* a, const uint32_t* b) {
    asm volatile(
        "mma.sync.aligned.m16n8k16.row.col.f32.f16.f16.f32 "
        "{%0,%1,%2,%3}, {%4,%5,%6,%7}, {%8,%9}, {%0,%1,%2,%3};"
        : "+f"(c[0]), "+f"(c[1]), "+f"(c[2]), "+f"(c[3])
        : "r"(a[0]), "r"(a[1]), "r"(a[2]), "r"(a[3]), "r"(b[0]), "r"(b[1]));
}
__device__ __forceinline__ uint32_t pack_f16(float lo, float hi) {
    uint32_t r;
    asm("cvt.rn.f16x2.f32 %0, %1, %2;" : "=r"(r) : "f"(hi), "f"(lo));
    return r;
}
__device__ __forceinline__ float ex2f(float x) {
    float r;
    asm("ex2.approx.f32 %0, %1;" : "=f"(r) : "f"(x));
    return r;
}
__device__ __forceinline__ void cp16(uint32_t saddr, const void* gaddr) {
    asm volatile("cp.async.cg.shared.global [%0], [%1], 16;"
                 :: "r"(saddr), "l"(gaddr));
}
#define CP_COMMIT() asm volatile("cp.async.commit_group;")
template<int N>
__device__ __forceinline__ void cp_wait() {
    asm volatile("cp.async.wait_group %0;" :: "n"(N));
}

// ---------------------------------------------------------------------------
// conversions / prep
// ---------------------------------------------------------------------------
__global__ void cvt_h(const float* __restrict__ in, __half* __restrict__ out, int n)
{
    int i = (blockIdx.x * blockDim.x + threadIdx.x) * 4;
    if (i < n) {
        float4 v = *(const float4*)(in + i);
        __half2 a, b;
        a.x = __float2half_rn(v.x); a.y = __float2half_rn(v.y);
        b.x = __float2half_rn(v.z); b.y = __float2half_rn(v.w);
        *(__half2*)(out + i)     = a;
        *(__half2*)(out + i + 2) = b;
    }
}

// three weight tensors in one launch (blockIdx.y selects)
__global__ void cvt_h3(const float* __restrict__ i0, const float* __restrict__ i1,
                       const float* __restrict__ i2, __half* __restrict__ o0,
                       __half* __restrict__ o1, __half* __restrict__ o2)
{
    const float* in  = (blockIdx.y == 0) ? i0 : (blockIdx.y == 1) ? i1 : i2;
    __half*      out = (blockIdx.y == 0) ? o0 : (blockIdx.y == 1) ? o1 : o2;
    int i = (blockIdx.x * blockDim.x + threadIdx.x) * 4;
    float4 v = *(const float4*)(in + i);
    __half2 a, b;
    a.x = __float2half_rn(v.x); a.y = __float2half_rn(v.y);
    b.x = __float2half_rn(v.z); b.y = __float2half_rn(v.w);
    *(__half2*)(out + i)     = a;
    *(__half2*)(out + i + 2) = b;
}

// w2 [DK][T_SEQ] f32 -> w2t [1024][DK] fp16, PRESCALED by log2e.
__global__ void prep_w2t(const float* __restrict__ w2, __half* __restrict__ w2t)
{
    int idx = blockIdx.x * 256 + threadIdx.x;     // 1024*64
    int s = idx >> 6, d = idx & 63;
    float v = (s < T_SEQ) ? w2[d * T_SEQ + s] * LOG2E : 0.f;
    w2t[idx] = __float2half_rn(v);
}

// per-(b,h,tile) V column sums (same row clamping as attn's sV loads).
__global__ void v_colsum(const __half* __restrict__ V, float* __restrict__ Scs)
{
    int t = blockIdx.x, h = blockIdx.y, b = blockIdx.z, d = threadIdx.x;
    float s = 0.f;
    #pragma unroll 8
    for (int i = 0; i < 128; i++) {
        int sidx = t * 128 + i; if (sidx > T_SEQ - 1) sidx = T_SEQ - 1;
        s += __half2float(V[((size_t)b * T_SEQ + sidx) * C_DIM + h * DK + d]);
    }
    Scs[(((size_t)b * H_NUM + h) * 8 + t) * DK + d] = s;
}

// ---------------------------------------------------------------------------
// fp16 HMMA GEMM, cp.async double-buffered K-loop.
// CTA 128x128, 8 warps 2x4, warp 64x32. smem = 2 bufs x (A,B) = 73728 B.
// ---------------------------------------------------------------------------
#define BM  128
#define BN  128
#define BK  64
#define LDS 72
#define TILE_ELEMS (BM * LDS)
#define GSMEM (4 * TILE_ELEMS * 2)            // 2 x (A + B): 73728 bytes

// MODE 0: f32 out (+bias). MODE 1 (qv-fused): relu->fp16 / plain fp16.
template<int MODE>
__global__ __launch_bounds__(256, 2)
void gemm_db(const __half* __restrict__ A0,
             const __half* __restrict__ B0, const __half* __restrict__ B1,
             const float* __restrict__ bias0, const float* __restrict__ bias1,
             float* __restrict__ Of, __half* __restrict__ O0,
             __half* __restrict__ O1, int R)
{
    extern __shared__ __half sm[];

    const int  tid  = threadIdx.x;
    const int  wid  = tid >> 5;
    const int  lane = tid & 31;
    const int  wm   = wid >> 2;
    const int  wn   = wid & 3;
    const int  m0   = blockIdx.y * BM;
    const bool isQ  = (MODE == 1) && (blockIdx.x < 8);
    const int  n0   = (MODE == 1 ? (isQ ? blockIdx.x : blockIdx.x - 8)
                                 : blockIdx.x) * BN;
    const __half* Bsrc = (MODE == 1) ? (isQ ? B0 : B1) : B0;
    const float*  bias = (MODE == 1) ? (isQ ? bias0 : bias1) : bias0;

    const uint32_t sb = smem_to_u32(sm);
    const int lrow = tid >> 3;          // 0..31
    const int lc8  = (tid & 7) * 8;

    auto issue = [&](int k0, int buf) {
        const uint32_t dA = sb + (uint32_t)(buf * 2 * TILE_ELEMS) * 2;
        const uint32_t dB = dA + (uint32_t)TILE_ELEMS * 2;
        #pragma unroll
        for (int i = 0; i < 4; i++) {
            int row = lrow + i * 32;
            uint32_t so = (uint32_t)(row * LDS + lc8) * 2;
            int ar = m0 + row; if (ar > R - 1) ar = R - 1;   // clamp: epilogue guards
            cp16(dA + so, A0 + (size_t)ar * C_DIM + k0 + lc8);
            cp16(dB + so, Bsrc + (size_t)(n0 + row) * C_DIM + k0 + lc8);
        }
    };

    float acc[4][4][4];
    #pragma unroll
    for (int f = 0; f < 4; f++)
        #pragma unroll
        for (int j = 0; j < 4; j++)
            #pragma unroll
            for (int e = 0; e < 4; e++) acc[f][j][e] = 0.f;

    const int a_r = wm * 64 + (lane & 15);
    const int b_r = wn * 32 + (lane & 15);
    const int l_c = (lane >> 4) << 3;

    issue(0, 0);
    CP_COMMIT();

    for (int kc = 0; kc < C_DIM / BK; kc++) {
        const int p = kc & 1;
        if (kc < C_DIM / BK - 1) {
            issue((kc + 1) * BK, 1 - p);
            CP_COMMIT();
            cp_wait<1>();
        } else {
            cp_wait<0>();
        }
        __syncthreads();

        const uint32_t sbA = sb + (uint32_t)(p * 2 * TILE_ELEMS) * 2;
        const uint32_t sbB = sbA + (uint32_t)TILE_ELEMS * 2;

        #pragma unroll
        for (int kk = 0; kk < BK; kk += 16) {
            uint32_t af[4][4], bh[2][4];
            #pragma unroll
            for (int pp = 0; pp < 2; pp++) {
                uint32_t off = (uint32_t)((b_r + pp * 16) * LDS + kk + l_c) * 2;
                ldsm_x4(bh[pp][0], bh[pp][1], bh[pp][2], bh[pp][3], sbB + off);
            }
            #pragma unroll
            for (int f = 0; f < 4; f++) {
                uint32_t off = (uint32_t)((a_r + f * 16) * LDS + kk + l_c) * 2;
                ldsm_x4(af[f][0], af[f][1], af[f][2], af[f][3], sbA + off);
            }
            #pragma unroll
            for (int f = 0; f < 4; f++)
                #pragma unroll
                for (int j = 0; j < 4; j++) {
                    int pp = j >> 1, hh = j & 1;
                    uint32_t bfr[2] = { bh[pp][hh], bh[pp][2 + hh] };
                    mma_f16(acc[f][j], af[f], bfr);
                }
        }
        __syncthreads();
    }

    const int qr = lane >> 2;
    const int qc = (lane & 3) * 2;
    #pragma unroll
    for (int f = 0; f < 4; f++) {
        #pragma unroll
        for (int j = 0; j < 4; j++) {
            int col = n0 + wn * 32 + j * 8 + qc;
            float b0 = bias[col], b1v = bias[col + 1];
            #pragma unroll
            for (int half = 0; half < 2; half++) {
                int row = m0 + wm * 64 + f * 16 + qr + half * 8;
                if (row < R) {
                    float v0 = acc[f][j][half * 2 + 0] + b0;
                    float v1 = acc[f][j][half * 2 + 1] + b1v;
                    if (MODE == 0) {
                        *(float2*)&Of[(size_t)row * C_DIM + col] = make_float2(v0, v1);
                    } else {
                        if (isQ) { v0 = fmaxf(v0, 0.f); v1 = fmaxf(v1, 0.f); }
                        __half* O = isQ ? O0 : O1;
                        __half2 hp;
                        hp.x = __float2half_rn(v0); hp.y = __float2half_rn(v1);
                        *(__half2*)&O[(size_t)row * C_DIM + col] = hp;
                    }
                }
            }
        }
    }
}

// ---------------------------------------------------------------------------
// HMMA fp16 flash attention, centered-P, prescaled-log2e scores,
// diag/non-diag split tile bodies, cp.async double-buffered K/V. (R12)
// ---------------------------------------------------------------------------
#define ATE   (128 * LDS)
#define ASMEM (5 * ATE * 2 + 1024 * 4 + 64 * 4)

template<bool DIAG>
__device__ __forceinline__ void attn_tile(
    uint32_t sbK, uint32_t sbV, int s0, const float* __restrict__ sb2a,
    const uint32_t (&qf)[4][4], float (&yacc)[8][4], float& ls0, float& ls1,
    int trow0, int c0l, int lgo, int lr16)
{
    #pragma unroll
    for (int j = 0; j < 8; j++) {
        float Sp[2][4];
        #pragma unroll
        for (int fh = 0; fh < 2; fh++)
            #pragma unroll
            for (int e = 0; e < 4; e++) Sp[fh][e] = 0.f;

        int nr = j * 16 + lr16;
        #pragma unroll
        for (int k = 0; k < 4; k++) {
            uint32_t bb[4];
            ldsm_x4(bb[0], bb[1], bb[2], bb[3],
                    sbK + (uint32_t)(nr * LDS + k * 16 + lgo) * 2);
            uint32_t blo[2] = { bb[0], bb[2] };
            uint32_t bhi[2] = { bb[1], bb[3] };
            mma_f16(Sp[0], qf[k], blo);
            mma_f16(Sp[1], qf[k], bhi);
        }

        float pv_[2][4];
        #pragma unroll
        for (int fh = 0; fh < 2; fh++) {
            int f = 2 * j + fh;
            float2 bb2 = *(const float2*)&sb2a[s0 + 8 * f + c0l];
            if (!DIAG) {
                pv_[fh][0] = ex2f(Sp[fh][0] + bb2.x) - 1.f;
                pv_[fh][1] = ex2f(Sp[fh][1] + bb2.y) - 1.f;
                pv_[fh][2] = ex2f(Sp[fh][2] + bb2.x) - 1.f;
                pv_[fh][3] = ex2f(Sp[fh][3] + bb2.y) - 1.f;
            } else {
                #pragma unroll
                for (int e = 0; e < 4; e++) {
                    int col = 8 * f + c0l + (e & 1);
                    int rr  = trow0 + ((e >> 1) << 3);
                    float sv = Sp[fh][e] + ((e & 1) ? bb2.y : bb2.x);
                    bool ok  = (s0 + col <= rr);
                    pv_[fh][e] = ok ? (ex2f(sv) - 1.f) : -1.f;
                }
            }
            ls0 += pv_[fh][0] + pv_[fh][1];
            ls1 += pv_[fh][2] + pv_[fh][3];
        }

        uint32_t Ah_[4];
        #pragma unroll
        for (int fh = 0; fh < 2; fh++) {
            Ah_[2 * fh + 0] = pack_f16(pv_[fh][0], pv_[fh][1]);
            Ah_[2 * fh + 1] = pack_f16(pv_[fh][2], pv_[fh][3]);
        }

        int srow = j * 16 + lr16;
        #pragma unroll
        for (int dg = 0; dg < 4; dg++) {
            uint32_t v4[4];
            ldsm_x4_t(v4[0], v4[1], v4[2], v4[3],
                      sbV + (uint32_t)(srow * LDS + dg * 16 + lgo) * 2);
            uint32_t b0[2] = { v4[0], v4[1] };
            uint32_t b1[2] = { v4[2], v4[3] };
            mma_f16(yacc[2 * dg],     Ah_, b0);
            mma_f16(yacc[2 * dg + 1], Ah_, b1);
        }
    }
}

__global__ __launch_bounds__(256, 2)
void attn_mma(const __half* __restrict__ Q, const __half* __restrict__ V,
              const __half* __restrict__ w2t, const float* __restrict__ b2,
              const float* __restrict__ Scs, __half* __restrict__ Yh)
{
    extern __shared__ __half asmem[];
    __half* sQ  = asmem;
    __half* sKV = asmem + ATE;
    float* sb2a   = (float*)(asmem + 5 * ATE);
    float* colacc = sb2a + 1024;

    const uint32_t sbQ  = smem_to_u32(sQ);
    const uint32_t sbKV = smem_to_u32(sKV);

    const int b    = blockIdx.z;
    const int h    = blockIdx.y;
    const int qt   = (int)(gridDim.x - 1) - (int)blockIdx.x;   // heavy first
    const int m0   = qt * 128;
    const int tid  = threadIdx.x;
    const int wid  = tid >> 5;
    const int lane = tid & 31;
    const int mw   = wid * 16;

    const int lrow = tid >> 3;
    const int lc8  = (tid & 7) * 8;

    auto issue_tile = [&](int nt, int buf) {
        const int s0 = nt * 128;
        const uint32_t dK = sbKV + (uint32_t)(buf * 2 * ATE) * 2;
        const uint32_t dV = dK + (uint32_t)ATE * 2;
        #pragma unroll
        for (int i = 0; i < 4; i++) {
            int row = lrow + i * 32;
            uint32_t so = (uint32_t)(row * LDS + lc8) * 2;
            cp16(dK + so, w2t + (size_t)(s0 + row) * DK + lc8);
            int s = s0 + row; if (s > T_SEQ - 1) s = T_SEQ - 1;
            cp16(dV + so, V + ((size_t)b * T_SEQ + s) * C_DIM + h * DK + lc8);
        }
    };

    issue_tile(0, 0);
    CP_COMMIT();

    for (int idx = tid; idx < 1024; idx += 256) {
        int row = idx >> 3, c8 = (idx & 7) * 8;
        int t = m0 + row; if (t > T_SEQ - 1) t = T_SEQ - 1;
        *(uint4*)(sQ + row * LDS + c8) =
            *(const uint4*)(Q + ((size_t)b * T_SEQ + t) * C_DIM + h * DK + c8);
    }
    for (int idx = tid; idx < 1024; idx += 256)
        sb2a[idx] = (idx < T_SEQ) ? b2[idx] * LOG2E : 0.f;
    if (tid < 64) {
        const float* sp = Scs + (((size_t)b * H_NUM + h) * 8) * DK + tid;
        float c = 0.f;
        for (int t = 0; t <= qt; t++) c += sp[t * DK];
        colacc[tid] = c;
    }
    __syncthreads();

    uint32_t qf[4][4];
    {
        int r  = mw + (lane & 15);
        int cg = (lane >> 4) << 3;
        #pragma unroll
        for (int k = 0; k < 4; k++)
            ldsm_x4(qf[k][0], qf[k][1], qf[k][2], qf[k][3],
                    sbQ + (uint32_t)(r * LDS + k * 16 + cg) * 2);
    }

    float yacc[8][4];
    #pragma unroll
    for (int j = 0; j < 8; j++)
        #pragma unroll
        for (int e = 0; e < 4; e++) yacc[j][e] = 0.f;
    float ls0 = 0.f, ls1 = 0.f;

    const int r0    = lane >> 2;
    const int c0l   = (lane & 3) * 2;
    const int trow0 = m0 + mw + r0;
    const int lgo   = (lane >> 4) << 3;
    const int lr16  = lane & 15;

    for (int nt = 0; nt < qt; nt++) {
        const int p = nt & 1;
        issue_tile(nt + 1, 1 - p);
        CP_COMMIT();
        cp_wait<1>();
        __syncthreads();
        const uint32_t sbK = sbKV + (uint32_t)(p * 2 * ATE) * 2;
        const uint32_t sbV = sbK + (uint32_t)ATE * 2;
        attn_tile<false>(sbK, sbV, nt * 128, sb2a, qf, yacc, ls0, ls1,
                         trow0, c0l, lgo, lr16);
        __syncthreads();
    }
    {
        const int p = qt & 1;
        cp_wait<0>();
        __syncthreads();
        const uint32_t sbK = sbKV + (uint32_t)(p * 2 * ATE) * 2;
        const uint32_t sbV = sbK + (uint32_t)ATE * 2;
        attn_tile<true>(sbK, sbV, qt * 128, sb2a, qf, yacc, ls0, ls1,
                        trow0, c0l, lgo, lr16);
    }

    ls0 += __shfl_xor_sync(0xffffffffu, ls0, 1);
    ls0 += __shfl_xor_sync(0xffffffffu, ls0, 2);
    ls1 += __shfl_xor_sync(0xffffffffu, ls1, 1);
    ls1 += __shfl_xor_sync(0xffffffffu, ls1, 2);
    const float lbase = 128.f * (float)(qt + 1);
    float inv0 = 1.f / (lbase + ls0);
    float inv1 = 1.f / (lbase + ls1);

    #pragma unroll
    for (int half = 0; half < 2; half++) {
        int t = trow0 + half * 8;
        if (t < T_SEQ) {
            float inv = half ? inv1 : inv0;
            size_t base = ((size_t)b * T_SEQ + t) * C_DIM + h * DK;
            #pragma unroll
            for (int j = 0; j < 8; j++) {
                int col = j * 8 + c0l;
                float v0 = (yacc[j][2 * half + 0] + colacc[col])     * inv;
                float v1 = (yacc[j][2 * half + 1] + colacc[col + 1]) * inv;
                __half2 hp;
                hp.x = __float2half_rn(v0); hp.y = __float2half_rn(v1);
                *(__half2*)&Yh[base + col] = hp;
            }
        }
    }
}

// ---------------------------------------------------------------------------
extern "C" void kernel_launch(void* const* d_in, const int* in_sizes, int n_in,
                              void* d_out, int out_size)
{
    const float* x       = (const float*)d_in[0];
    const float* w1_w    = (const float*)d_in[1];
    const float* w1_b    = (const float*)d_in[2];
    const float* w2      = (const float*)d_in[3];
    const float* b2      = (const float*)d_in[4];
    const float* value_w = (const float*)d_in[5];
    const float* value_b = (const float*)d_in[6];
    const float* proj_w  = (const float*)d_in[7];
    const float* proj_b  = (const float*)d_in[8];
    float* out = (float*)d_out;

    __half *xb, *qb, *vs, *yh, *w1s, *vws, *pws, *w2t;
    float* scs;
    cudaGetSymbolAddress((void**)&xb,  g_xb);
    cudaGetSymbolAddress((void**)&qb,  g_qb);  cudaGetSymbolAddress((void**)&vs,  g_vs);
    cudaGetSymbolAddress((void**)&yh,  g_yh);
    cudaGetSymbolAddress((void**)&w1s, g_w1s); cudaGetSymbolAddress((void**)&vws, g_vws);
    cudaGetSymbolAddress((void**)&pws, g_pws); cudaGetSymbolAddress((void**)&w2t, g_w2t);
    cudaGetSymbolAddress((void**)&scs, g_scs);

    cudaFuncSetAttribute(gemm_db<0>, cudaFuncAttributeMaxDynamicSharedMemorySize, GSMEM);
    cudaFuncSetAttribute(gemm_db<1>, cudaFuncAttributeMaxDynamicSharedMemorySize, GSMEM);
    cudaFuncSetAttribute(attn_mma,   cudaFuncAttributeMaxDynamicSharedMemorySize, ASMEM);

    const int NX = R_ROWS * C_DIM;
    const int NW = C_DIM * C_DIM;
    cvt_h<<<NX / 4 / 256, 256>>>(x, xb, NX);
    cvt_h3<<<dim3(NW / 4 / 256, 3), 256>>>(w1_w, value_w, proj_w, w1s, vws, pws);
    prep_w2t<<<(1024 * DK) / 256, 256>>>(w2, w2t);

    // fused relu + value GEMMs, double-buffered
    gemm_db<1><<<dim3(16, 64), 256, GSMEM>>>(xb, w1s, vws, w1_b, value_b,
                                             nullptr, qb, vs, R_ROWS);

    v_colsum<<<dim3(8, H_NUM, B_SZ), 64>>>(vs, scs);

    attn_mma<<<dim3(8, H_NUM, B_SZ), 256, ASMEM>>>(qb, vs, w2t, b2, scs, yh);

    // projection GEMM, double-buffered
    gemm_db<0><<<dim3(8, 64), 256, GSMEM>>>(yh, pws, nullptr, proj_b, nullptr,
                                            out, nullptr, nullptr, R_ROWS);
}